// round 1
// baseline (speedup 1.0000x reference)
#include <cuda_runtime.h>

// Problem constants
#define Bb    2
#define Sq    2048
#define DIN   2048
#define DOUT  2048
#define NH    16
#define NKV   4
#define HD    128
#define GS    4
#define MROWS (Bb*Sq)        // 4096
#define DKV   (NKV*HD)       // 512

// Scratch (static device globals -- no allocations allowed in kernel_launch)
__device__ float g_q[(size_t)MROWS*DOUT];   // 32 MB  [b,s,h,d]
__device__ float g_k[(size_t)MROWS*DKV];    //  8 MB  [b,s,kh,d]
__device__ float g_v[(size_t)MROWS*DKV];    //  8 MB  [b,s,kh,d]
__device__ float g_ctx[(size_t)MROWS*DOUT]; // 32 MB  [b,s,h*HD+d]

// ---------------------------------------------------------------------------
// SGEMM: C[M,N] = A[M,K] * B[K,N], row-major, M%128==0, N%128==0, K%8==0.
// 128x128 tile, 256 threads, 8x8 per thread, padded smem (conflict-free).
// ---------------------------------------------------------------------------
__global__ __launch_bounds__(256) void sgemm128(
    const float* __restrict__ A, const float* __restrict__ Bw,
    float* __restrict__ C, int M, int N, int K)
{
    __shared__ float As[8][132];
    __shared__ float Bs[8][132];
    const int t  = threadIdx.x;
    const int tx = t & 15, ty = t >> 4;
    const int row0 = blockIdx.y << 7;
    const int col0 = blockIdx.x << 7;

    float acc[8][8];
#pragma unroll
    for (int i = 0; i < 8; i++)
#pragma unroll
        for (int j = 0; j < 8; j++) acc[i][j] = 0.f;

    for (int k0 = 0; k0 < K; k0 += 8) {
#pragma unroll
        for (int i = 0; i < 4; i++) {           // A tile 128x8, stored transposed
            int li = t + (i << 8);
            int r = li >> 3, kk = li & 7;
            As[kk][r] = A[(size_t)(row0 + r) * K + k0 + kk];
        }
#pragma unroll
        for (int i = 0; i < 4; i++) {           // B tile 8x128, coalesced
            int li = t + (i << 8);
            int kk = li >> 7, c = li & 127;
            Bs[kk][c] = Bw[(size_t)(k0 + kk) * N + col0 + c];
        }
        __syncthreads();
#pragma unroll
        for (int kk = 0; kk < 8; kk++) {
            float4 a0 = *(const float4*)&As[kk][ty * 8];
            float4 a1 = *(const float4*)&As[kk][ty * 8 + 4];
            float4 b0 = *(const float4*)&Bs[kk][tx * 8];
            float4 b1 = *(const float4*)&Bs[kk][tx * 8 + 4];
            float a[8] = {a0.x, a0.y, a0.z, a0.w, a1.x, a1.y, a1.z, a1.w};
            float b[8] = {b0.x, b0.y, b0.z, b0.w, b1.x, b1.y, b1.z, b1.w};
#pragma unroll
            for (int i = 0; i < 8; i++)
#pragma unroll
                for (int j = 0; j < 8; j++)
                    acc[i][j] = fmaf(a[i], b[j], acc[i][j]);
        }
        __syncthreads();
    }
#pragma unroll
    for (int i = 0; i < 8; i++) {
        size_t r = (size_t)(row0 + ty * 8 + i);
        *(float4*)&C[r * N + col0 + tx * 8]     = make_float4(acc[i][0], acc[i][1], acc[i][2], acc[i][3]);
        *(float4*)&C[r * N + col0 + tx * 8 + 4] = make_float4(acc[i][4], acc[i][5], acc[i][6], acc[i][7]);
    }
}

// ---------------------------------------------------------------------------
// RoPE in place on [B,S,nheads,HD]. One thread per (row, head, d<64) pair.
// ---------------------------------------------------------------------------
__global__ void rope_kernel(float* __restrict__ tns,
                            const float* __restrict__ cosT,
                            const float* __restrict__ sinT, int nheads)
{
    const int hd2 = HD / 2;
    int idx = blockIdx.x * blockDim.x + threadIdx.x;
    if (idx >= MROWS * nheads * hd2) return;
    int d    = idx % hd2;
    int h    = (idx / hd2) % nheads;
    int sidx = idx / (hd2 * nheads);
    int s    = sidx & (Sq - 1);
    float* base = tns + ((size_t)sidx * nheads + h) * HD;
    float c1 = cosT[s * HD + d],       s1 = sinT[s * HD + d];
    float c2 = cosT[s * HD + d + hd2], s2 = sinT[s * HD + d + hd2];
    float t1 = base[d], t2 = base[d + hd2];
    base[d]       = t1 * c1 - t2 * s1;   // rot[d]      = -t2
    base[d + hd2] = t2 * c2 + t1 * s2;   // rot[d+hd2]  = +t1
}

// ---------------------------------------------------------------------------
// Flash attention, fp32, causal, GQA (4 Q-heads share one KV head).
// Block = (qtile of 64 rows, head, batch). 256 threads.
// ---------------------------------------------------------------------------
#define BM 64
#define BN 64
#define QK_STR 132   // Q/K smem row stride (pad 4)
#define S_STR  65    // score smem row stride (pad 1)
#define ATTN_SMEM ((BM*QK_STR + BN*QK_STR + BN*HD + BM*S_STR + BM) * 4)

__global__ __launch_bounds__(256) void flash_attn(
    const float* __restrict__ Qg, const float* __restrict__ Kg,
    const float* __restrict__ Vg, float* __restrict__ Og)
{
    extern __shared__ float smc[];
    float* Qs   = smc;                   // 64 x 132
    float* Ks   = Qs + BM * QK_STR;      // 64 x 132
    float* Vs   = Ks + BN * QK_STR;      // 64 x 128
    float* Ssm  = Vs + BN * HD;          // 64 x 65
    float* alph = Ssm + BM * S_STR;      // 64

    const int qtile = gridDim.x - 1 - blockIdx.x;   // big-work blocks first
    const int h = blockIdx.y, b = blockIdx.z;
    const int kh = h >> 2;
    const int t  = threadIdx.x;
    const int tr = t >> 4, tc = t & 15;
    const int q0 = qtile * BM;
    const float scale = 0.08838834764831845f;       // 1/sqrt(128)

    // Load Q tile (scaled). Layout [b,s,h,d]; rows contiguous in d.
    {
        const float* qbase = Qg + (((size_t)b * Sq + q0) * NH + h) * HD;
        for (int li = t; li < BM * (HD / 4); li += 256) {
            int r = li >> 5, d4 = li & 31;
            float4 v = *(const float4*)(qbase + (size_t)r * NH * HD + d4 * 4);
            v.x *= scale; v.y *= scale; v.z *= scale; v.w *= scale;
            *(float4*)&Qs[r * QK_STR + d4 * 4] = v;
        }
    }

    float o[4][8];
#pragma unroll
    for (int i = 0; i < 4; i++)
#pragma unroll
        for (int j = 0; j < 8; j++) o[i][j] = 0.f;
    float m_i = -1e30f, l_i = 0.f;
    __syncthreads();

    const int kend = q0 + BM;
    for (int k0 = 0; k0 < kend; k0 += BN) {
        // Load K/V tile for this KV head. Layout [b,s,kh,d].
        const float* kbase = Kg + (((size_t)b * Sq + k0) * NKV + kh) * HD;
        const float* vbase = Vg + (((size_t)b * Sq + k0) * NKV + kh) * HD;
        for (int li = t; li < BN * (HD / 4); li += 256) {
            int r = li >> 5, d4 = li & 31;
            *(float4*)&Ks[r * QK_STR + d4 * 4] = *(const float4*)(kbase + (size_t)r * NKV * HD + d4 * 4);
            *(float4*)&Vs[r * HD + d4 * 4]     = *(const float4*)(vbase + (size_t)r * NKV * HD + d4 * 4);
        }
        __syncthreads();

        // S = Q * K^T : rows tr*4+i, cols tc+16*j (conflict-friendly spread)
        float sacc[4][4];
#pragma unroll
        for (int i = 0; i < 4; i++)
#pragma unroll
            for (int j = 0; j < 4; j++) sacc[i][j] = 0.f;
#pragma unroll 4
        for (int kk = 0; kk < HD; kk += 4) {
            float4 a4[4], b4[4];
#pragma unroll
            for (int i = 0; i < 4; i++) a4[i] = *(const float4*)&Qs[(tr * 4 + i) * QK_STR + kk];
#pragma unroll
            for (int j = 0; j < 4; j++) b4[j] = *(const float4*)&Ks[(tc + 16 * j) * QK_STR + kk];
#pragma unroll
            for (int i = 0; i < 4; i++)
#pragma unroll
                for (int j = 0; j < 4; j++) {
                    sacc[i][j] = fmaf(a4[i].x, b4[j].x, sacc[i][j]);
                    sacc[i][j] = fmaf(a4[i].y, b4[j].y, sacc[i][j]);
                    sacc[i][j] = fmaf(a4[i].z, b4[j].z, sacc[i][j]);
                    sacc[i][j] = fmaf(a4[i].w, b4[j].w, sacc[i][j]);
                }
        }
        const bool diag = (k0 == q0);   // only diagonal tile needs masking
#pragma unroll
        for (int i = 0; i < 4; i++) {
            int qr = q0 + tr * 4 + i;
#pragma unroll
            for (int j = 0; j < 4; j++) {
                int kc = k0 + tc + 16 * j;
                float v = sacc[i][j];
                if (diag && kc > qr) v = -1e30f;
                Ssm[(tr * 4 + i) * S_STR + tc + 16 * j] = v;
            }
        }
        __syncthreads();

        // Online softmax: thread t < 64 owns row t (conflict-free via S_STR=65)
        if (t < BM) {
            float rmax = -1e30f;
#pragma unroll 4
            for (int j = 0; j < BN; j++) rmax = fmaxf(rmax, Ssm[t * S_STR + j]);
            float m_new = fmaxf(m_i, rmax);
            float a = __expf(m_i - m_new);
            float ls = 0.f;
#pragma unroll 4
            for (int j = 0; j < BN; j++) {
                float e = __expf(Ssm[t * S_STR + j] - m_new);
                Ssm[t * S_STR + j] = e;
                ls += e;
            }
            l_i = l_i * a + ls;
            m_i = m_new;
            alph[t] = a;
        }
        __syncthreads();

        // O = O*alpha + P*V : rows tr*4+i, cols tc*8..tc*8+7
        float al[4];
#pragma unroll
        for (int i = 0; i < 4; i++) al[i] = alph[tr * 4 + i];
#pragma unroll
        for (int i = 0; i < 4; i++)
#pragma unroll
            for (int j = 0; j < 8; j++) o[i][j] *= al[i];
#pragma unroll 2
        for (int jj = 0; jj < BN; jj++) {
            float p[4];
#pragma unroll
            for (int i = 0; i < 4; i++) p[i] = Ssm[(tr * 4 + i) * S_STR + jj];
            float4 v0 = *(const float4*)&Vs[jj * HD + tc * 8];
            float4 v1 = *(const float4*)&Vs[jj * HD + tc * 8 + 4];
#pragma unroll
            for (int i = 0; i < 4; i++) {
                o[i][0] = fmaf(p[i], v0.x, o[i][0]);
                o[i][1] = fmaf(p[i], v0.y, o[i][1]);
                o[i][2] = fmaf(p[i], v0.z, o[i][2]);
                o[i][3] = fmaf(p[i], v0.w, o[i][3]);
                o[i][4] = fmaf(p[i], v1.x, o[i][4]);
                o[i][5] = fmaf(p[i], v1.y, o[i][5]);
                o[i][6] = fmaf(p[i], v1.z, o[i][6]);
                o[i][7] = fmaf(p[i], v1.w, o[i][7]);
            }
        }
        __syncthreads();
    }

    if (t < BM) alph[t] = 1.f / l_i;
    __syncthreads();
#pragma unroll
    for (int i = 0; i < 4; i++) {
        float inv = alph[tr * 4 + i];
        size_t row = (size_t)b * Sq + q0 + tr * 4 + i;
        float* dst = Og + row * DOUT + h * HD + tc * 8;
        *(float4*)dst       = make_float4(o[i][0] * inv, o[i][1] * inv, o[i][2] * inv, o[i][3] * inv);
        *(float4*)(dst + 4) = make_float4(o[i][4] * inv, o[i][5] * inv, o[i][6] * inv, o[i][7] * inv);
    }
}

// ---------------------------------------------------------------------------
extern "C" void kernel_launch(void* const* d_in, const int* in_sizes, int n_in,
                              void* d_out, int out_size)
{
    const float* x    = (const float*)d_in[0];
    const float* Wq   = (const float*)d_in[1];
    const float* Wk   = (const float*)d_in[2];
    const float* Wv   = (const float*)d_in[3];
    const float* Wo   = (const float*)d_in[4];
    const float* cosT = (const float*)d_in[5];
    const float* sinT = (const float*)d_in[6];
    float* out = (float*)d_out;

    float *q, *k, *v, *ctx;
    cudaGetSymbolAddress((void**)&q,   g_q);
    cudaGetSymbolAddress((void**)&k,   g_k);
    cudaGetSymbolAddress((void**)&v,   g_v);
    cudaGetSymbolAddress((void**)&ctx, g_ctx);

    cudaFuncSetAttribute(flash_attn, cudaFuncAttributeMaxDynamicSharedMemorySize, ATTN_SMEM);

    dim3 thr(256);
    // QKV projections
    sgemm128<<<dim3(DOUT / 128, MROWS / 128), thr>>>(x, Wq, q, MROWS, DOUT, DIN);
    sgemm128<<<dim3(DKV  / 128, MROWS / 128), thr>>>(x, Wk, k, MROWS, DKV,  DIN);
    sgemm128<<<dim3(DKV  / 128, MROWS / 128), thr>>>(x, Wv, v, MROWS, DKV,  DIN);
    // RoPE on Q and K
    rope_kernel<<<MROWS * NH  * (HD / 2) / 256, thr>>>(q, cosT, sinT, NH);
    rope_kernel<<<MROWS * NKV * (HD / 2) / 256, thr>>>(k, cosT, sinT, NKV);
    // Attention
    flash_attn<<<dim3(Sq / BM, NH, Bb), thr, ATTN_SMEM>>>(q, k, v, ctx);
    // Output projection
    sgemm128<<<dim3(DOUT / 128, MROWS / 128), thr>>>(ctx, Wo, out, MROWS, DOUT, DOUT);
}

// round 3
// speedup vs baseline: 1.7587x; 1.7587x over previous
#include <cuda_runtime.h>
#include <cuda_bf16.h>
#include <cstdint>

// Problem constants
#define Bb    2
#define Sq    2048
#define DIN   2048
#define DOUT  2048
#define NH    16
#define NKV   4
#define HD    128
#define MROWS (Bb*Sq)        // 4096
#define DKV   (NKV*HD)       // 512

// Scratch
__device__ float g_q[(size_t)MROWS*DOUT];
__device__ float g_k[(size_t)MROWS*DKV];
__device__ float g_v[(size_t)MROWS*DKV];
__device__ float g_ctx[(size_t)MROWS*DOUT];

// ---------------------------------------------------------------------------
// Warp-level MMA helpers (standard PTX, works on base sm_103 target)
// ---------------------------------------------------------------------------
__device__ __forceinline__ uint32_t smem_u32(const void* p) {
    uint32_t a;
    asm("{ .reg .u64 t; cvta.to.shared.u64 t, %1; cvt.u32.u64 %0, t; }" : "=r"(a) : "l"(p));
    return a;
}
__device__ __forceinline__ void ldsm_x4(uint32_t& r0, uint32_t& r1, uint32_t& r2, uint32_t& r3,
                                        uint32_t addr) {
    asm volatile("ldmatrix.sync.aligned.m8n8.x4.shared.b16 {%0,%1,%2,%3}, [%4];"
                 : "=r"(r0), "=r"(r1), "=r"(r2), "=r"(r3) : "r"(addr));
}
__device__ __forceinline__ void ldsm_x4t(uint32_t& r0, uint32_t& r1, uint32_t& r2, uint32_t& r3,
                                         uint32_t addr) {
    asm volatile("ldmatrix.sync.aligned.m8n8.x4.trans.shared.b16 {%0,%1,%2,%3}, [%4];"
                 : "=r"(r0), "=r"(r1), "=r"(r2), "=r"(r3) : "r"(addr));
}
__device__ __forceinline__ void mma16816(float* d, const uint32_t* a, const uint32_t* b) {
    asm volatile(
        "mma.sync.aligned.m16n8k16.row.col.f32.bf16.bf16.f32 "
        "{%0,%1,%2,%3}, {%4,%5,%6,%7}, {%8,%9}, {%0,%1,%2,%3};"
        : "+f"(d[0]), "+f"(d[1]), "+f"(d[2]), "+f"(d[3])
        : "r"(a[0]), "r"(a[1]), "r"(a[2]), "r"(a[3]), "r"(b[0]), "r"(b[1]));
}
__device__ __forceinline__ uint32_t packbf2(__nv_bfloat16 a, __nv_bfloat16 b) {
    return (uint32_t)__bfloat16_as_ushort(a) | ((uint32_t)__bfloat16_as_ushort(b) << 16);
}

// ---------------------------------------------------------------------------
// HMMA bf16 GEMM with 2-term split: C = A*W, fp32 in/out, fp32 accumulate.
// 128x128 CTA tile, 8 warps (2x4), 64x32 warp tile, K chunks of 64.
// Padded smem: A rows 72 bf16 (144B), B rows 136 bf16 (272B) -> ldmatrix
// conflict-free (bank of row r advances by 4 mod 32).
// ---------------------------------------------------------------------------
#define KC    64
#define A_STR 72
#define B_STR 136
#define AH_OFF 0
#define AL_OFF 18432
#define BH_OFF 36864
#define BL_OFF 54272
#define GEMM_SMEM 71680

__global__ __launch_bounds__(256) void gemm_mma(
    const float* __restrict__ A, const float* __restrict__ W,
    float* __restrict__ C, int M, int N, int K)
{
    extern __shared__ char smg[];
    const uint32_t sb = smem_u32(smg);
    const int t = threadIdx.x;
    const int wid = t >> 5, lane = t & 31;
    const int wm = wid >> 2, wn = wid & 3;
    const int row0 = blockIdx.y << 7, col0 = blockIdx.x << 7;

    float acc[4][4][4];
#pragma unroll
    for (int mi = 0; mi < 4; mi++)
#pragma unroll
        for (int nt = 0; nt < 4; nt++)
#pragma unroll
            for (int e = 0; e < 4; e++) acc[mi][nt][e] = 0.f;

    const int arow = lane & 15, agrp = (lane >> 4) << 3;   // ldmatrix lane addressing

    const int nch = K / KC;
    for (int c = 0; c < nch; c++) {
        const int k0 = c * KC;
        // ---- stage A tile 128x64: fp32 -> bf16 hi/lo ----
#pragma unroll
        for (int i = 0; i < 8; i++) {
            int li = t + (i << 8);
            int r = li >> 4, c4 = li & 15;
            float4 f = *(const float4*)(A + (size_t)(row0 + r) * K + k0 + c4 * 4);
            float fv[4] = {f.x, f.y, f.z, f.w};
            __nv_bfloat16 h[4], l[4];
#pragma unroll
            for (int j = 0; j < 4; j++) {
                h[j] = __float2bfloat16(fv[j]);
                l[j] = __float2bfloat16(fv[j] - __bfloat162float(h[j]));
            }
            uint32_t off = (uint32_t)(r * A_STR + c4 * 4) * 2;
            *(uint2*)(smg + AH_OFF + off) = make_uint2(packbf2(h[0], h[1]), packbf2(h[2], h[3]));
            *(uint2*)(smg + AL_OFF + off) = make_uint2(packbf2(l[0], l[1]), packbf2(l[2], l[3]));
        }
        // ---- stage B tile 64x128 (k-major rows): fp32 -> bf16 hi/lo ----
#pragma unroll
        for (int i = 0; i < 8; i++) {
            int li = t + (i << 8);
            int kk = li >> 5, n4 = li & 31;
            float4 f = *(const float4*)(W + (size_t)(k0 + kk) * N + col0 + n4 * 4);
            float fv[4] = {f.x, f.y, f.z, f.w};
            __nv_bfloat16 h[4], l[4];
#pragma unroll
            for (int j = 0; j < 4; j++) {
                h[j] = __float2bfloat16(fv[j]);
                l[j] = __float2bfloat16(fv[j] - __bfloat162float(h[j]));
            }
            uint32_t off = (uint32_t)(kk * B_STR + n4 * 4) * 2;
            *(uint2*)(smg + BH_OFF + off) = make_uint2(packbf2(h[0], h[1]), packbf2(h[2], h[3]));
            *(uint2*)(smg + BL_OFF + off) = make_uint2(packbf2(l[0], l[1]), packbf2(l[2], l[3]));
        }
        __syncthreads();

        // ---- compute: 4 k-steps of 16, 3 split passes ----
#pragma unroll
        for (int ks = 0; ks < 4; ks++) {
            uint32_t ah[4][4], al[4][4];
#pragma unroll
            for (int mi = 0; mi < 4; mi++) {
                uint32_t ao = (uint32_t)((wm * 64 + mi * 16 + arow) * A_STR + ks * 16 + agrp) * 2;
                ldsm_x4(ah[mi][0], ah[mi][1], ah[mi][2], ah[mi][3], sb + AH_OFF + ao);
                ldsm_x4(al[mi][0], al[mi][1], al[mi][2], al[mi][3], sb + AL_OFF + ao);
            }
            uint32_t bh[4][2], bl[4][2];
#pragma unroll
            for (int p = 0; p < 2; p++) {
                uint32_t bo = (uint32_t)((ks * 16 + arow) * B_STR + wn * 32 + p * 16 + agrp) * 2;
                uint32_t r0, r1, r2, r3;
                ldsm_x4t(r0, r1, r2, r3, sb + BH_OFF + bo);
                bh[2 * p][0] = r0; bh[2 * p][1] = r1;
                bh[2 * p + 1][0] = r2; bh[2 * p + 1][1] = r3;
                ldsm_x4t(r0, r1, r2, r3, sb + BL_OFF + bo);
                bl[2 * p][0] = r0; bl[2 * p][1] = r1;
                bl[2 * p + 1][0] = r2; bl[2 * p + 1][1] = r3;
            }
#pragma unroll
            for (int mi = 0; mi < 4; mi++)
#pragma unroll
                for (int nt = 0; nt < 4; nt++) {
                    mma16816(acc[mi][nt], ah[mi], bh[nt]);
                    mma16816(acc[mi][nt], al[mi], bh[nt]);
                    mma16816(acc[mi][nt], ah[mi], bl[nt]);
                }
        }
        __syncthreads();
    }

    // ---- epilogue: write accumulators (lane mapping of m16n8 D frag) ----
    const int drow = lane >> 2, dcol = (lane & 3) * 2;
#pragma unroll
    for (int mi = 0; mi < 4; mi++) {
        int r = row0 + wm * 64 + mi * 16 + drow;
#pragma unroll
        for (int nt = 0; nt < 4; nt++) {
            int col = col0 + wn * 32 + nt * 8 + dcol;
            *(float2*)(C + (size_t)r * N + col)       = make_float2(acc[mi][nt][0], acc[mi][nt][1]);
            *(float2*)(C + (size_t)(r + 8) * N + col) = make_float2(acc[mi][nt][2], acc[mi][nt][3]);
        }
    }
}

// ---------------------------------------------------------------------------
// RoPE in place on [B,S,nheads,HD].
// ---------------------------------------------------------------------------
__global__ void rope_kernel(float* __restrict__ tns,
                            const float* __restrict__ cosT,
                            const float* __restrict__ sinT, int nheads)
{
    const int hd2 = HD / 2;
    int idx = blockIdx.x * blockDim.x + threadIdx.x;
    if (idx >= MROWS * nheads * hd2) return;
    int d    = idx % hd2;
    int h    = (idx / hd2) % nheads;
    int sidx = idx / (hd2 * nheads);
    int s    = sidx & (Sq - 1);
    float* base = tns + ((size_t)sidx * nheads + h) * HD;
    float c1 = cosT[s * HD + d],       s1 = sinT[s * HD + d];
    float c2 = cosT[s * HD + d + hd2], s2 = sinT[s * HD + d + hd2];
    float t1 = base[d], t2 = base[d + hd2];
    base[d]       = t1 * c1 - t2 * s1;
    base[d + hd2] = t2 * c2 + t1 * s2;
}

// ---------------------------------------------------------------------------
// Flash attention, fp32, causal, GQA. (unchanged from R1 — known correct)
// ---------------------------------------------------------------------------
#define BM 64
#define BN 64
#define QK_STR 132
#define S_STR  65
#define ATTN_SMEM ((BM*QK_STR + BN*QK_STR + BN*HD + BM*S_STR + BM) * 4)

__global__ __launch_bounds__(256) void flash_attn(
    const float* __restrict__ Qg, const float* __restrict__ Kg,
    const float* __restrict__ Vg, float* __restrict__ Og)
{
    extern __shared__ float smc[];
    float* Qs   = smc;
    float* Ks   = Qs + BM * QK_STR;
    float* Vs   = Ks + BN * QK_STR;
    float* Ssm  = Vs + BN * HD;
    float* alph = Ssm + BM * S_STR;

    const int qtile = gridDim.x - 1 - blockIdx.x;
    const int h = blockIdx.y, b = blockIdx.z;
    const int kh = h >> 2;
    const int t  = threadIdx.x;
    const int tr = t >> 4, tc = t & 15;
    const int q0 = qtile * BM;
    const float scale = 0.08838834764831845f;

    {
        const float* qbase = Qg + (((size_t)b * Sq + q0) * NH + h) * HD;
        for (int li = t; li < BM * (HD / 4); li += 256) {
            int r = li >> 5, d4 = li & 31;
            float4 v = *(const float4*)(qbase + (size_t)r * NH * HD + d4 * 4);
            v.x *= scale; v.y *= scale; v.z *= scale; v.w *= scale;
            *(float4*)&Qs[r * QK_STR + d4 * 4] = v;
        }
    }

    float o[4][8];
#pragma unroll
    for (int i = 0; i < 4; i++)
#pragma unroll
        for (int j = 0; j < 8; j++) o[i][j] = 0.f;
    float m_i = -1e30f, l_i = 0.f;
    __syncthreads();

    const int kend = q0 + BM;
    for (int k0 = 0; k0 < kend; k0 += BN) {
        const float* kbase = Kg + (((size_t)b * Sq + k0) * NKV + kh) * HD;
        const float* vbase = Vg + (((size_t)b * Sq + k0) * NKV + kh) * HD;
        for (int li = t; li < BN * (HD / 4); li += 256) {
            int r = li >> 5, d4 = li & 31;
            *(float4*)&Ks[r * QK_STR + d4 * 4] = *(const float4*)(kbase + (size_t)r * NKV * HD + d4 * 4);
            *(float4*)&Vs[r * HD + d4 * 4]     = *(const float4*)(vbase + (size_t)r * NKV * HD + d4 * 4);
        }
        __syncthreads();

        float sacc[4][4];
#pragma unroll
        for (int i = 0; i < 4; i++)
#pragma unroll
            for (int j = 0; j < 4; j++) sacc[i][j] = 0.f;
#pragma unroll 4
        for (int kk = 0; kk < HD; kk += 4) {
            float4 a4[4], b4[4];
#pragma unroll
            for (int i = 0; i < 4; i++) a4[i] = *(const float4*)&Qs[(tr * 4 + i) * QK_STR + kk];
#pragma unroll
            for (int j = 0; j < 4; j++) b4[j] = *(const float4*)&Ks[(tc + 16 * j) * QK_STR + kk];
#pragma unroll
            for (int i = 0; i < 4; i++)
#pragma unroll
                for (int j = 0; j < 4; j++) {
                    sacc[i][j] = fmaf(a4[i].x, b4[j].x, sacc[i][j]);
                    sacc[i][j] = fmaf(a4[i].y, b4[j].y, sacc[i][j]);
                    sacc[i][j] = fmaf(a4[i].z, b4[j].z, sacc[i][j]);
                    sacc[i][j] = fmaf(a4[i].w, b4[j].w, sacc[i][j]);
                }
        }
        const bool diag = (k0 == q0);
#pragma unroll
        for (int i = 0; i < 4; i++) {
            int qr = q0 + tr * 4 + i;
#pragma unroll
            for (int j = 0; j < 4; j++) {
                int kc = k0 + tc + 16 * j;
                float v = sacc[i][j];
                if (diag && kc > qr) v = -1e30f;
                Ssm[(tr * 4 + i) * S_STR + tc + 16 * j] = v;
            }
        }
        __syncthreads();

        if (t < BM) {
            float rmax = -1e30f;
#pragma unroll 4
            for (int j = 0; j < BN; j++) rmax = fmaxf(rmax, Ssm[t * S_STR + j]);
            float m_new = fmaxf(m_i, rmax);
            float a = __expf(m_i - m_new);
            float ls = 0.f;
#pragma unroll 4
            for (int j = 0; j < BN; j++) {
                float e = __expf(Ssm[t * S_STR + j] - m_new);
                Ssm[t * S_STR + j] = e;
                ls += e;
            }
            l_i = l_i * a + ls;
            m_i = m_new;
            alph[t] = a;
        }
        __syncthreads();

        float al[4];
#pragma unroll
        for (int i = 0; i < 4; i++) al[i] = alph[tr * 4 + i];
#pragma unroll
        for (int i = 0; i < 4; i++)
#pragma unroll
            for (int j = 0; j < 8; j++) o[i][j] *= al[i];
#pragma unroll 2
        for (int jj = 0; jj < BN; jj++) {
            float p[4];
#pragma unroll
            for (int i = 0; i < 4; i++) p[i] = Ssm[(tr * 4 + i) * S_STR + jj];
            float4 v0 = *(const float4*)&Vs[jj * HD + tc * 8];
            float4 v1 = *(const float4*)&Vs[jj * HD + tc * 8 + 4];
#pragma unroll
            for (int i = 0; i < 4; i++) {
                o[i][0] = fmaf(p[i], v0.x, o[i][0]);
                o[i][1] = fmaf(p[i], v0.y, o[i][1]);
                o[i][2] = fmaf(p[i], v0.z, o[i][2]);
                o[i][3] = fmaf(p[i], v0.w, o[i][3]);
                o[i][4] = fmaf(p[i], v1.x, o[i][4]);
                o[i][5] = fmaf(p[i], v1.y, o[i][5]);
                o[i][6] = fmaf(p[i], v1.z, o[i][6]);
                o[i][7] = fmaf(p[i], v1.w, o[i][7]);
            }
        }
        __syncthreads();
    }

    if (t < BM) alph[t] = 1.f / l_i;
    __syncthreads();
#pragma unroll
    for (int i = 0; i < 4; i++) {
        float inv = alph[tr * 4 + i];
        size_t row = (size_t)b * Sq + q0 + tr * 4 + i;
        float* dst = Og + row * DOUT + h * HD + tc * 8;
        *(float4*)dst       = make_float4(o[i][0] * inv, o[i][1] * inv, o[i][2] * inv, o[i][3] * inv);
        *(float4*)(dst + 4) = make_float4(o[i][4] * inv, o[i][5] * inv, o[i][6] * inv, o[i][7] * inv);
    }
}

// ---------------------------------------------------------------------------
extern "C" void kernel_launch(void* const* d_in, const int* in_sizes, int n_in,
                              void* d_out, int out_size)
{
    const float* x    = (const float*)d_in[0];
    const float* Wq   = (const float*)d_in[1];
    const float* Wk   = (const float*)d_in[2];
    const float* Wv   = (const float*)d_in[3];
    const float* Wo   = (const float*)d_in[4];
    const float* cosT = (const float*)d_in[5];
    const float* sinT = (const float*)d_in[6];
    float* out = (float*)d_out;

    float *q, *k, *v, *ctx;
    cudaGetSymbolAddress((void**)&q,   g_q);
    cudaGetSymbolAddress((void**)&k,   g_k);
    cudaGetSymbolAddress((void**)&v,   g_v);
    cudaGetSymbolAddress((void**)&ctx, g_ctx);

    cudaFuncSetAttribute(gemm_mma,   cudaFuncAttributeMaxDynamicSharedMemorySize, GEMM_SMEM);
    cudaFuncSetAttribute(flash_attn, cudaFuncAttributeMaxDynamicSharedMemorySize, ATTN_SMEM);

    dim3 thr(256);
    gemm_mma<<<dim3(DOUT / 128, MROWS / 128), thr, GEMM_SMEM>>>(x, Wq, q, MROWS, DOUT, DIN);
    gemm_mma<<<dim3(DKV  / 128, MROWS / 128), thr, GEMM_SMEM>>>(x, Wk, k, MROWS, DKV,  DIN);
    gemm_mma<<<dim3(DKV  / 128, MROWS / 128), thr, GEMM_SMEM>>>(x, Wv, v, MROWS, DKV,  DIN);
    rope_kernel<<<MROWS * NH  * (HD / 2) / 256, thr>>>(q, cosT, sinT, NH);
    rope_kernel<<<MROWS * NKV * (HD / 2) / 256, thr>>>(k, cosT, sinT, NKV);
    flash_attn<<<dim3(Sq / BM, NH, Bb), thr, ATTN_SMEM>>>(q, k, v, ctx);
    gemm_mma<<<dim3(DOUT / 128, MROWS / 128), thr, GEMM_SMEM>>>(ctx, Wo, out, MROWS, DOUT, DOUT);
}

// round 4
// speedup vs baseline: 3.0508x; 1.7347x over previous
#include <cuda_runtime.h>
#include <cuda_bf16.h>
#include <cstdint>

// Problem constants
#define Bb    2
#define Sq    2048
#define DIN   2048
#define DOUT  2048
#define NH    16
#define NKV   4
#define HD    128
#define MROWS (Bb*Sq)        // 4096
#define DKV   (NKV*HD)       // 512

// Scratch
__device__ float g_q[(size_t)MROWS*DOUT];
__device__ float g_k[(size_t)MROWS*DKV];
__device__ float g_v[(size_t)MROWS*DKV];
__device__ float g_ctx[(size_t)MROWS*DOUT];

// ---------------------------------------------------------------------------
// Warp-level MMA helpers (standard PTX, base sm_103 target)
// ---------------------------------------------------------------------------
__device__ __forceinline__ uint32_t smem_u32(const void* p) {
    uint32_t a;
    asm("{ .reg .u64 t; cvta.to.shared.u64 t, %1; cvt.u32.u64 %0, t; }" : "=r"(a) : "l"(p));
    return a;
}
__device__ __forceinline__ void ldsm_x4(uint32_t& r0, uint32_t& r1, uint32_t& r2, uint32_t& r3,
                                        uint32_t addr) {
    asm volatile("ldmatrix.sync.aligned.m8n8.x4.shared.b16 {%0,%1,%2,%3}, [%4];"
                 : "=r"(r0), "=r"(r1), "=r"(r2), "=r"(r3) : "r"(addr));
}
__device__ __forceinline__ void ldsm_x4t(uint32_t& r0, uint32_t& r1, uint32_t& r2, uint32_t& r3,
                                         uint32_t addr) {
    asm volatile("ldmatrix.sync.aligned.m8n8.x4.trans.shared.b16 {%0,%1,%2,%3}, [%4];"
                 : "=r"(r0), "=r"(r1), "=r"(r2), "=r"(r3) : "r"(addr));
}
__device__ __forceinline__ void mma16816(float* d, const uint32_t* a, const uint32_t* b) {
    asm volatile(
        "mma.sync.aligned.m16n8k16.row.col.f32.bf16.bf16.f32 "
        "{%0,%1,%2,%3}, {%4,%5,%6,%7}, {%8,%9}, {%0,%1,%2,%3};"
        : "+f"(d[0]), "+f"(d[1]), "+f"(d[2]), "+f"(d[3])
        : "r"(a[0]), "r"(a[1]), "r"(a[2]), "r"(a[3]), "r"(b[0]), "r"(b[1]));
}
__device__ __forceinline__ uint32_t packbf2(__nv_bfloat16 a, __nv_bfloat16 b) {
    return (uint32_t)__bfloat16_as_ushort(a) | ((uint32_t)__bfloat16_as_ushort(b) << 16);
}
__device__ __forceinline__ uint32_t split_hi_pack(float a, float b, uint32_t& lo) {
    __nv_bfloat16 ha = __float2bfloat16(a), hb = __float2bfloat16(b);
    lo = packbf2(__float2bfloat16(a - __bfloat162float(ha)),
                 __float2bfloat16(b - __bfloat162float(hb)));
    return packbf2(ha, hb);
}

// ---------------------------------------------------------------------------
// HMMA bf16 GEMM with 2-term split (unchanged from R3, verified)
// ---------------------------------------------------------------------------
#define KC    64
#define A_STR 72
#define B_STR 136
#define AH_OFF 0
#define AL_OFF 18432
#define BH_OFF 36864
#define BL_OFF 54272
#define GEMM_SMEM 71680

__global__ __launch_bounds__(256) void gemm_mma(
    const float* __restrict__ A, const float* __restrict__ W,
    float* __restrict__ C, int M, int N, int K)
{
    extern __shared__ char smg[];
    const uint32_t sb = smem_u32(smg);
    const int t = threadIdx.x;
    const int wid = t >> 5, lane = t & 31;
    const int wm = wid >> 2, wn = wid & 3;
    const int row0 = blockIdx.y << 7, col0 = blockIdx.x << 7;

    float acc[4][4][4];
#pragma unroll
    for (int mi = 0; mi < 4; mi++)
#pragma unroll
        for (int nt = 0; nt < 4; nt++)
#pragma unroll
            for (int e = 0; e < 4; e++) acc[mi][nt][e] = 0.f;

    const int arow = lane & 15, agrp = (lane >> 4) << 3;

    const int nch = K / KC;
    for (int c = 0; c < nch; c++) {
        const int k0 = c * KC;
#pragma unroll
        for (int i = 0; i < 8; i++) {
            int li = t + (i << 8);
            int r = li >> 4, c4 = li & 15;
            float4 f = *(const float4*)(A + (size_t)(row0 + r) * K + k0 + c4 * 4);
            uint32_t l01, l23;
            uint32_t h01 = split_hi_pack(f.x, f.y, l01);
            uint32_t h23 = split_hi_pack(f.z, f.w, l23);
            uint32_t off = (uint32_t)(r * A_STR + c4 * 4) * 2;
            *(uint2*)(smg + AH_OFF + off) = make_uint2(h01, h23);
            *(uint2*)(smg + AL_OFF + off) = make_uint2(l01, l23);
        }
#pragma unroll
        for (int i = 0; i < 8; i++) {
            int li = t + (i << 8);
            int kk = li >> 5, n4 = li & 31;
            float4 f = *(const float4*)(W + (size_t)(k0 + kk) * N + col0 + n4 * 4);
            uint32_t l01, l23;
            uint32_t h01 = split_hi_pack(f.x, f.y, l01);
            uint32_t h23 = split_hi_pack(f.z, f.w, l23);
            uint32_t off = (uint32_t)(kk * B_STR + n4 * 4) * 2;
            *(uint2*)(smg + BH_OFF + off) = make_uint2(h01, h23);
            *(uint2*)(smg + BL_OFF + off) = make_uint2(l01, l23);
        }
        __syncthreads();

#pragma unroll
        for (int ks = 0; ks < 4; ks++) {
            uint32_t ah[4][4], al[4][4];
#pragma unroll
            for (int mi = 0; mi < 4; mi++) {
                uint32_t ao = (uint32_t)((wm * 64 + mi * 16 + arow) * A_STR + ks * 16 + agrp) * 2;
                ldsm_x4(ah[mi][0], ah[mi][1], ah[mi][2], ah[mi][3], sb + AH_OFF + ao);
                ldsm_x4(al[mi][0], al[mi][1], al[mi][2], al[mi][3], sb + AL_OFF + ao);
            }
            uint32_t bh[4][2], bl[4][2];
#pragma unroll
            for (int p = 0; p < 2; p++) {
                uint32_t bo = (uint32_t)((ks * 16 + arow) * B_STR + wn * 32 + p * 16 + agrp) * 2;
                uint32_t r0, r1, r2, r3;
                ldsm_x4t(r0, r1, r2, r3, sb + BH_OFF + bo);
                bh[2 * p][0] = r0; bh[2 * p][1] = r1;
                bh[2 * p + 1][0] = r2; bh[2 * p + 1][1] = r3;
                ldsm_x4t(r0, r1, r2, r3, sb + BL_OFF + bo);
                bl[2 * p][0] = r0; bl[2 * p][1] = r1;
                bl[2 * p + 1][0] = r2; bl[2 * p + 1][1] = r3;
            }
#pragma unroll
            for (int mi = 0; mi < 4; mi++)
#pragma unroll
                for (int nt = 0; nt < 4; nt++) {
                    mma16816(acc[mi][nt], ah[mi], bh[nt]);
                    mma16816(acc[mi][nt], al[mi], bh[nt]);
                    mma16816(acc[mi][nt], ah[mi], bl[nt]);
                }
        }
        __syncthreads();
    }

    const int drow = lane >> 2, dcol = (lane & 3) * 2;
#pragma unroll
    for (int mi = 0; mi < 4; mi++) {
        int r = row0 + wm * 64 + mi * 16 + drow;
#pragma unroll
        for (int nt = 0; nt < 4; nt++) {
            int col = col0 + wn * 32 + nt * 8 + dcol;
            *(float2*)(C + (size_t)r * N + col)       = make_float2(acc[mi][nt][0], acc[mi][nt][1]);
            *(float2*)(C + (size_t)(r + 8) * N + col) = make_float2(acc[mi][nt][2], acc[mi][nt][3]);
        }
    }
}

// ---------------------------------------------------------------------------
// RoPE in place on [B,S,nheads,HD].
// ---------------------------------------------------------------------------
__global__ void rope_kernel(float* __restrict__ tns,
                            const float* __restrict__ cosT,
                            const float* __restrict__ sinT, int nheads)
{
    const int hd2 = HD / 2;
    int idx = blockIdx.x * blockDim.x + threadIdx.x;
    if (idx >= MROWS * nheads * hd2) return;
    int d    = idx % hd2;
    int h    = (idx / hd2) % nheads;
    int sidx = idx / (hd2 * nheads);
    int s    = sidx & (Sq - 1);
    float* base = tns + ((size_t)sidx * nheads + h) * HD;
    float c1 = cosT[s * HD + d],       s1 = sinT[s * HD + d];
    float c2 = cosT[s * HD + d + hd2], s2 = sinT[s * HD + d + hd2];
    float t1 = base[d], t2 = base[d + hd2];
    base[d]       = t1 * c1 - t2 * s1;
    base[d + hd2] = t2 * c2 + t1 * s2;
}

// ---------------------------------------------------------------------------
// Tensor-core flash attention: BM=128 q rows, BN=64 keys, 8 warps.
// Each warp owns 16 full rows -> register softmax (quad shfl reduce).
// QK^T and PV both 3-pass bf16 split, fp32 accumulate.
// ---------------------------------------------------------------------------
#define FBM 128
#define FBN 64
#define F_STR 136               // bf16 elements per smem row (272B, bank step 4)
#define QH_OFF 0
#define QL_OFF 34816
#define KH_OFF 69632
#define KL_OFF 87040
#define VH_OFF 104448
#define VL_OFF 121856
#define FATTN_SMEM 139264

__global__ __launch_bounds__(256, 1) void flash_attn_mma(
    const float* __restrict__ Qg, const float* __restrict__ Kg,
    const float* __restrict__ Vg, float* __restrict__ Og)
{
    extern __shared__ char smf[];
    const uint32_t sb = smem_u32(smf);
    const int qtile = gridDim.x - 1 - blockIdx.x;
    const int h = blockIdx.y, b = blockIdx.z;
    const int kh = h >> 2;
    const int t = threadIdx.x;
    const int w = t >> 5, lane = t & 31;
    const int arow = lane & 15, agrp = (lane >> 4) << 3;
    const int q0 = qtile * FBM;
    const float scale = 0.08838834764831845f;

    // ---- stage Q tile 128x128 (scaled, split) ----
    {
        const float* qbase = Qg + (((size_t)b * Sq + q0) * NH + h) * HD;
#pragma unroll
        for (int i = 0; i < 16; i++) {
            int li = t + (i << 8);
            int r = li >> 5, c4 = li & 31;
            float4 f = *(const float4*)(qbase + (size_t)r * NH * HD + c4 * 4);
            f.x *= scale; f.y *= scale; f.z *= scale; f.w *= scale;
            uint32_t l01, l23;
            uint32_t h01 = split_hi_pack(f.x, f.y, l01);
            uint32_t h23 = split_hi_pack(f.z, f.w, l23);
            uint32_t off = (uint32_t)(r * F_STR + c4 * 4) * 2;
            *(uint2*)(smf + QH_OFF + off) = make_uint2(h01, h23);
            *(uint2*)(smf + QL_OFF + off) = make_uint2(l01, l23);
        }
    }

    float o[16][4];
#pragma unroll
    for (int nt = 0; nt < 16; nt++)
#pragma unroll
        for (int e = 0; e < 4; e++) o[nt][e] = 0.f;
    float m0 = -1e30f, m1 = -1e30f, l0 = 0.f, l1 = 0.f;

    const int wrow_max = q0 + w * 16 + 15;   // last row this warp owns
    const int kend = q0 + FBM;

    for (int k0 = 0; k0 < kend; k0 += FBN) {
        // ---- stage K/V tiles 64x128 (split) ----
        __syncthreads();   // protect previous iteration's reads
        {
            const float* kbase = Kg + (((size_t)b * Sq + k0) * NKV + kh) * HD;
            const float* vbase = Vg + (((size_t)b * Sq + k0) * NKV + kh) * HD;
#pragma unroll
            for (int i = 0; i < 8; i++) {
                int li = t + (i << 8);
                int r = li >> 5, c4 = li & 31;
                uint32_t off = (uint32_t)(r * F_STR + c4 * 4) * 2;
                float4 f = *(const float4*)(kbase + (size_t)r * NKV * HD + c4 * 4);
                uint32_t l01, l23;
                uint32_t h01 = split_hi_pack(f.x, f.y, l01);
                uint32_t h23 = split_hi_pack(f.z, f.w, l23);
                *(uint2*)(smf + KH_OFF + off) = make_uint2(h01, h23);
                *(uint2*)(smf + KL_OFF + off) = make_uint2(l01, l23);
                f = *(const float4*)(vbase + (size_t)r * NKV * HD + c4 * 4);
                h01 = split_hi_pack(f.x, f.y, l01);
                h23 = split_hi_pack(f.z, f.w, l23);
                *(uint2*)(smf + VH_OFF + off) = make_uint2(h01, h23);
                *(uint2*)(smf + VL_OFF + off) = make_uint2(l01, l23);
            }
        }
        __syncthreads();

        if (k0 > wrow_max) continue;   // fully masked for this warp

        // ---- S = Q K^T (16 x 64 per warp), 3-pass split ----
        float s[8][4];
#pragma unroll
        for (int nt = 0; nt < 8; nt++)
#pragma unroll
            for (int e = 0; e < 4; e++) s[nt][e] = 0.f;

#pragma unroll
        for (int ks = 0; ks < 8; ks++) {
            uint32_t qh[4], ql[4];
            uint32_t qa = (uint32_t)((w * 16 + arow) * F_STR + ks * 16 + agrp) * 2;
            ldsm_x4(qh[0], qh[1], qh[2], qh[3], sb + QH_OFF + qa);
            ldsm_x4(ql[0], ql[1], ql[2], ql[3], sb + QL_OFF + qa);
#pragma unroll
            for (int g = 0; g < 4; g++) {
                uint32_t ka = (uint32_t)((g * 16 + arow) * F_STR + ks * 16 + agrp) * 2;
                uint32_t h0, h1, h2, h3, e0, e1, e2, e3;
                ldsm_x4(h0, h1, h2, h3, sb + KH_OFF + ka);   // non-trans: K[n,k]
                ldsm_x4(e0, e1, e2, e3, sb + KL_OFF + ka);
                uint32_t bh0[2] = {h0, h2}, bh1[2] = {h1, h3};
                uint32_t bl0[2] = {e0, e2}, bl1[2] = {e1, e3};
                mma16816(s[2 * g],     qh, bh0);
                mma16816(s[2 * g],     ql, bh0);
                mma16816(s[2 * g],     qh, bl0);
                mma16816(s[2 * g + 1], qh, bh1);
                mma16816(s[2 * g + 1], ql, bh1);
                mma16816(s[2 * g + 1], qh, bl1);
            }
        }

        // ---- causal mask (tail tiles only) ----
        const int rg0 = q0 + w * 16 + (lane >> 2);
        if (k0 + FBN - 1 > q0 + w * 16) {
            int cg = k0 + 2 * (lane & 3);
#pragma unroll
            for (int nt = 0; nt < 8; nt++) {
                int c = cg + nt * 8;
                if (c     > rg0)     s[nt][0] = -1e30f;
                if (c + 1 > rg0)     s[nt][1] = -1e30f;
                if (c     > rg0 + 8) s[nt][2] = -1e30f;
                if (c + 1 > rg0 + 8) s[nt][3] = -1e30f;
            }
        }

        // ---- register online softmax (rows rg0, rg0+8) ----
        float mx0 = -1e30f, mx1 = -1e30f;
#pragma unroll
        for (int nt = 0; nt < 8; nt++) {
            mx0 = fmaxf(mx0, fmaxf(s[nt][0], s[nt][1]));
            mx1 = fmaxf(mx1, fmaxf(s[nt][2], s[nt][3]));
        }
        mx0 = fmaxf(mx0, __shfl_xor_sync(0xffffffffu, mx0, 1));
        mx0 = fmaxf(mx0, __shfl_xor_sync(0xffffffffu, mx0, 2));
        mx1 = fmaxf(mx1, __shfl_xor_sync(0xffffffffu, mx1, 1));
        mx1 = fmaxf(mx1, __shfl_xor_sync(0xffffffffu, mx1, 2));
        float mn0 = fmaxf(m0, mx0), mn1 = fmaxf(m1, mx1);
        float a0 = __expf(m0 - mn0), a1 = __expf(m1 - mn1);
        m0 = mn0; m1 = mn1;

        float sum0 = 0.f, sum1 = 0.f;
#pragma unroll
        for (int nt = 0; nt < 8; nt++) {
            s[nt][0] = __expf(s[nt][0] - mn0);
            s[nt][1] = __expf(s[nt][1] - mn0);
            s[nt][2] = __expf(s[nt][2] - mn1);
            s[nt][3] = __expf(s[nt][3] - mn1);
            sum0 += s[nt][0] + s[nt][1];
            sum1 += s[nt][2] + s[nt][3];
        }
        sum0 += __shfl_xor_sync(0xffffffffu, sum0, 1);
        sum0 += __shfl_xor_sync(0xffffffffu, sum0, 2);
        sum1 += __shfl_xor_sync(0xffffffffu, sum1, 1);
        sum1 += __shfl_xor_sync(0xffffffffu, sum1, 2);
        l0 = l0 * a0 + sum0;
        l1 = l1 * a1 + sum1;

#pragma unroll
        for (int nt = 0; nt < 16; nt++) {
            o[nt][0] *= a0; o[nt][1] *= a0;
            o[nt][2] *= a1; o[nt][3] *= a1;
        }

        // ---- P -> bf16 hi/lo A-frags (4 k-steps over 64 keys) ----
        uint32_t aph[4][4], apl[4][4];
#pragma unroll
        for (int ts = 0; ts < 4; ts++) {
            aph[ts][0] = split_hi_pack(s[2 * ts][0],     s[2 * ts][1],     apl[ts][0]);
            aph[ts][1] = split_hi_pack(s[2 * ts][2],     s[2 * ts][3],     apl[ts][1]);
            aph[ts][2] = split_hi_pack(s[2 * ts + 1][0], s[2 * ts + 1][1], apl[ts][2]);
            aph[ts][3] = split_hi_pack(s[2 * ts + 1][2], s[2 * ts + 1][3], apl[ts][3]);
        }

        // ---- O += P V (16 x 128 per warp), 3-pass split ----
#pragma unroll
        for (int ts = 0; ts < 4; ts++) {
#pragma unroll
            for (int g = 0; g < 8; g++) {
                uint32_t va = (uint32_t)((ts * 16 + arow) * F_STR + g * 16 + agrp) * 2;
                uint32_t h0, h1, h2, h3, e0, e1, e2, e3;
                ldsm_x4t(h0, h1, h2, h3, sb + VH_OFF + va);  // trans: V[k,n]
                ldsm_x4t(e0, e1, e2, e3, sb + VL_OFF + va);
                uint32_t bh0[2] = {h0, h1}, bh1[2] = {h2, h3};
                uint32_t bl0[2] = {e0, e1}, bl1[2] = {e2, e3};
                mma16816(o[2 * g],     aph[ts], bh0);
                mma16816(o[2 * g],     apl[ts], bh0);
                mma16816(o[2 * g],     aph[ts], bl0);
                mma16816(o[2 * g + 1], aph[ts], bh1);
                mma16816(o[2 * g + 1], apl[ts], bh1);
                mma16816(o[2 * g + 1], aph[ts], bl1);
            }
        }
    }

    // ---- normalize + write ctx [b,s, h*HD + d] ----
    float inv0 = 1.f / l0, inv1 = 1.f / l1;
    const int rg0 = q0 + w * 16 + (lane >> 2);
    float* dst0 = Og + ((size_t)b * Sq + rg0) * DOUT + h * HD + 2 * (lane & 3);
    float* dst1 = dst0 + (size_t)8 * DOUT;
#pragma unroll
    for (int nt = 0; nt < 16; nt++) {
        *(float2*)(dst0 + nt * 8) = make_float2(o[nt][0] * inv0, o[nt][1] * inv0);
        *(float2*)(dst1 + nt * 8) = make_float2(o[nt][2] * inv1, o[nt][3] * inv1);
    }
}

// ---------------------------------------------------------------------------
extern "C" void kernel_launch(void* const* d_in, const int* in_sizes, int n_in,
                              void* d_out, int out_size)
{
    const float* x    = (const float*)d_in[0];
    const float* Wq   = (const float*)d_in[1];
    const float* Wk   = (const float*)d_in[2];
    const float* Wv   = (const float*)d_in[3];
    const float* Wo   = (const float*)d_in[4];
    const float* cosT = (const float*)d_in[5];
    const float* sinT = (const float*)d_in[6];
    float* out = (float*)d_out;

    float *q, *k, *v, *ctx;
    cudaGetSymbolAddress((void**)&q,   g_q);
    cudaGetSymbolAddress((void**)&k,   g_k);
    cudaGetSymbolAddress((void**)&v,   g_v);
    cudaGetSymbolAddress((void**)&ctx, g_ctx);

    cudaFuncSetAttribute(gemm_mma,       cudaFuncAttributeMaxDynamicSharedMemorySize, GEMM_SMEM);
    cudaFuncSetAttribute(flash_attn_mma, cudaFuncAttributeMaxDynamicSharedMemorySize, FATTN_SMEM);

    dim3 thr(256);
    gemm_mma<<<dim3(DOUT / 128, MROWS / 128), thr, GEMM_SMEM>>>(x, Wq, q, MROWS, DOUT, DIN);
    gemm_mma<<<dim3(DKV  / 128, MROWS / 128), thr, GEMM_SMEM>>>(x, Wk, k, MROWS, DKV,  DIN);
    gemm_mma<<<dim3(DKV  / 128, MROWS / 128), thr, GEMM_SMEM>>>(x, Wv, v, MROWS, DKV,  DIN);
    rope_kernel<<<MROWS * NH  * (HD / 2) / 256, thr>>>(q, cosT, sinT, NH);
    rope_kernel<<<MROWS * NKV * (HD / 2) / 256, thr>>>(k, cosT, sinT, NKV);
    flash_attn_mma<<<dim3(Sq / FBM, NH, Bb), thr, FATTN_SMEM>>>(q, k, v, ctx);
    gemm_mma<<<dim3(DOUT / 128, MROWS / 128), thr, GEMM_SMEM>>>(ctx, Wo, out, MROWS, DOUT, DOUT);
}

// round 5
// speedup vs baseline: 3.2321x; 1.0594x over previous
#include <cuda_runtime.h>
#include <cuda_bf16.h>
#include <cstdint>

// Problem constants
#define Bb    2
#define Sq    2048
#define DIN   2048
#define DOUT  2048
#define NH    16
#define NKV   4
#define HD    128
#define MROWS (Bb*Sq)        // 4096
#define DKV   (NKV*HD)       // 512

// Scratch
__device__ float g_q[(size_t)MROWS*DOUT];
__device__ float g_k[(size_t)MROWS*DKV];
__device__ float g_v[(size_t)MROWS*DKV];
// pre-split bf16 operands
__device__ __nv_bfloat16 g_xh[(size_t)MROWS*DIN],  g_xl[(size_t)MROWS*DIN];
__device__ __nv_bfloat16 g_wqh[(size_t)DIN*DOUT],  g_wql[(size_t)DIN*DOUT];
__device__ __nv_bfloat16 g_wkh[(size_t)DIN*DKV],   g_wkl[(size_t)DIN*DKV];
__device__ __nv_bfloat16 g_wvh[(size_t)DIN*DKV],   g_wvl[(size_t)DIN*DKV];
__device__ __nv_bfloat16 g_woh[(size_t)DOUT*DOUT], g_wol[(size_t)DOUT*DOUT];
__device__ __nv_bfloat16 g_ch[(size_t)MROWS*DOUT], g_cl[(size_t)MROWS*DOUT];

// ---------------------------------------------------------------------------
// Helpers
// ---------------------------------------------------------------------------
__device__ __forceinline__ uint32_t smem_u32(const void* p) {
    uint32_t a;
    asm("{ .reg .u64 t; cvta.to.shared.u64 t, %1; cvt.u32.u64 %0, t; }" : "=r"(a) : "l"(p));
    return a;
}
__device__ __forceinline__ void ldsm_x4(uint32_t& r0, uint32_t& r1, uint32_t& r2, uint32_t& r3,
                                        uint32_t addr) {
    asm volatile("ldmatrix.sync.aligned.m8n8.x4.shared.b16 {%0,%1,%2,%3}, [%4];"
                 : "=r"(r0), "=r"(r1), "=r"(r2), "=r"(r3) : "r"(addr));
}
__device__ __forceinline__ void ldsm_x4t(uint32_t& r0, uint32_t& r1, uint32_t& r2, uint32_t& r3,
                                         uint32_t addr) {
    asm volatile("ldmatrix.sync.aligned.m8n8.x4.trans.shared.b16 {%0,%1,%2,%3}, [%4];"
                 : "=r"(r0), "=r"(r1), "=r"(r2), "=r"(r3) : "r"(addr));
}
__device__ __forceinline__ void mma16816(float* d, const uint32_t* a, const uint32_t* b) {
    asm volatile(
        "mma.sync.aligned.m16n8k16.row.col.f32.bf16.bf16.f32 "
        "{%0,%1,%2,%3}, {%4,%5,%6,%7}, {%8,%9}, {%0,%1,%2,%3};"
        : "+f"(d[0]), "+f"(d[1]), "+f"(d[2]), "+f"(d[3])
        : "r"(a[0]), "r"(a[1]), "r"(a[2]), "r"(a[3]), "r"(b[0]), "r"(b[1]));
}
__device__ __forceinline__ uint32_t packbf2(__nv_bfloat16 a, __nv_bfloat16 b) {
    return (uint32_t)__bfloat16_as_ushort(a) | ((uint32_t)__bfloat16_as_ushort(b) << 16);
}
__device__ __forceinline__ uint32_t split_hi_pack(float a, float b, uint32_t& lo) {
    __nv_bfloat16 ha = __float2bfloat16(a), hb = __float2bfloat16(b);
    lo = packbf2(__float2bfloat16(a - __bfloat162float(ha)),
                 __float2bfloat16(b - __bfloat162float(hb)));
    return packbf2(ha, hb);
}
__device__ __forceinline__ void cpa16(uint32_t dst, const void* src) {
    asm volatile("cp.async.cg.shared.global [%0], [%1], 16;" :: "r"(dst), "l"(src));
}
#define CP_COMMIT() asm volatile("cp.async.commit_group;" ::: "memory")
#define CP_WAIT1()  asm volatile("cp.async.wait_group 1;" ::: "memory")

// ---------------------------------------------------------------------------
// fp32 -> bf16 hi/lo split (vectorized)
// ---------------------------------------------------------------------------
__global__ void split_kernel(const float* __restrict__ in,
                             __nv_bfloat16* __restrict__ hi,
                             __nv_bfloat16* __restrict__ lo, int n4)
{
    int i = blockIdx.x * blockDim.x + threadIdx.x;
    if (i >= n4) return;
    float4 f = ((const float4*)in)[i];
    uint32_t l01, l23;
    uint32_t h01 = split_hi_pack(f.x, f.y, l01);
    uint32_t h23 = split_hi_pack(f.z, f.w, l23);
    ((uint2*)hi)[i] = make_uint2(h01, h23);
    ((uint2*)lo)[i] = make_uint2(l01, l23);
}

// ---------------------------------------------------------------------------
// HMMA bf16 GEMM, pre-split inputs, double-buffered cp.async pipeline.
// C[M,N] = (Ah+Al)*(Bh+Bl) 3-pass; 128x128 tile, 8 warps, K chunks of 64.
// ---------------------------------------------------------------------------
#define KC    64
#define A_STR 72
#define B_STR 136
#define AH_OFF 0
#define AL_OFF 18432
#define BH_OFF 36864
#define BL_OFF 54272
#define STAGE  71680
#define GEMM_SMEM (2*STAGE)

#define GEMM_LOAD(k0, st)                                                            \
    {                                                                                \
        uint32_t base = sb + (st) * STAGE;                                           \
        _Pragma("unroll")                                                            \
        for (int i = 0; i < 4; i++) {                                                \
            int li = t + (i << 8);                                                   \
            int r = li >> 3, ch = li & 7;                                            \
            size_t so = (size_t)(row0 + r) * K + (k0) + ch * 8;                      \
            uint32_t dof = (uint32_t)(r * A_STR + ch * 8) * 2;                       \
            cpa16(base + AH_OFF + dof, Ah + so);                                     \
            cpa16(base + AL_OFF + dof, Al + so);                                     \
        }                                                                            \
        _Pragma("unroll")                                                            \
        for (int i = 0; i < 4; i++) {                                                \
            int li = t + (i << 8);                                                   \
            int kk = li >> 4, ch = li & 15;                                          \
            size_t so = (size_t)((k0) + kk) * N + col0 + ch * 8;                     \
            uint32_t dof = (uint32_t)(kk * B_STR + ch * 8) * 2;                      \
            cpa16(base + BH_OFF + dof, Bh + so);                                     \
            cpa16(base + BL_OFF + dof, Bl + so);                                     \
        }                                                                            \
    }

__global__ __launch_bounds__(256) void gemm_mma(
    const __nv_bfloat16* __restrict__ Ah, const __nv_bfloat16* __restrict__ Al,
    const __nv_bfloat16* __restrict__ Bh, const __nv_bfloat16* __restrict__ Bl,
    float* __restrict__ C, int M, int N, int K)
{
    extern __shared__ char smg[];
    const uint32_t sb = smem_u32(smg);
    const int t = threadIdx.x;
    const int wid = t >> 5, lane = t & 31;
    const int wm = wid >> 2, wn = wid & 3;
    const int row0 = blockIdx.y << 7, col0 = blockIdx.x << 7;

    float acc[4][4][4];
#pragma unroll
    for (int mi = 0; mi < 4; mi++)
#pragma unroll
        for (int nt = 0; nt < 4; nt++)
#pragma unroll
            for (int e = 0; e < 4; e++) acc[mi][nt][e] = 0.f;

    const int arow = lane & 15, agrp = (lane >> 4) << 3;
    const int nch = K / KC;

    GEMM_LOAD(0, 0);
    CP_COMMIT();
    if (nch > 1) GEMM_LOAD(KC, 1);
    CP_COMMIT();

    for (int c = 0; c < nch; c++) {
        CP_WAIT1();
        __syncthreads();

        const uint32_t stb = sb + (c & 1) * STAGE;
#pragma unroll
        for (int ks = 0; ks < 4; ks++) {
            uint32_t ah[4][4], al[4][4];
#pragma unroll
            for (int mi = 0; mi < 4; mi++) {
                uint32_t ao = (uint32_t)((wm * 64 + mi * 16 + arow) * A_STR + ks * 16 + agrp) * 2;
                ldsm_x4(ah[mi][0], ah[mi][1], ah[mi][2], ah[mi][3], stb + AH_OFF + ao);
                ldsm_x4(al[mi][0], al[mi][1], al[mi][2], al[mi][3], stb + AL_OFF + ao);
            }
            uint32_t bh[4][2], bl[4][2];
#pragma unroll
            for (int p = 0; p < 2; p++) {
                uint32_t bo = (uint32_t)((ks * 16 + arow) * B_STR + wn * 32 + p * 16 + agrp) * 2;
                uint32_t r0, r1, r2, r3;
                ldsm_x4t(r0, r1, r2, r3, stb + BH_OFF + bo);
                bh[2 * p][0] = r0; bh[2 * p][1] = r1;
                bh[2 * p + 1][0] = r2; bh[2 * p + 1][1] = r3;
                ldsm_x4t(r0, r1, r2, r3, stb + BL_OFF + bo);
                bl[2 * p][0] = r0; bl[2 * p][1] = r1;
                bl[2 * p + 1][0] = r2; bl[2 * p + 1][1] = r3;
            }
#pragma unroll
            for (int mi = 0; mi < 4; mi++)
#pragma unroll
                for (int nt = 0; nt < 4; nt++) {
                    mma16816(acc[mi][nt], ah[mi], bh[nt]);
                    mma16816(acc[mi][nt], al[mi], bh[nt]);
                    mma16816(acc[mi][nt], ah[mi], bl[nt]);
                }
        }
        __syncthreads();
        if (c + 2 < nch) GEMM_LOAD((c + 2) * KC, (c & 1));
        CP_COMMIT();
    }

    const int drow = lane >> 2, dcol = (lane & 3) * 2;
#pragma unroll
    for (int mi = 0; mi < 4; mi++) {
        int r = row0 + wm * 64 + mi * 16 + drow;
#pragma unroll
        for (int nt = 0; nt < 4; nt++) {
            int col = col0 + wn * 32 + nt * 8 + dcol;
            *(float2*)(C + (size_t)r * N + col)       = make_float2(acc[mi][nt][0], acc[mi][nt][1]);
            *(float2*)(C + (size_t)(r + 8) * N + col) = make_float2(acc[mi][nt][2], acc[mi][nt][3]);
        }
    }
}

// ---------------------------------------------------------------------------
// RoPE in place on [B,S,nheads,HD].
// ---------------------------------------------------------------------------
__global__ void rope_kernel(float* __restrict__ tns,
                            const float* __restrict__ cosT,
                            const float* __restrict__ sinT, int nheads)
{
    const int hd2 = HD / 2;
    int idx = blockIdx.x * blockDim.x + threadIdx.x;
    if (idx >= MROWS * nheads * hd2) return;
    int d    = idx % hd2;
    int h    = (idx / hd2) % nheads;
    int sidx = idx / (hd2 * nheads);
    int s    = sidx & (Sq - 1);
    float* base = tns + ((size_t)sidx * nheads + h) * HD;
    float c1 = cosT[s * HD + d],       s1 = sinT[s * HD + d];
    float c2 = cosT[s * HD + d + hd2], s2 = sinT[s * HD + d + hd2];
    float t1 = base[d], t2 = base[d + hd2];
    base[d]       = t1 * c1 - t2 * s1;
    base[d + hd2] = t2 * c2 + t1 * s2;
}

// ---------------------------------------------------------------------------
// Tensor-core flash attention (R4, verified) — epilogue now emits bf16 hi/lo.
// ---------------------------------------------------------------------------
#define FBM 128
#define FBN 64
#define F_STR 136
#define QH_OFF 0
#define QL_OFF 34816
#define KH_OFF 69632
#define KL_OFF 87040
#define VH_OFF 104448
#define VL_OFF 121856
#define FATTN_SMEM 139264

__global__ __launch_bounds__(256, 1) void flash_attn_mma(
    const float* __restrict__ Qg, const float* __restrict__ Kg,
    const float* __restrict__ Vg,
    __nv_bfloat16* __restrict__ Oh, __nv_bfloat16* __restrict__ Ol)
{
    extern __shared__ char smf[];
    const uint32_t sb = smem_u32(smf);
    const int qtile = gridDim.x - 1 - blockIdx.x;
    const int h = blockIdx.y, b = blockIdx.z;
    const int kh = h >> 2;
    const int t = threadIdx.x;
    const int w = t >> 5, lane = t & 31;
    const int arow = lane & 15, agrp = (lane >> 4) << 3;
    const int q0 = qtile * FBM;
    const float scale = 0.08838834764831845f;

    {
        const float* qbase = Qg + (((size_t)b * Sq + q0) * NH + h) * HD;
#pragma unroll
        for (int i = 0; i < 16; i++) {
            int li = t + (i << 8);
            int r = li >> 5, c4 = li & 31;
            float4 f = *(const float4*)(qbase + (size_t)r * NH * HD + c4 * 4);
            f.x *= scale; f.y *= scale; f.z *= scale; f.w *= scale;
            uint32_t l01, l23;
            uint32_t h01 = split_hi_pack(f.x, f.y, l01);
            uint32_t h23 = split_hi_pack(f.z, f.w, l23);
            uint32_t off = (uint32_t)(r * F_STR + c4 * 4) * 2;
            *(uint2*)(smf + QH_OFF + off) = make_uint2(h01, h23);
            *(uint2*)(smf + QL_OFF + off) = make_uint2(l01, l23);
        }
    }

    float o[16][4];
#pragma unroll
    for (int nt = 0; nt < 16; nt++)
#pragma unroll
        for (int e = 0; e < 4; e++) o[nt][e] = 0.f;
    float m0 = -1e30f, m1 = -1e30f, l0 = 0.f, l1 = 0.f;

    const int wrow_max = q0 + w * 16 + 15;
    const int kend = q0 + FBM;

    for (int k0 = 0; k0 < kend; k0 += FBN) {
        __syncthreads();
        {
            const float* kbase = Kg + (((size_t)b * Sq + k0) * NKV + kh) * HD;
            const float* vbase = Vg + (((size_t)b * Sq + k0) * NKV + kh) * HD;
#pragma unroll
            for (int i = 0; i < 8; i++) {
                int li = t + (i << 8);
                int r = li >> 5, c4 = li & 31;
                uint32_t off = (uint32_t)(r * F_STR + c4 * 4) * 2;
                float4 f = *(const float4*)(kbase + (size_t)r * NKV * HD + c4 * 4);
                uint32_t l01, l23;
                uint32_t h01 = split_hi_pack(f.x, f.y, l01);
                uint32_t h23 = split_hi_pack(f.z, f.w, l23);
                *(uint2*)(smf + KH_OFF + off) = make_uint2(h01, h23);
                *(uint2*)(smf + KL_OFF + off) = make_uint2(l01, l23);
                f = *(const float4*)(vbase + (size_t)r * NKV * HD + c4 * 4);
                h01 = split_hi_pack(f.x, f.y, l01);
                h23 = split_hi_pack(f.z, f.w, l23);
                *(uint2*)(smf + VH_OFF + off) = make_uint2(h01, h23);
                *(uint2*)(smf + VL_OFF + off) = make_uint2(l01, l23);
            }
        }
        __syncthreads();

        if (k0 > wrow_max) continue;

        float s[8][4];
#pragma unroll
        for (int nt = 0; nt < 8; nt++)
#pragma unroll
            for (int e = 0; e < 4; e++) s[nt][e] = 0.f;

#pragma unroll
        for (int ks = 0; ks < 8; ks++) {
            uint32_t qh[4], ql[4];
            uint32_t qa = (uint32_t)((w * 16 + arow) * F_STR + ks * 16 + agrp) * 2;
            ldsm_x4(qh[0], qh[1], qh[2], qh[3], sb + QH_OFF + qa);
            ldsm_x4(ql[0], ql[1], ql[2], ql[3], sb + QL_OFF + qa);
#pragma unroll
            for (int g = 0; g < 4; g++) {
                uint32_t ka = (uint32_t)((g * 16 + arow) * F_STR + ks * 16 + agrp) * 2;
                uint32_t h0, h1, h2, h3, e0, e1, e2, e3;
                ldsm_x4(h0, h1, h2, h3, sb + KH_OFF + ka);
                ldsm_x4(e0, e1, e2, e3, sb + KL_OFF + ka);
                uint32_t bh0[2] = {h0, h2}, bh1[2] = {h1, h3};
                uint32_t bl0[2] = {e0, e2}, bl1[2] = {e1, e3};
                mma16816(s[2 * g],     qh, bh0);
                mma16816(s[2 * g],     ql, bh0);
                mma16816(s[2 * g],     qh, bl0);
                mma16816(s[2 * g + 1], qh, bh1);
                mma16816(s[2 * g + 1], ql, bh1);
                mma16816(s[2 * g + 1], qh, bl1);
            }
        }

        const int rg0 = q0 + w * 16 + (lane >> 2);
        if (k0 + FBN - 1 > q0 + w * 16) {
            int cg = k0 + 2 * (lane & 3);
#pragma unroll
            for (int nt = 0; nt < 8; nt++) {
                int c = cg + nt * 8;
                if (c     > rg0)     s[nt][0] = -1e30f;
                if (c + 1 > rg0)     s[nt][1] = -1e30f;
                if (c     > rg0 + 8) s[nt][2] = -1e30f;
                if (c + 1 > rg0 + 8) s[nt][3] = -1e30f;
            }
        }

        float mx0 = -1e30f, mx1 = -1e30f;
#pragma unroll
        for (int nt = 0; nt < 8; nt++) {
            mx0 = fmaxf(mx0, fmaxf(s[nt][0], s[nt][1]));
            mx1 = fmaxf(mx1, fmaxf(s[nt][2], s[nt][3]));
        }
        mx0 = fmaxf(mx0, __shfl_xor_sync(0xffffffffu, mx0, 1));
        mx0 = fmaxf(mx0, __shfl_xor_sync(0xffffffffu, mx0, 2));
        mx1 = fmaxf(mx1, __shfl_xor_sync(0xffffffffu, mx1, 1));
        mx1 = fmaxf(mx1, __shfl_xor_sync(0xffffffffu, mx1, 2));
        float mn0 = fmaxf(m0, mx0), mn1 = fmaxf(m1, mx1);
        float a0 = __expf(m0 - mn0), a1 = __expf(m1 - mn1);
        m0 = mn0; m1 = mn1;

        float sum0 = 0.f, sum1 = 0.f;
#pragma unroll
        for (int nt = 0; nt < 8; nt++) {
            s[nt][0] = __expf(s[nt][0] - mn0);
            s[nt][1] = __expf(s[nt][1] - mn0);
            s[nt][2] = __expf(s[nt][2] - mn1);
            s[nt][3] = __expf(s[nt][3] - mn1);
            sum0 += s[nt][0] + s[nt][1];
            sum1 += s[nt][2] + s[nt][3];
        }
        sum0 += __shfl_xor_sync(0xffffffffu, sum0, 1);
        sum0 += __shfl_xor_sync(0xffffffffu, sum0, 2);
        sum1 += __shfl_xor_sync(0xffffffffu, sum1, 1);
        sum1 += __shfl_xor_sync(0xffffffffu, sum1, 2);
        l0 = l0 * a0 + sum0;
        l1 = l1 * a1 + sum1;

#pragma unroll
        for (int nt = 0; nt < 16; nt++) {
            o[nt][0] *= a0; o[nt][1] *= a0;
            o[nt][2] *= a1; o[nt][3] *= a1;
        }

        uint32_t aph[4][4], apl[4][4];
#pragma unroll
        for (int ts = 0; ts < 4; ts++) {
            aph[ts][0] = split_hi_pack(s[2 * ts][0],     s[2 * ts][1],     apl[ts][0]);
            aph[ts][1] = split_hi_pack(s[2 * ts][2],     s[2 * ts][3],     apl[ts][1]);
            aph[ts][2] = split_hi_pack(s[2 * ts + 1][0], s[2 * ts + 1][1], apl[ts][2]);
            aph[ts][3] = split_hi_pack(s[2 * ts + 1][2], s[2 * ts + 1][3], apl[ts][3]);
        }

#pragma unroll
        for (int ts = 0; ts < 4; ts++) {
#pragma unroll
            for (int g = 0; g < 8; g++) {
                uint32_t va = (uint32_t)((ts * 16 + arow) * F_STR + g * 16 + agrp) * 2;
                uint32_t h0, h1, h2, h3, e0, e1, e2, e3;
                ldsm_x4t(h0, h1, h2, h3, sb + VH_OFF + va);
                ldsm_x4t(e0, e1, e2, e3, sb + VL_OFF + va);
                uint32_t bh0[2] = {h0, h1}, bh1[2] = {h2, h3};
                uint32_t bl0[2] = {e0, e1}, bl1[2] = {e2, e3};
                mma16816(o[2 * g],     aph[ts], bh0);
                mma16816(o[2 * g],     apl[ts], bh0);
                mma16816(o[2 * g],     aph[ts], bl0);
                mma16816(o[2 * g + 1], aph[ts], bh1);
                mma16816(o[2 * g + 1], apl[ts], bh1);
                mma16816(o[2 * g + 1], aph[ts], bl1);
            }
        }
    }

    // ---- normalize + split + write ctx hi/lo bf16 ----
    float inv0 = 1.f / l0, inv1 = 1.f / l1;
    const int rg0 = q0 + w * 16 + (lane >> 2);
    size_t base0 = ((size_t)b * Sq + rg0) * DOUT + h * HD + 2 * (lane & 3);
    size_t base1 = base0 + (size_t)8 * DOUT;
#pragma unroll
    for (int nt = 0; nt < 16; nt++) {
        uint32_t lo0, lo1;
        uint32_t hi0 = split_hi_pack(o[nt][0] * inv0, o[nt][1] * inv0, lo0);
        uint32_t hi1 = split_hi_pack(o[nt][2] * inv1, o[nt][3] * inv1, lo1);
        ((uint32_t*)Oh)[(base0 + nt * 8) >> 1] = hi0;
        ((uint32_t*)Ol)[(base0 + nt * 8) >> 1] = lo0;
        ((uint32_t*)Oh)[(base1 + nt * 8) >> 1] = hi1;
        ((uint32_t*)Ol)[(base1 + nt * 8) >> 1] = lo1;
    }
}

// ---------------------------------------------------------------------------
extern "C" void kernel_launch(void* const* d_in, const int* in_sizes, int n_in,
                              void* d_out, int out_size)
{
    const float* x    = (const float*)d_in[0];
    const float* Wq   = (const float*)d_in[1];
    const float* Wk   = (const float*)d_in[2];
    const float* Wv   = (const float*)d_in[3];
    const float* Wo   = (const float*)d_in[4];
    const float* cosT = (const float*)d_in[5];
    const float* sinT = (const float*)d_in[6];
    float* out = (float*)d_out;

    float *q, *k, *v;
    __nv_bfloat16 *xh, *xl, *wqh, *wql, *wkh, *wkl, *wvh, *wvl, *woh, *wol, *ch, *cl;
    cudaGetSymbolAddress((void**)&q,   g_q);
    cudaGetSymbolAddress((void**)&k,   g_k);
    cudaGetSymbolAddress((void**)&v,   g_v);
    cudaGetSymbolAddress((void**)&xh,  g_xh);  cudaGetSymbolAddress((void**)&xl,  g_xl);
    cudaGetSymbolAddress((void**)&wqh, g_wqh); cudaGetSymbolAddress((void**)&wql, g_wql);
    cudaGetSymbolAddress((void**)&wkh, g_wkh); cudaGetSymbolAddress((void**)&wkl, g_wkl);
    cudaGetSymbolAddress((void**)&wvh, g_wvh); cudaGetSymbolAddress((void**)&wvl, g_wvl);
    cudaGetSymbolAddress((void**)&woh, g_woh); cudaGetSymbolAddress((void**)&wol, g_wol);
    cudaGetSymbolAddress((void**)&ch,  g_ch);  cudaGetSymbolAddress((void**)&cl,  g_cl);

    cudaFuncSetAttribute(gemm_mma,       cudaFuncAttributeMaxDynamicSharedMemorySize, GEMM_SMEM);
    cudaFuncSetAttribute(flash_attn_mma, cudaFuncAttributeMaxDynamicSharedMemorySize, FATTN_SMEM);

    dim3 thr(256);
    // Pre-split all GEMM operands to bf16 hi/lo
    split_kernel<<<(MROWS * DIN / 4 + 255) / 256, thr>>>(x,  xh,  xl,  MROWS * DIN / 4);
    split_kernel<<<(DIN * DOUT / 4 + 255) / 256, thr>>>(Wq, wqh, wql, DIN * DOUT / 4);
    split_kernel<<<(DIN * DKV  / 4 + 255) / 256, thr>>>(Wk, wkh, wkl, DIN * DKV / 4);
    split_kernel<<<(DIN * DKV  / 4 + 255) / 256, thr>>>(Wv, wvh, wvl, DIN * DKV / 4);
    split_kernel<<<(DOUT * DOUT / 4 + 255) / 256, thr>>>(Wo, woh, wol, DOUT * DOUT / 4);

    // QKV projections
    gemm_mma<<<dim3(DOUT / 128, MROWS / 128), thr, GEMM_SMEM>>>(xh, xl, wqh, wql, q, MROWS, DOUT, DIN);
    gemm_mma<<<dim3(DKV  / 128, MROWS / 128), thr, GEMM_SMEM>>>(xh, xl, wkh, wkl, k, MROWS, DKV,  DIN);
    gemm_mma<<<dim3(DKV  / 128, MROWS / 128), thr, GEMM_SMEM>>>(xh, xl, wvh, wvl, v, MROWS, DKV,  DIN);
    // RoPE
    rope_kernel<<<MROWS * NH  * (HD / 2) / 256, thr>>>(q, cosT, sinT, NH);
    rope_kernel<<<MROWS * NKV * (HD / 2) / 256, thr>>>(k, cosT, sinT, NKV);
    // Attention (emits ctx as bf16 hi/lo)
    flash_attn_mma<<<dim3(Sq / FBM, NH, Bb), thr, FATTN_SMEM>>>(q, k, v, ch, cl);
    // Output projection
    gemm_mma<<<dim3(DOUT / 128, MROWS / 128), thr, GEMM_SMEM>>>(ch, cl, woh, wol, out, MROWS, DOUT, DOUT);
}

// round 6
// speedup vs baseline: 4.9285x; 1.5249x over previous
#include <cuda_runtime.h>
#include <cuda_fp16.h>
#include <cstdint>

// Problem constants
#define Bb    2
#define Sq    2048
#define DIN   2048
#define DOUT  2048
#define NH    16
#define NKV   4
#define HD    128
#define MROWS (Bb*Sq)        // 4096
#define DKV   (NKV*HD)       // 512

// Scratch
__device__ float g_q[(size_t)MROWS*DOUT];
__device__ float g_k[(size_t)MROWS*DKV];
__device__ float g_v[(size_t)MROWS*DKV];
// pre-split fp16 operands (A-side split hi/lo; B-side hi only)
__device__ __half g_xh[(size_t)MROWS*DIN],  g_xl[(size_t)MROWS*DIN];
__device__ __half g_wqh[(size_t)DIN*DOUT];
__device__ __half g_wkh[(size_t)DIN*DKV];
__device__ __half g_wvh[(size_t)DIN*DKV];
__device__ __half g_woh[(size_t)DOUT*DOUT];
__device__ __half g_ch[(size_t)MROWS*DOUT], g_cl[(size_t)MROWS*DOUT];

// ---------------------------------------------------------------------------
// Helpers
// ---------------------------------------------------------------------------
__device__ __forceinline__ uint32_t smem_u32(const void* p) {
    uint32_t a;
    asm("{ .reg .u64 t; cvta.to.shared.u64 t, %1; cvt.u32.u64 %0, t; }" : "=r"(a) : "l"(p));
    return a;
}
__device__ __forceinline__ void ldsm_x4(uint32_t& r0, uint32_t& r1, uint32_t& r2, uint32_t& r3,
                                        uint32_t addr) {
    asm volatile("ldmatrix.sync.aligned.m8n8.x4.shared.b16 {%0,%1,%2,%3}, [%4];"
                 : "=r"(r0), "=r"(r1), "=r"(r2), "=r"(r3) : "r"(addr));
}
__device__ __forceinline__ void ldsm_x4t(uint32_t& r0, uint32_t& r1, uint32_t& r2, uint32_t& r3,
                                         uint32_t addr) {
    asm volatile("ldmatrix.sync.aligned.m8n8.x4.trans.shared.b16 {%0,%1,%2,%3}, [%4];"
                 : "=r"(r0), "=r"(r1), "=r"(r2), "=r"(r3) : "r"(addr));
}
__device__ __forceinline__ void mma16816(float* d, const uint32_t* a, const uint32_t* b) {
    asm volatile(
        "mma.sync.aligned.m16n8k16.row.col.f32.f16.f16.f32 "
        "{%0,%1,%2,%3}, {%4,%5,%6,%7}, {%8,%9}, {%0,%1,%2,%3};"
        : "+f"(d[0]), "+f"(d[1]), "+f"(d[2]), "+f"(d[3])
        : "r"(a[0]), "r"(a[1]), "r"(a[2]), "r"(a[3]), "r"(b[0]), "r"(b[1]));
}
__device__ __forceinline__ uint32_t packh2(__half a, __half b) {
    return (uint32_t)__half_as_ushort(a) | ((uint32_t)__half_as_ushort(b) << 16);
}
__device__ __forceinline__ uint32_t pack_hi(float a, float b) {
    __half2 h = __floats2half2_rn(a, b);
    return *(uint32_t*)&h;
}
__device__ __forceinline__ uint32_t split_hi_pack(float a, float b, uint32_t& lo) {
    __half ha = __float2half_rn(a), hb = __float2half_rn(b);
    lo = packh2(__float2half_rn(a - __half2float(ha)),
                __float2half_rn(b - __half2float(hb)));
    return packh2(ha, hb);
}
__device__ __forceinline__ void cpa16(uint32_t dst, const void* src) {
    asm volatile("cp.async.cg.shared.global [%0], [%1], 16;" :: "r"(dst), "l"(src));
}
#define CP_COMMIT() asm volatile("cp.async.commit_group;" ::: "memory")
#define CP_WAIT1()  asm volatile("cp.async.wait_group 1;" ::: "memory")

// ---------------------------------------------------------------------------
// fp32 -> fp16 hi/lo split, and hi-only convert
// ---------------------------------------------------------------------------
__global__ void split_kernel(const float* __restrict__ in,
                             __half* __restrict__ hi, __half* __restrict__ lo, int n4)
{
    int i = blockIdx.x * blockDim.x + threadIdx.x;
    if (i >= n4) return;
    float4 f = ((const float4*)in)[i];
    uint32_t l01, l23;
    uint32_t h01 = split_hi_pack(f.x, f.y, l01);
    uint32_t h23 = split_hi_pack(f.z, f.w, l23);
    ((uint2*)hi)[i] = make_uint2(h01, h23);
    ((uint2*)lo)[i] = make_uint2(l01, l23);
}
__global__ void conv_kernel(const float* __restrict__ in,
                            __half* __restrict__ hi, int n4)
{
    int i = blockIdx.x * blockDim.x + threadIdx.x;
    if (i >= n4) return;
    float4 f = ((const float4*)in)[i];
    ((uint2*)hi)[i] = make_uint2(pack_hi(f.x, f.y), pack_hi(f.z, f.w));
}

// ---------------------------------------------------------------------------
// HMMA fp16 GEMM, 2-pass split (Ah*Bh + Al*Bh), cp.async double buffer.
// C[M,N]; 128x128 tile, 8 warps, K chunks of 64.
// ---------------------------------------------------------------------------
#define KC    64
#define A_STR 72
#define B_STR 136
#define AH_OFF 0
#define AL_OFF 18432
#define BH_OFF 36864
#define STAGE  54272
#define GEMM_SMEM (2*STAGE)

#define GEMM_LOAD(k0, st)                                                            \
    {                                                                                \
        uint32_t base = sb + (st) * STAGE;                                           \
        _Pragma("unroll")                                                            \
        for (int i = 0; i < 4; i++) {                                                \
            int li = t + (i << 8);                                                   \
            int r = li >> 3, ch = li & 7;                                            \
            size_t so = (size_t)(row0 + r) * K + (k0) + ch * 8;                      \
            uint32_t dof = (uint32_t)(r * A_STR + ch * 8) * 2;                       \
            cpa16(base + AH_OFF + dof, Ah + so);                                     \
            cpa16(base + AL_OFF + dof, Al + so);                                     \
        }                                                                            \
        _Pragma("unroll")                                                            \
        for (int i = 0; i < 4; i++) {                                                \
            int li = t + (i << 8);                                                   \
            int kk = li >> 4, ch = li & 15;                                          \
            size_t so = (size_t)((k0) + kk) * N + col0 + ch * 8;                     \
            uint32_t dof = (uint32_t)(kk * B_STR + ch * 8) * 2;                      \
            cpa16(base + BH_OFF + dof, Bh + so);                                     \
        }                                                                            \
    }

__global__ __launch_bounds__(256) void gemm_mma(
    const __half* __restrict__ Ah, const __half* __restrict__ Al,
    const __half* __restrict__ Bh,
    float* __restrict__ C, int M, int N, int K)
{
    extern __shared__ char smg[];
    const uint32_t sb = smem_u32(smg);
    const int t = threadIdx.x;
    const int wid = t >> 5, lane = t & 31;
    const int wm = wid >> 2, wn = wid & 3;
    const int row0 = blockIdx.y << 7, col0 = blockIdx.x << 7;

    float acc[4][4][4];
#pragma unroll
    for (int mi = 0; mi < 4; mi++)
#pragma unroll
        for (int nt = 0; nt < 4; nt++)
#pragma unroll
            for (int e = 0; e < 4; e++) acc[mi][nt][e] = 0.f;

    const int arow = lane & 15, agrp = (lane >> 4) << 3;
    const int nch = K / KC;

    GEMM_LOAD(0, 0);
    CP_COMMIT();
    if (nch > 1) GEMM_LOAD(KC, 1);
    CP_COMMIT();

    for (int c = 0; c < nch; c++) {
        CP_WAIT1();
        __syncthreads();

        const uint32_t stb = sb + (c & 1) * STAGE;
#pragma unroll
        for (int ks = 0; ks < 4; ks++) {
            uint32_t ah[4][4], al[4][4];
#pragma unroll
            for (int mi = 0; mi < 4; mi++) {
                uint32_t ao = (uint32_t)((wm * 64 + mi * 16 + arow) * A_STR + ks * 16 + agrp) * 2;
                ldsm_x4(ah[mi][0], ah[mi][1], ah[mi][2], ah[mi][3], stb + AH_OFF + ao);
                ldsm_x4(al[mi][0], al[mi][1], al[mi][2], al[mi][3], stb + AL_OFF + ao);
            }
            uint32_t bh[4][2];
#pragma unroll
            for (int p = 0; p < 2; p++) {
                uint32_t bo = (uint32_t)((ks * 16 + arow) * B_STR + wn * 32 + p * 16 + agrp) * 2;
                uint32_t r0, r1, r2, r3;
                ldsm_x4t(r0, r1, r2, r3, stb + BH_OFF + bo);
                bh[2 * p][0] = r0; bh[2 * p][1] = r1;
                bh[2 * p + 1][0] = r2; bh[2 * p + 1][1] = r3;
            }
#pragma unroll
            for (int mi = 0; mi < 4; mi++)
#pragma unroll
                for (int nt = 0; nt < 4; nt++) {
                    mma16816(acc[mi][nt], ah[mi], bh[nt]);
                    mma16816(acc[mi][nt], al[mi], bh[nt]);
                }
        }
        __syncthreads();
        if (c + 2 < nch) GEMM_LOAD((c + 2) * KC, (c & 1));
        CP_COMMIT();
    }

    const int drow = lane >> 2, dcol = (lane & 3) * 2;
#pragma unroll
    for (int mi = 0; mi < 4; mi++) {
        int r = row0 + wm * 64 + mi * 16 + drow;
#pragma unroll
        for (int nt = 0; nt < 4; nt++) {
            int col = col0 + wn * 32 + nt * 8 + dcol;
            *(float2*)(C + (size_t)r * N + col)       = make_float2(acc[mi][nt][0], acc[mi][nt][1]);
            *(float2*)(C + (size_t)(r + 8) * N + col) = make_float2(acc[mi][nt][2], acc[mi][nt][3]);
        }
    }
}

// ---------------------------------------------------------------------------
// RoPE in place on [B,S,nheads,HD].
// ---------------------------------------------------------------------------
__global__ void rope_kernel(float* __restrict__ tns,
                            const float* __restrict__ cosT,
                            const float* __restrict__ sinT, int nheads)
{
    const int hd2 = HD / 2;
    int idx = blockIdx.x * blockDim.x + threadIdx.x;
    if (idx >= MROWS * nheads * hd2) return;
    int d    = idx % hd2;
    int h    = (idx / hd2) % nheads;
    int sidx = idx / (hd2 * nheads);
    int s    = sidx & (Sq - 1);
    float* base = tns + ((size_t)sidx * nheads + h) * HD;
    float c1 = cosT[s * HD + d],       s1 = sinT[s * HD + d];
    float c2 = cosT[s * HD + d + hd2], s2 = sinT[s * HD + d + hd2];
    float t1 = base[d], t2 = base[d + hd2];
    base[d]       = t1 * c1 - t2 * s1;
    base[d + hd2] = t2 * c2 + t1 * s2;
}

// ---------------------------------------------------------------------------
// Tensor-core flash attention, fp16 2-pass split (Q and P split; K,V hi only).
// ---------------------------------------------------------------------------
#define FBM 128
#define FBN 64
#define F_STR 136
#define QH_OFF 0
#define QL_OFF 34816
#define KH_OFF 69632
#define VH_OFF 87040
#define FATTN_SMEM 104448

__global__ __launch_bounds__(256, 1) void flash_attn_mma(
    const float* __restrict__ Qg, const float* __restrict__ Kg,
    const float* __restrict__ Vg,
    __half* __restrict__ Oh, __half* __restrict__ Ol)
{
    extern __shared__ char smf[];
    const uint32_t sb = smem_u32(smf);
    const int qtile = gridDim.x - 1 - blockIdx.x;
    const int h = blockIdx.y, b = blockIdx.z;
    const int kh = h >> 2;
    const int t = threadIdx.x;
    const int w = t >> 5, lane = t & 31;
    const int arow = lane & 15, agrp = (lane >> 4) << 3;
    const int q0 = qtile * FBM;
    const float scale = 0.08838834764831845f;

    // ---- stage Q tile 128x128 (scaled, split hi/lo) ----
    {
        const float* qbase = Qg + (((size_t)b * Sq + q0) * NH + h) * HD;
#pragma unroll
        for (int i = 0; i < 16; i++) {
            int li = t + (i << 8);
            int r = li >> 5, c4 = li & 31;
            float4 f = *(const float4*)(qbase + (size_t)r * NH * HD + c4 * 4);
            f.x *= scale; f.y *= scale; f.z *= scale; f.w *= scale;
            uint32_t l01, l23;
            uint32_t h01 = split_hi_pack(f.x, f.y, l01);
            uint32_t h23 = split_hi_pack(f.z, f.w, l23);
            uint32_t off = (uint32_t)(r * F_STR + c4 * 4) * 2;
            *(uint2*)(smf + QH_OFF + off) = make_uint2(h01, h23);
            *(uint2*)(smf + QL_OFF + off) = make_uint2(l01, l23);
        }
    }

    float o[16][4];
#pragma unroll
    for (int nt = 0; nt < 16; nt++)
#pragma unroll
        for (int e = 0; e < 4; e++) o[nt][e] = 0.f;
    float m0 = -1e30f, m1 = -1e30f, l0 = 0.f, l1 = 0.f;

    const int wrow_max = q0 + w * 16 + 15;
    const int kend = q0 + FBM;

    for (int k0 = 0; k0 < kend; k0 += FBN) {
        // ---- stage K/V tiles 64x128 (hi only) ----
        __syncthreads();
        {
            const float* kbase = Kg + (((size_t)b * Sq + k0) * NKV + kh) * HD;
            const float* vbase = Vg + (((size_t)b * Sq + k0) * NKV + kh) * HD;
#pragma unroll
            for (int i = 0; i < 8; i++) {
                int li = t + (i << 8);
                int r = li >> 5, c4 = li & 31;
                uint32_t off = (uint32_t)(r * F_STR + c4 * 4) * 2;
                float4 f = *(const float4*)(kbase + (size_t)r * NKV * HD + c4 * 4);
                *(uint2*)(smf + KH_OFF + off) = make_uint2(pack_hi(f.x, f.y), pack_hi(f.z, f.w));
                f = *(const float4*)(vbase + (size_t)r * NKV * HD + c4 * 4);
                *(uint2*)(smf + VH_OFF + off) = make_uint2(pack_hi(f.x, f.y), pack_hi(f.z, f.w));
            }
        }
        __syncthreads();

        if (k0 > wrow_max) continue;

        // ---- S = Q K^T (16 x 64 per warp), 2-pass ----
        float s[8][4];
#pragma unroll
        for (int nt = 0; nt < 8; nt++)
#pragma unroll
            for (int e = 0; e < 4; e++) s[nt][e] = 0.f;

#pragma unroll
        for (int ks = 0; ks < 8; ks++) {
            uint32_t qh[4], ql[4];
            uint32_t qa = (uint32_t)((w * 16 + arow) * F_STR + ks * 16 + agrp) * 2;
            ldsm_x4(qh[0], qh[1], qh[2], qh[3], sb + QH_OFF + qa);
            ldsm_x4(ql[0], ql[1], ql[2], ql[3], sb + QL_OFF + qa);
#pragma unroll
            for (int g = 0; g < 4; g++) {
                uint32_t ka = (uint32_t)((g * 16 + arow) * F_STR + ks * 16 + agrp) * 2;
                uint32_t h0, h1, h2, h3;
                ldsm_x4(h0, h1, h2, h3, sb + KH_OFF + ka);
                uint32_t bh0[2] = {h0, h2}, bh1[2] = {h1, h3};
                mma16816(s[2 * g],     qh, bh0);
                mma16816(s[2 * g],     ql, bh0);
                mma16816(s[2 * g + 1], qh, bh1);
                mma16816(s[2 * g + 1], ql, bh1);
            }
        }

        const int rg0 = q0 + w * 16 + (lane >> 2);
        if (k0 + FBN - 1 > q0 + w * 16) {
            int cg = k0 + 2 * (lane & 3);
#pragma unroll
            for (int nt = 0; nt < 8; nt++) {
                int c = cg + nt * 8;
                if (c     > rg0)     s[nt][0] = -1e30f;
                if (c + 1 > rg0)     s[nt][1] = -1e30f;
                if (c     > rg0 + 8) s[nt][2] = -1e30f;
                if (c + 1 > rg0 + 8) s[nt][3] = -1e30f;
            }
        }

        // ---- register online softmax ----
        float mx0 = -1e30f, mx1 = -1e30f;
#pragma unroll
        for (int nt = 0; nt < 8; nt++) {
            mx0 = fmaxf(mx0, fmaxf(s[nt][0], s[nt][1]));
            mx1 = fmaxf(mx1, fmaxf(s[nt][2], s[nt][3]));
        }
        mx0 = fmaxf(mx0, __shfl_xor_sync(0xffffffffu, mx0, 1));
        mx0 = fmaxf(mx0, __shfl_xor_sync(0xffffffffu, mx0, 2));
        mx1 = fmaxf(mx1, __shfl_xor_sync(0xffffffffu, mx1, 1));
        mx1 = fmaxf(mx1, __shfl_xor_sync(0xffffffffu, mx1, 2));
        float mn0 = fmaxf(m0, mx0), mn1 = fmaxf(m1, mx1);
        float a0 = __expf(m0 - mn0), a1 = __expf(m1 - mn1);
        m0 = mn0; m1 = mn1;

        float sum0 = 0.f, sum1 = 0.f;
#pragma unroll
        for (int nt = 0; nt < 8; nt++) {
            s[nt][0] = __expf(s[nt][0] - mn0);
            s[nt][1] = __expf(s[nt][1] - mn0);
            s[nt][2] = __expf(s[nt][2] - mn1);
            s[nt][3] = __expf(s[nt][3] - mn1);
            sum0 += s[nt][0] + s[nt][1];
            sum1 += s[nt][2] + s[nt][3];
        }
        sum0 += __shfl_xor_sync(0xffffffffu, sum0, 1);
        sum0 += __shfl_xor_sync(0xffffffffu, sum0, 2);
        sum1 += __shfl_xor_sync(0xffffffffu, sum1, 1);
        sum1 += __shfl_xor_sync(0xffffffffu, sum1, 2);
        l0 = l0 * a0 + sum0;
        l1 = l1 * a1 + sum1;

#pragma unroll
        for (int nt = 0; nt < 16; nt++) {
            o[nt][0] *= a0; o[nt][1] *= a0;
            o[nt][2] *= a1; o[nt][3] *= a1;
        }

        // ---- P -> fp16 hi/lo A-frags ----
        uint32_t aph[4][4], apl[4][4];
#pragma unroll
        for (int ts = 0; ts < 4; ts++) {
            aph[ts][0] = split_hi_pack(s[2 * ts][0],     s[2 * ts][1],     apl[ts][0]);
            aph[ts][1] = split_hi_pack(s[2 * ts][2],     s[2 * ts][3],     apl[ts][1]);
            aph[ts][2] = split_hi_pack(s[2 * ts + 1][0], s[2 * ts + 1][1], apl[ts][2]);
            aph[ts][3] = split_hi_pack(s[2 * ts + 1][2], s[2 * ts + 1][3], apl[ts][3]);
        }

        // ---- O += P V (2-pass) ----
#pragma unroll
        for (int ts = 0; ts < 4; ts++) {
#pragma unroll
            for (int g = 0; g < 8; g++) {
                uint32_t va = (uint32_t)((ts * 16 + arow) * F_STR + g * 16 + agrp) * 2;
                uint32_t h0, h1, h2, h3;
                ldsm_x4t(h0, h1, h2, h3, sb + VH_OFF + va);
                uint32_t bh0[2] = {h0, h1}, bh1[2] = {h2, h3};
                mma16816(o[2 * g],     aph[ts], bh0);
                mma16816(o[2 * g],     apl[ts], bh0);
                mma16816(o[2 * g + 1], aph[ts], bh1);
                mma16816(o[2 * g + 1], apl[ts], bh1);
            }
        }
    }

    // ---- normalize + split + write ctx hi/lo fp16 ----
    float inv0 = 1.f / l0, inv1 = 1.f / l1;
    const int rg0 = q0 + w * 16 + (lane >> 2);
    size_t base0 = ((size_t)b * Sq + rg0) * DOUT + h * HD + 2 * (lane & 3);
    size_t base1 = base0 + (size_t)8 * DOUT;
#pragma unroll
    for (int nt = 0; nt < 16; nt++) {
        uint32_t lo0, lo1;
        uint32_t hi0 = split_hi_pack(o[nt][0] * inv0, o[nt][1] * inv0, lo0);
        uint32_t hi1 = split_hi_pack(o[nt][2] * inv1, o[nt][3] * inv1, lo1);
        ((uint32_t*)Oh)[(base0 + nt * 8) >> 1] = hi0;
        ((uint32_t*)Ol)[(base0 + nt * 8) >> 1] = lo0;
        ((uint32_t*)Oh)[(base1 + nt * 8) >> 1] = hi1;
        ((uint32_t*)Ol)[(base1 + nt * 8) >> 1] = lo1;
    }
}

// ---------------------------------------------------------------------------
extern "C" void kernel_launch(void* const* d_in, const int* in_sizes, int n_in,
                              void* d_out, int out_size)
{
    const float* x    = (const float*)d_in[0];
    const float* Wq   = (const float*)d_in[1];
    const float* Wk   = (const float*)d_in[2];
    const float* Wv   = (const float*)d_in[3];
    const float* Wo   = (const float*)d_in[4];
    const float* cosT = (const float*)d_in[5];
    const float* sinT = (const float*)d_in[6];
    float* out = (float*)d_out;

    float *q, *k, *v;
    __half *xh, *xl, *wqh, *wkh, *wvh, *woh, *ch, *cl;
    cudaGetSymbolAddress((void**)&q,   g_q);
    cudaGetSymbolAddress((void**)&k,   g_k);
    cudaGetSymbolAddress((void**)&v,   g_v);
    cudaGetSymbolAddress((void**)&xh,  g_xh);  cudaGetSymbolAddress((void**)&xl, g_xl);
    cudaGetSymbolAddress((void**)&wqh, g_wqh);
    cudaGetSymbolAddress((void**)&wkh, g_wkh);
    cudaGetSymbolAddress((void**)&wvh, g_wvh);
    cudaGetSymbolAddress((void**)&woh, g_woh);
    cudaGetSymbolAddress((void**)&ch,  g_ch);  cudaGetSymbolAddress((void**)&cl, g_cl);

    cudaFuncSetAttribute(gemm_mma,       cudaFuncAttributeMaxDynamicSharedMemorySize, GEMM_SMEM);
    cudaFuncSetAttribute(flash_attn_mma, cudaFuncAttributeMaxDynamicSharedMemorySize, FATTN_SMEM);

    dim3 thr(256);
    // Pre-split x (hi/lo); weights hi only
    split_kernel<<<(MROWS * DIN / 4 + 255) / 256, thr>>>(x, xh, xl, MROWS * DIN / 4);
    conv_kernel<<<(DIN * DOUT / 4 + 255) / 256, thr>>>(Wq, wqh, DIN * DOUT / 4);
    conv_kernel<<<(DIN * DKV  / 4 + 255) / 256, thr>>>(Wk, wkh, DIN * DKV / 4);
    conv_kernel<<<(DIN * DKV  / 4 + 255) / 256, thr>>>(Wv, wvh, DIN * DKV / 4);
    conv_kernel<<<(DOUT * DOUT / 4 + 255) / 256, thr>>>(Wo, woh, DOUT * DOUT / 4);

    // QKV projections (2-pass fp16 split)
    gemm_mma<<<dim3(DOUT / 128, MROWS / 128), thr, GEMM_SMEM>>>(xh, xl, wqh, q, MROWS, DOUT, DIN);
    gemm_mma<<<dim3(DKV  / 128, MROWS / 128), thr, GEMM_SMEM>>>(xh, xl, wkh, k, MROWS, DKV,  DIN);
    gemm_mma<<<dim3(DKV  / 128, MROWS / 128), thr, GEMM_SMEM>>>(xh, xl, wvh, v, MROWS, DKV,  DIN);
    // RoPE
    rope_kernel<<<MROWS * NH  * (HD / 2) / 256, thr>>>(q, cosT, sinT, NH);
    rope_kernel<<<MROWS * NKV * (HD / 2) / 256, thr>>>(k, cosT, sinT, NKV);
    // Attention (emits ctx as fp16 hi/lo)
    flash_attn_mma<<<dim3(Sq / FBM, NH, Bb), thr, FATTN_SMEM>>>(q, k, v, ch, cl);
    // Output projection
    gemm_mma<<<dim3(DOUT / 128, MROWS / 128), thr, GEMM_SMEM>>>(ch, cl, woh, out, MROWS, DOUT, DOUT);
}

// round 7
// speedup vs baseline: 5.1276x; 1.0404x over previous
#include <cuda_runtime.h>
#include <cuda_fp16.h>
#include <cstdint>

// Problem constants
#define Bb    2
#define Sq    2048
#define DIN   2048
#define DOUT  2048
#define NH    16
#define NKV   4
#define HD    128
#define MROWS (Bb*Sq)        // 4096
#define DKV   (NKV*HD)       // 512
#define NQKV  (DOUT + 2*DKV) // 3072

// Scratch
__device__ float  g_qkv[(size_t)MROWS*NQKV];         // fused QKV output (fp32)
__device__ __half g_xh[(size_t)MROWS*DIN],  g_xl[(size_t)MROWS*DIN];
__device__ __half g_wqkv[(size_t)DIN*NQKV];          // fused weights (hi)
__device__ __half g_woh[(size_t)DOUT*DOUT];
__device__ __half g_qh[(size_t)MROWS*DOUT], g_ql[(size_t)MROWS*DOUT];
__device__ __half g_kh[(size_t)MROWS*DKV];
__device__ __half g_vh[(size_t)MROWS*DKV];
__device__ __half g_ch[(size_t)MROWS*DOUT], g_cl[(size_t)MROWS*DOUT];

// ---------------------------------------------------------------------------
// Helpers
// ---------------------------------------------------------------------------
__device__ __forceinline__ uint32_t smem_u32(const void* p) {
    uint32_t a;
    asm("{ .reg .u64 t; cvta.to.shared.u64 t, %1; cvt.u32.u64 %0, t; }" : "=r"(a) : "l"(p));
    return a;
}
__device__ __forceinline__ void ldsm_x4(uint32_t& r0, uint32_t& r1, uint32_t& r2, uint32_t& r3,
                                        uint32_t addr) {
    asm volatile("ldmatrix.sync.aligned.m8n8.x4.shared.b16 {%0,%1,%2,%3}, [%4];"
                 : "=r"(r0), "=r"(r1), "=r"(r2), "=r"(r3) : "r"(addr));
}
__device__ __forceinline__ void ldsm_x4t(uint32_t& r0, uint32_t& r1, uint32_t& r2, uint32_t& r3,
                                         uint32_t addr) {
    asm volatile("ldmatrix.sync.aligned.m8n8.x4.trans.shared.b16 {%0,%1,%2,%3}, [%4];"
                 : "=r"(r0), "=r"(r1), "=r"(r2), "=r"(r3) : "r"(addr));
}
__device__ __forceinline__ void mma16816(float* d, const uint32_t* a, const uint32_t* b) {
    asm volatile(
        "mma.sync.aligned.m16n8k16.row.col.f32.f16.f16.f32 "
        "{%0,%1,%2,%3}, {%4,%5,%6,%7}, {%8,%9}, {%0,%1,%2,%3};"
        : "+f"(d[0]), "+f"(d[1]), "+f"(d[2]), "+f"(d[3])
        : "r"(a[0]), "r"(a[1]), "r"(a[2]), "r"(a[3]), "r"(b[0]), "r"(b[1]));
}
__device__ __forceinline__ uint32_t packh2(__half a, __half b) {
    return (uint32_t)__half_as_ushort(a) | ((uint32_t)__half_as_ushort(b) << 16);
}
__device__ __forceinline__ uint32_t pack_hi(float a, float b) {
    __half2 h = __floats2half2_rn(a, b);
    return *(uint32_t*)&h;
}
__device__ __forceinline__ uint32_t split_hi_pack(float a, float b, uint32_t& lo) {
    __half ha = __float2half_rn(a), hb = __float2half_rn(b);
    lo = packh2(__float2half_rn(a - __half2float(ha)),
                __float2half_rn(b - __half2float(hb)));
    return packh2(ha, hb);
}
__device__ __forceinline__ void cpa16(uint32_t dst, const void* src) {
    asm volatile("cp.async.cg.shared.global [%0], [%1], 16;" :: "r"(dst), "l"(src));
}
#define CP_COMMIT() asm volatile("cp.async.commit_group;" ::: "memory")
#define CP_WAIT1()  asm volatile("cp.async.wait_group 1;" ::: "memory")
#define CP_WAIT0()  asm volatile("cp.async.wait_group 0;" ::: "memory")

// ---------------------------------------------------------------------------
// Conversions / prep
// ---------------------------------------------------------------------------
__global__ void split_kernel(const float* __restrict__ in,
                             __half* __restrict__ hi, __half* __restrict__ lo, int n4)
{
    int i = blockIdx.x * blockDim.x + threadIdx.x;
    if (i >= n4) return;
    float4 f = ((const float4*)in)[i];
    uint32_t l01, l23;
    uint32_t h01 = split_hi_pack(f.x, f.y, l01);
    uint32_t h23 = split_hi_pack(f.z, f.w, l23);
    ((uint2*)hi)[i] = make_uint2(h01, h23);
    ((uint2*)lo)[i] = make_uint2(l01, l23);
}
// fp32 [K,N] -> fp16 hi into out[k*ostride + ooff + n]
__global__ void convw_kernel(const float* __restrict__ in, __half* __restrict__ out,
                             int N, int ostride, int ooff, int n4)
{
    int i = blockIdx.x * blockDim.x + threadIdx.x;
    if (i >= n4) return;
    float4 f = ((const float4*)in)[i];
    int row = i / (N / 4), c4 = i % (N / 4);
    *(uint2*)(out + (size_t)row * ostride + ooff + c4 * 4)
        = make_uint2(pack_hi(f.x, f.y), pack_hi(f.z, f.w));
}
// q slice of qkv: rope + scale + fp16 hi/lo split
__global__ void prep_q(const float* __restrict__ qkv,
                       const float* __restrict__ cosT, const float* __restrict__ sinT,
                       __half* __restrict__ qh, __half* __restrict__ ql)
{
    const float scale = 0.08838834764831845f;
    int idx = blockIdx.x * blockDim.x + threadIdx.x;
    if (idx >= MROWS * NH * 64) return;
    int d = idx & 63, h = (idx >> 6) & (NH - 1), row = idx >> 10;
    int s = row & (Sq - 1);
    const float* src = qkv + (size_t)row * NQKV + h * HD;
    float t1 = src[d], t2 = src[d + 64];
    float c1 = cosT[s * HD + d],      s1 = sinT[s * HD + d];
    float c2 = cosT[s * HD + d + 64], s2 = sinT[s * HD + d + 64];
    float r1 = (t1 * c1 - t2 * s1) * scale;
    float r2 = (t2 * c2 + t1 * s2) * scale;
    size_t o = (size_t)row * DOUT + h * HD + d;
    __half h1 = __float2half_rn(r1), h2 = __float2half_rn(r2);
    qh[o]      = h1; ql[o]      = __float2half_rn(r1 - __half2float(h1));
    qh[o + 64] = h2; ql[o + 64] = __float2half_rn(r2 - __half2float(h2));
}
// k slice of qkv: rope + fp16 hi
__global__ void prep_k(const float* __restrict__ qkv,
                       const float* __restrict__ cosT, const float* __restrict__ sinT,
                       __half* __restrict__ kh)
{
    int idx = blockIdx.x * blockDim.x + threadIdx.x;
    if (idx >= MROWS * NKV * 64) return;
    int d = idx & 63, h = (idx >> 6) & (NKV - 1), row = idx >> 8;
    int s = row & (Sq - 1);
    const float* src = qkv + (size_t)row * NQKV + DOUT + h * HD;
    float t1 = src[d], t2 = src[d + 64];
    float c1 = cosT[s * HD + d],      s1 = sinT[s * HD + d];
    float c2 = cosT[s * HD + d + 64], s2 = sinT[s * HD + d + 64];
    size_t o = (size_t)row * DKV + h * HD + d;
    kh[o]      = __float2half_rn(t1 * c1 - t2 * s1);
    kh[o + 64] = __float2half_rn(t2 * c2 + t1 * s2);
}
// v slice of qkv: fp16 hi
__global__ void prep_v(const float* __restrict__ qkv, __half* __restrict__ vh, int n4)
{
    int i = blockIdx.x * blockDim.x + threadIdx.x;
    if (i >= n4) return;
    int row = i >> 7, c4 = i & 127;   // 512/4 = 128 vecs per row
    float4 f = *(const float4*)(qkv + (size_t)row * NQKV + DOUT + DKV + c4 * 4);
    ((uint2*)vh)[i] = make_uint2(pack_hi(f.x, f.y), pack_hi(f.z, f.w));
}

// ---------------------------------------------------------------------------
// HMMA fp16 GEMM, 2-pass split, cp.async double buffer (verified R6)
// ---------------------------------------------------------------------------
#define KC    64
#define A_STR 72
#define B_STR 136
#define AH_OFF 0
#define AL_OFF 18432
#define BH_OFF 36864
#define STAGE  54272
#define GEMM_SMEM (2*STAGE)

#define GEMM_LOAD(k0, st)                                                            \
    {                                                                                \
        uint32_t base = sb + (st) * STAGE;                                           \
        _Pragma("unroll")                                                            \
        for (int i = 0; i < 4; i++) {                                                \
            int li = t + (i << 8);                                                   \
            int r = li >> 3, ch = li & 7;                                            \
            size_t so = (size_t)(row0 + r) * K + (k0) + ch * 8;                      \
            uint32_t dof = (uint32_t)(r * A_STR + ch * 8) * 2;                       \
            cpa16(base + AH_OFF + dof, Ah + so);                                     \
            cpa16(base + AL_OFF + dof, Al + so);                                     \
        }                                                                            \
        _Pragma("unroll")                                                            \
        for (int i = 0; i < 4; i++) {                                                \
            int li = t + (i << 8);                                                   \
            int kk = li >> 4, ch = li & 15;                                          \
            size_t so = (size_t)((k0) + kk) * N + col0 + ch * 8;                     \
            uint32_t dof = (uint32_t)(kk * B_STR + ch * 8) * 2;                      \
            cpa16(base + BH_OFF + dof, Bh + so);                                     \
        }                                                                            \
    }

__global__ __launch_bounds__(256) void gemm_mma(
    const __half* __restrict__ Ah, const __half* __restrict__ Al,
    const __half* __restrict__ Bh,
    float* __restrict__ C, int M, int N, int K)
{
    extern __shared__ char smg[];
    const uint32_t sb = smem_u32(smg);
    const int t = threadIdx.x;
    const int wid = t >> 5, lane = t & 31;
    const int wm = wid >> 2, wn = wid & 3;
    const int row0 = blockIdx.y << 7, col0 = blockIdx.x << 7;

    float acc[4][4][4];
#pragma unroll
    for (int mi = 0; mi < 4; mi++)
#pragma unroll
        for (int nt = 0; nt < 4; nt++)
#pragma unroll
            for (int e = 0; e < 4; e++) acc[mi][nt][e] = 0.f;

    const int arow = lane & 15, agrp = (lane >> 4) << 3;
    const int nch = K / KC;

    GEMM_LOAD(0, 0);
    CP_COMMIT();
    if (nch > 1) GEMM_LOAD(KC, 1);
    CP_COMMIT();

    for (int c = 0; c < nch; c++) {
        CP_WAIT1();
        __syncthreads();

        const uint32_t stb = sb + (c & 1) * STAGE;
#pragma unroll
        for (int ks = 0; ks < 4; ks++) {
            uint32_t ah[4][4], al[4][4];
#pragma unroll
            for (int mi = 0; mi < 4; mi++) {
                uint32_t ao = (uint32_t)((wm * 64 + mi * 16 + arow) * A_STR + ks * 16 + agrp) * 2;
                ldsm_x4(ah[mi][0], ah[mi][1], ah[mi][2], ah[mi][3], stb + AH_OFF + ao);
                ldsm_x4(al[mi][0], al[mi][1], al[mi][2], al[mi][3], stb + AL_OFF + ao);
            }
            uint32_t bh[4][2];
#pragma unroll
            for (int p = 0; p < 2; p++) {
                uint32_t bo = (uint32_t)((ks * 16 + arow) * B_STR + wn * 32 + p * 16 + agrp) * 2;
                uint32_t r0, r1, r2, r3;
                ldsm_x4t(r0, r1, r2, r3, stb + BH_OFF + bo);
                bh[2 * p][0] = r0; bh[2 * p][1] = r1;
                bh[2 * p + 1][0] = r2; bh[2 * p + 1][1] = r3;
            }
#pragma unroll
            for (int mi = 0; mi < 4; mi++)
#pragma unroll
                for (int nt = 0; nt < 4; nt++) {
                    mma16816(acc[mi][nt], ah[mi], bh[nt]);
                    mma16816(acc[mi][nt], al[mi], bh[nt]);
                }
        }
        __syncthreads();
        if (c + 2 < nch) GEMM_LOAD((c + 2) * KC, (c & 1));
        CP_COMMIT();
    }

    const int drow = lane >> 2, dcol = (lane & 3) * 2;
#pragma unroll
    for (int mi = 0; mi < 4; mi++) {
        int r = row0 + wm * 64 + mi * 16 + drow;
#pragma unroll
        for (int nt = 0; nt < 4; nt++) {
            int col = col0 + wn * 32 + nt * 8 + dcol;
            *(float2*)(C + (size_t)r * N + col)       = make_float2(acc[mi][nt][0], acc[mi][nt][1]);
            *(float2*)(C + (size_t)(r + 8) * N + col) = make_float2(acc[mi][nt][2], acc[mi][nt][3]);
        }
    }
}

// ---------------------------------------------------------------------------
// Tensor-core flash attention: fp16 inputs pre-prepped, cp.async K/V pipeline.
// ---------------------------------------------------------------------------
#define FBM 128
#define FBN 64
#define F_STR 136
#define QH_OFF 0
#define QL_OFF 34816
#define KV0_OFF 69632
#define KV_STAGE 34816      // K(17408) + V(17408) per stage
#define FATTN_SMEM 139264

#define KV_LOAD(k0_, st)                                                             \
    {                                                                                \
        const __half* kb = Kh + ((size_t)b * Sq + (k0_)) * DKV + kh * HD;            \
        const __half* vb = Vh + ((size_t)b * Sq + (k0_)) * DKV + kh * HD;            \
        uint32_t kbase = sb + KV0_OFF + (st) * KV_STAGE;                             \
        _Pragma("unroll")                                                            \
        for (int i = 0; i < 4; i++) {                                                \
            int li = t + (i << 8);                                                   \
            int r = li >> 4, c8 = li & 15;                                           \
            uint32_t dof = (uint32_t)(r * F_STR + c8 * 8) * 2;                       \
            cpa16(kbase + dof,         kb + (size_t)r * DKV + c8 * 8);               \
            cpa16(kbase + 17408 + dof, vb + (size_t)r * DKV + c8 * 8);               \
        }                                                                            \
    }

__global__ __launch_bounds__(256, 1) void flash_attn_mma(
    const __half* __restrict__ Qh, const __half* __restrict__ Ql,
    const __half* __restrict__ Kh, const __half* __restrict__ Vh,
    __half* __restrict__ Oh, __half* __restrict__ Ol)
{
    extern __shared__ char smf[];
    const uint32_t sb = smem_u32(smf);
    const int qtile = gridDim.x - 1 - blockIdx.x;
    const int h = blockIdx.y, b = blockIdx.z;
    const int kh = h >> 2;
    const int t = threadIdx.x;
    const int w = t >> 5, lane = t & 31;
    const int arow = lane & 15, agrp = (lane >> 4) << 3;
    const int q0 = qtile * FBM;

    // ---- prefetch Q (hi/lo) + KV tile 0 as group 0 ----
    {
        const __half* qbh = Qh + ((size_t)b * Sq + q0) * DOUT + h * HD;
        const __half* qbl = Ql + ((size_t)b * Sq + q0) * DOUT + h * HD;
#pragma unroll
        for (int i = 0; i < 8; i++) {
            int li = t + (i << 8);
            int r = li >> 4, c8 = li & 15;
            uint32_t dof = (uint32_t)(r * F_STR + c8 * 8) * 2;
            cpa16(sb + QH_OFF + dof, qbh + (size_t)r * DOUT + c8 * 8);
            cpa16(sb + QL_OFF + dof, qbl + (size_t)r * DOUT + c8 * 8);
        }
    }
    KV_LOAD(0, 0);
    CP_COMMIT();

    float o[16][4];
#pragma unroll
    for (int nt = 0; nt < 16; nt++)
#pragma unroll
        for (int e = 0; e < 4; e++) o[nt][e] = 0.f;
    float m0 = -1e30f, m1 = -1e30f, l0 = 0.f, l1 = 0.f;

    const int wrow_max = q0 + w * 16 + 15;
    const int niter = (q0 + FBM) / FBN;

    for (int it = 0; it < niter; it++) {
        const int k0 = it * FBN;
        if (it + 1 < niter) {
            KV_LOAD((it + 1) * FBN, (it + 1) & 1);
            CP_COMMIT();
            CP_WAIT1();
        } else {
            CP_WAIT0();
        }
        __syncthreads();

        if (k0 <= wrow_max) {
            const uint32_t kvb = sb + KV0_OFF + (it & 1) * KV_STAGE;
            const uint32_t KHo = kvb, VHo = kvb + 17408;

            // ---- S = Q K^T (16 x 64 per warp), 2-pass ----
            float s[8][4];
#pragma unroll
            for (int nt = 0; nt < 8; nt++)
#pragma unroll
                for (int e = 0; e < 4; e++) s[nt][e] = 0.f;

#pragma unroll
            for (int ks = 0; ks < 8; ks++) {
                uint32_t qh[4], ql[4];
                uint32_t qa = (uint32_t)((w * 16 + arow) * F_STR + ks * 16 + agrp) * 2;
                ldsm_x4(qh[0], qh[1], qh[2], qh[3], sb + QH_OFF + qa);
                ldsm_x4(ql[0], ql[1], ql[2], ql[3], sb + QL_OFF + qa);
#pragma unroll
                for (int g = 0; g < 4; g++) {
                    uint32_t ka = (uint32_t)((g * 16 + arow) * F_STR + ks * 16 + agrp) * 2;
                    uint32_t h0, h1, h2, h3;
                    ldsm_x4(h0, h1, h2, h3, KHo + ka);
                    uint32_t bh0[2] = {h0, h2}, bh1[2] = {h1, h3};
                    mma16816(s[2 * g],     qh, bh0);
                    mma16816(s[2 * g],     ql, bh0);
                    mma16816(s[2 * g + 1], qh, bh1);
                    mma16816(s[2 * g + 1], ql, bh1);
                }
            }

            const int rg0 = q0 + w * 16 + (lane >> 2);
            if (k0 + FBN - 1 > q0 + w * 16) {
                int cg = k0 + 2 * (lane & 3);
#pragma unroll
                for (int nt = 0; nt < 8; nt++) {
                    int c = cg + nt * 8;
                    if (c     > rg0)     s[nt][0] = -1e30f;
                    if (c + 1 > rg0)     s[nt][1] = -1e30f;
                    if (c     > rg0 + 8) s[nt][2] = -1e30f;
                    if (c + 1 > rg0 + 8) s[nt][3] = -1e30f;
                }
            }

            // ---- register online softmax ----
            float mx0 = -1e30f, mx1 = -1e30f;
#pragma unroll
            for (int nt = 0; nt < 8; nt++) {
                mx0 = fmaxf(mx0, fmaxf(s[nt][0], s[nt][1]));
                mx1 = fmaxf(mx1, fmaxf(s[nt][2], s[nt][3]));
            }
            mx0 = fmaxf(mx0, __shfl_xor_sync(0xffffffffu, mx0, 1));
            mx0 = fmaxf(mx0, __shfl_xor_sync(0xffffffffu, mx0, 2));
            mx1 = fmaxf(mx1, __shfl_xor_sync(0xffffffffu, mx1, 1));
            mx1 = fmaxf(mx1, __shfl_xor_sync(0xffffffffu, mx1, 2));
            float mn0 = fmaxf(m0, mx0), mn1 = fmaxf(m1, mx1);
            float a0 = __expf(m0 - mn0), a1 = __expf(m1 - mn1);
            m0 = mn0; m1 = mn1;

            float sum0 = 0.f, sum1 = 0.f;
#pragma unroll
            for (int nt = 0; nt < 8; nt++) {
                s[nt][0] = __expf(s[nt][0] - mn0);
                s[nt][1] = __expf(s[nt][1] - mn0);
                s[nt][2] = __expf(s[nt][2] - mn1);
                s[nt][3] = __expf(s[nt][3] - mn1);
                sum0 += s[nt][0] + s[nt][1];
                sum1 += s[nt][2] + s[nt][3];
            }
            sum0 += __shfl_xor_sync(0xffffffffu, sum0, 1);
            sum0 += __shfl_xor_sync(0xffffffffu, sum0, 2);
            sum1 += __shfl_xor_sync(0xffffffffu, sum1, 1);
            sum1 += __shfl_xor_sync(0xffffffffu, sum1, 2);
            l0 = l0 * a0 + sum0;
            l1 = l1 * a1 + sum1;

#pragma unroll
            for (int nt = 0; nt < 16; nt++) {
                o[nt][0] *= a0; o[nt][1] *= a0;
                o[nt][2] *= a1; o[nt][3] *= a1;
            }

            // ---- P -> fp16 hi/lo A-frags ----
            uint32_t aph[4][4], apl[4][4];
#pragma unroll
            for (int ts = 0; ts < 4; ts++) {
                aph[ts][0] = split_hi_pack(s[2 * ts][0],     s[2 * ts][1],     apl[ts][0]);
                aph[ts][1] = split_hi_pack(s[2 * ts][2],     s[2 * ts][3],     apl[ts][1]);
                aph[ts][2] = split_hi_pack(s[2 * ts + 1][0], s[2 * ts + 1][1], apl[ts][2]);
                aph[ts][3] = split_hi_pack(s[2 * ts + 1][2], s[2 * ts + 1][3], apl[ts][3]);
            }

            // ---- O += P V (2-pass) ----
#pragma unroll
            for (int ts = 0; ts < 4; ts++) {
#pragma unroll
                for (int g = 0; g < 8; g++) {
                    uint32_t va = (uint32_t)((ts * 16 + arow) * F_STR + g * 16 + agrp) * 2;
                    uint32_t h0, h1, h2, h3;
                    ldsm_x4t(h0, h1, h2, h3, VHo + va);
                    uint32_t bh0[2] = {h0, h1}, bh1[2] = {h2, h3};
                    mma16816(o[2 * g],     aph[ts], bh0);
                    mma16816(o[2 * g],     apl[ts], bh0);
                    mma16816(o[2 * g + 1], aph[ts], bh1);
                    mma16816(o[2 * g + 1], apl[ts], bh1);
                }
            }
        }
        __syncthreads();
    }

    // ---- normalize + split + write ctx hi/lo fp16 ----
    float inv0 = 1.f / l0, inv1 = 1.f / l1;
    const int rg0 = q0 + w * 16 + (lane >> 2);
    size_t base0 = ((size_t)b * Sq + rg0) * DOUT + h * HD + 2 * (lane & 3);
    size_t base1 = base0 + (size_t)8 * DOUT;
#pragma unroll
    for (int nt = 0; nt < 16; nt++) {
        uint32_t lo0, lo1;
        uint32_t hi0 = split_hi_pack(o[nt][0] * inv0, o[nt][1] * inv0, lo0);
        uint32_t hi1 = split_hi_pack(o[nt][2] * inv1, o[nt][3] * inv1, lo1);
        ((uint32_t*)Oh)[(base0 + nt * 8) >> 1] = hi0;
        ((uint32_t*)Ol)[(base0 + nt * 8) >> 1] = lo0;
        ((uint32_t*)Oh)[(base1 + nt * 8) >> 1] = hi1;
        ((uint32_t*)Ol)[(base1 + nt * 8) >> 1] = lo1;
    }
}

// ---------------------------------------------------------------------------
extern "C" void kernel_launch(void* const* d_in, const int* in_sizes, int n_in,
                              void* d_out, int out_size)
{
    const float* x    = (const float*)d_in[0];
    const float* Wq   = (const float*)d_in[1];
    const float* Wk   = (const float*)d_in[2];
    const float* Wv   = (const float*)d_in[3];
    const float* Wo   = (const float*)d_in[4];
    const float* cosT = (const float*)d_in[5];
    const float* sinT = (const float*)d_in[6];
    float* out = (float*)d_out;

    float* qkv;
    __half *xh, *xl, *wqkv, *woh, *qh, *ql, *khb, *vhb, *ch, *cl;
    cudaGetSymbolAddress((void**)&qkv,  g_qkv);
    cudaGetSymbolAddress((void**)&xh,   g_xh);   cudaGetSymbolAddress((void**)&xl, g_xl);
    cudaGetSymbolAddress((void**)&wqkv, g_wqkv);
    cudaGetSymbolAddress((void**)&woh,  g_woh);
    cudaGetSymbolAddress((void**)&qh,   g_qh);   cudaGetSymbolAddress((void**)&ql, g_ql);
    cudaGetSymbolAddress((void**)&khb,  g_kh);
    cudaGetSymbolAddress((void**)&vhb,  g_vh);
    cudaGetSymbolAddress((void**)&ch,   g_ch);   cudaGetSymbolAddress((void**)&cl, g_cl);

    cudaFuncSetAttribute(gemm_mma,       cudaFuncAttributeMaxDynamicSharedMemorySize, GEMM_SMEM);
    cudaFuncSetAttribute(flash_attn_mma, cudaFuncAttributeMaxDynamicSharedMemorySize, FATTN_SMEM);

    dim3 thr(256);
    // Operand prep: x hi/lo split; weights hi into fused buffer
    split_kernel<<<(MROWS * DIN / 4 + 255) / 256, thr>>>(x, xh, xl, MROWS * DIN / 4);
    convw_kernel<<<(DIN * DOUT / 4 + 255) / 256, thr>>>(Wq, wqkv, DOUT, NQKV, 0,          DIN * DOUT / 4);
    convw_kernel<<<(DIN * DKV  / 4 + 255) / 256, thr>>>(Wk, wqkv, DKV,  NQKV, DOUT,       DIN * DKV / 4);
    convw_kernel<<<(DIN * DKV  / 4 + 255) / 256, thr>>>(Wv, wqkv, DKV,  NQKV, DOUT + DKV, DIN * DKV / 4);
    convw_kernel<<<(DOUT * DOUT / 4 + 255) / 256, thr>>>(Wo, woh, DOUT, DOUT, 0,          DOUT * DOUT / 4);

    // Fused QKV projection (one launch, N=3072)
    gemm_mma<<<dim3(NQKV / 128, MROWS / 128), thr, GEMM_SMEM>>>(xh, xl, wqkv, qkv, MROWS, NQKV, DIN);

    // Prep: rope+scale+split q; rope k (hi); v (hi)
    prep_q<<<MROWS * NH  * 64 / 256, thr>>>(qkv, cosT, sinT, qh, ql);
    prep_k<<<MROWS * NKV * 64 / 256, thr>>>(qkv, cosT, sinT, khb);
    prep_v<<<MROWS * DKV / 4 / 256, thr>>>(qkv, vhb, MROWS * DKV / 4);

    // Attention (cp.async pipelined)
    flash_attn_mma<<<dim3(Sq / FBM, NH, Bb), thr, FATTN_SMEM>>>(qh, ql, khb, vhb, ch, cl);

    // Output projection
    gemm_mma<<<dim3(DOUT / 128, MROWS / 128), thr, GEMM_SMEM>>>(ch, cl, woh, out, MROWS, DOUT, DOUT);
}

// round 8
// speedup vs baseline: 5.1456x; 1.0035x over previous
#include <cuda_runtime.h>
#include <cuda_fp16.h>
#include <cstdint>

// Problem constants
#define Bb    2
#define Sq    2048
#define DIN   2048
#define DOUT  2048
#define NH    16
#define NKV   4
#define HD    128
#define MROWS (Bb*Sq)        // 4096
#define DKV   (NKV*HD)       // 512
#define NQKV  (DOUT + 2*DKV) // 3072

// Scratch
__device__ float  g_qkv[(size_t)MROWS*NQKV];
__device__ __half g_xh[(size_t)MROWS*DIN],  g_xl[(size_t)MROWS*DIN];
__device__ __half g_wqkv[(size_t)DIN*NQKV];
__device__ __half g_woh[(size_t)DOUT*DOUT];
__device__ __half g_qh[(size_t)MROWS*DOUT], g_ql[(size_t)MROWS*DOUT];
__device__ __half g_kh[(size_t)MROWS*DKV];
__device__ __half g_vh[(size_t)MROWS*DKV];
__device__ __half g_ch[(size_t)MROWS*DOUT], g_cl[(size_t)MROWS*DOUT];

// ---------------------------------------------------------------------------
// Helpers
// ---------------------------------------------------------------------------
__device__ __forceinline__ uint32_t smem_u32(const void* p) {
    uint32_t a;
    asm("{ .reg .u64 t; cvta.to.shared.u64 t, %1; cvt.u32.u64 %0, t; }" : "=r"(a) : "l"(p));
    return a;
}
__device__ __forceinline__ void ldsm_x4(uint32_t& r0, uint32_t& r1, uint32_t& r2, uint32_t& r3,
                                        uint32_t addr) {
    asm volatile("ldmatrix.sync.aligned.m8n8.x4.shared.b16 {%0,%1,%2,%3}, [%4];"
                 : "=r"(r0), "=r"(r1), "=r"(r2), "=r"(r3) : "r"(addr));
}
__device__ __forceinline__ void ldsm_x4t(uint32_t& r0, uint32_t& r1, uint32_t& r2, uint32_t& r3,
                                         uint32_t addr) {
    asm volatile("ldmatrix.sync.aligned.m8n8.x4.trans.shared.b16 {%0,%1,%2,%3}, [%4];"
                 : "=r"(r0), "=r"(r1), "=r"(r2), "=r"(r3) : "r"(addr));
}
__device__ __forceinline__ void mma16816(float* d, const uint32_t* a, const uint32_t* b) {
    asm volatile(
        "mma.sync.aligned.m16n8k16.row.col.f32.f16.f16.f32 "
        "{%0,%1,%2,%3}, {%4,%5,%6,%7}, {%8,%9}, {%0,%1,%2,%3};"
        : "+f"(d[0]), "+f"(d[1]), "+f"(d[2]), "+f"(d[3])
        : "r"(a[0]), "r"(a[1]), "r"(a[2]), "r"(a[3]), "r"(b[0]), "r"(b[1]));
}
__device__ __forceinline__ uint32_t packh2(__half a, __half b) {
    return (uint32_t)__half_as_ushort(a) | ((uint32_t)__half_as_ushort(b) << 16);
}
__device__ __forceinline__ uint32_t pack_hi(float a, float b) {
    __half2 h = __floats2half2_rn(a, b);
    return *(uint32_t*)&h;
}
__device__ __forceinline__ uint32_t split_hi_pack(float a, float b, uint32_t& lo) {
    __half ha = __float2half_rn(a), hb = __float2half_rn(b);
    lo = packh2(__float2half_rn(a - __half2float(ha)),
                __float2half_rn(b - __half2float(hb)));
    return packh2(ha, hb);
}
__device__ __forceinline__ void cpa16(uint32_t dst, const void* src) {
    asm volatile("cp.async.cg.shared.global [%0], [%1], 16;" :: "r"(dst), "l"(src));
}
#define CP_COMMIT() asm volatile("cp.async.commit_group;" ::: "memory")
#define CP_WAIT1()  asm volatile("cp.async.wait_group 1;" ::: "memory")
#define CP_WAIT0()  asm volatile("cp.async.wait_group 0;" ::: "memory")

// ---------------------------------------------------------------------------
// Conversions / prep (unchanged, verified)
// ---------------------------------------------------------------------------
__global__ void split_kernel(const float* __restrict__ in,
                             __half* __restrict__ hi, __half* __restrict__ lo, int n4)
{
    int i = blockIdx.x * blockDim.x + threadIdx.x;
    if (i >= n4) return;
    float4 f = ((const float4*)in)[i];
    uint32_t l01, l23;
    uint32_t h01 = split_hi_pack(f.x, f.y, l01);
    uint32_t h23 = split_hi_pack(f.z, f.w, l23);
    ((uint2*)hi)[i] = make_uint2(h01, h23);
    ((uint2*)lo)[i] = make_uint2(l01, l23);
}
__global__ void convw_kernel(const float* __restrict__ in, __half* __restrict__ out,
                             int N, int ostride, int ooff, int n4)
{
    int i = blockIdx.x * blockDim.x + threadIdx.x;
    if (i >= n4) return;
    float4 f = ((const float4*)in)[i];
    int row = i / (N / 4), c4 = i % (N / 4);
    *(uint2*)(out + (size_t)row * ostride + ooff + c4 * 4)
        = make_uint2(pack_hi(f.x, f.y), pack_hi(f.z, f.w));
}
__global__ void prep_q(const float* __restrict__ qkv,
                       const float* __restrict__ cosT, const float* __restrict__ sinT,
                       __half* __restrict__ qh, __half* __restrict__ ql)
{
    const float scale = 0.08838834764831845f;
    int idx = blockIdx.x * blockDim.x + threadIdx.x;
    if (idx >= MROWS * NH * 64) return;
    int d = idx & 63, h = (idx >> 6) & (NH - 1), row = idx >> 10;
    int s = row & (Sq - 1);
    const float* src = qkv + (size_t)row * NQKV + h * HD;
    float t1 = src[d], t2 = src[d + 64];
    float c1 = cosT[s * HD + d],      s1 = sinT[s * HD + d];
    float c2 = cosT[s * HD + d + 64], s2 = sinT[s * HD + d + 64];
    float r1 = (t1 * c1 - t2 * s1) * scale;
    float r2 = (t2 * c2 + t1 * s2) * scale;
    size_t o = (size_t)row * DOUT + h * HD + d;
    __half h1 = __float2half_rn(r1), h2 = __float2half_rn(r2);
    qh[o]      = h1; ql[o]      = __float2half_rn(r1 - __half2float(h1));
    qh[o + 64] = h2; ql[o + 64] = __float2half_rn(r2 - __half2float(h2));
}
__global__ void prep_k(const float* __restrict__ qkv,
                       const float* __restrict__ cosT, const float* __restrict__ sinT,
                       __half* __restrict__ kh)
{
    int idx = blockIdx.x * blockDim.x + threadIdx.x;
    if (idx >= MROWS * NKV * 64) return;
    int d = idx & 63, h = (idx >> 6) & (NKV - 1), row = idx >> 8;
    int s = row & (Sq - 1);
    const float* src = qkv + (size_t)row * NQKV + DOUT + h * HD;
    float t1 = src[d], t2 = src[d + 64];
    float c1 = cosT[s * HD + d],      s1 = sinT[s * HD + d];
    float c2 = cosT[s * HD + d + 64], s2 = sinT[s * HD + d + 64];
    size_t o = (size_t)row * DKV + h * HD + d;
    kh[o]      = __float2half_rn(t1 * c1 - t2 * s1);
    kh[o + 64] = __float2half_rn(t2 * c2 + t1 * s2);
}
__global__ void prep_v(const float* __restrict__ qkv, __half* __restrict__ vh, int n4)
{
    int i = blockIdx.x * blockDim.x + threadIdx.x;
    if (i >= n4) return;
    int row = i >> 7, c4 = i & 127;
    float4 f = *(const float4*)(qkv + (size_t)row * NQKV + DOUT + DKV + c4 * 4);
    ((uint2*)vh)[i] = make_uint2(pack_hi(f.x, f.y), pack_hi(f.z, f.w));
}

// ---------------------------------------------------------------------------
// HMMA fp16 GEMM, 2-pass split, cp.async double buffer +
// register-level fragment double-buffering (hide ldmatrix latency under MMA).
// ---------------------------------------------------------------------------
#define KC    64
#define A_STR 72
#define B_STR 136
#define AH_OFF 0
#define AL_OFF 18432
#define BH_OFF 36864
#define STAGE  54272
#define GEMM_SMEM (2*STAGE)

#define GEMM_LOAD(k0, st)                                                            \
    {                                                                                \
        uint32_t base = sb + (st) * STAGE;                                           \
        _Pragma("unroll")                                                            \
        for (int i = 0; i < 4; i++) {                                                \
            int li = t + (i << 8);                                                   \
            int r = li >> 3, ch = li & 7;                                            \
            size_t so = (size_t)(row0 + r) * K + (k0) + ch * 8;                      \
            uint32_t dof = (uint32_t)(r * A_STR + ch * 8) * 2;                       \
            cpa16(base + AH_OFF + dof, Ah + so);                                     \
            cpa16(base + AL_OFF + dof, Al + so);                                     \
        }                                                                            \
        _Pragma("unroll")                                                            \
        for (int i = 0; i < 4; i++) {                                                \
            int li = t + (i << 8);                                                   \
            int kk = li >> 4, ch = li & 15;                                          \
            size_t so = (size_t)((k0) + kk) * N + col0 + ch * 8;                     \
            uint32_t dof = (uint32_t)(kk * B_STR + ch * 8) * 2;                      \
            cpa16(base + BH_OFF + dof, Bh + so);                                     \
        }                                                                            \
    }

#define FRAG_LOAD(buf, ks)                                                                    \
    {                                                                                         \
        _Pragma("unroll")                                                                     \
        for (int mi = 0; mi < 4; mi++) {                                                      \
            uint32_t ao = (uint32_t)((wm * 64 + mi * 16 + arow) * A_STR + (ks) * 16 + agrp) * 2; \
            ldsm_x4(ah[buf][mi][0], ah[buf][mi][1], ah[buf][mi][2], ah[buf][mi][3],           \
                    stb + AH_OFF + ao);                                                       \
            ldsm_x4(al[buf][mi][0], al[buf][mi][1], al[buf][mi][2], al[buf][mi][3],           \
                    stb + AL_OFF + ao);                                                       \
        }                                                                                     \
        _Pragma("unroll")                                                                     \
        for (int p = 0; p < 2; p++) {                                                         \
            uint32_t bo = (uint32_t)(((ks) * 16 + arow) * B_STR + wn * 32 + p * 16 + agrp) * 2; \
            uint32_t r0, r1, r2, r3;                                                          \
            ldsm_x4t(r0, r1, r2, r3, stb + BH_OFF + bo);                                      \
            bh[buf][2 * p][0] = r0;     bh[buf][2 * p][1] = r1;                               \
            bh[buf][2 * p + 1][0] = r2; bh[buf][2 * p + 1][1] = r3;                           \
        }                                                                                     \
    }

__global__ __launch_bounds__(256) void gemm_mma(
    const __half* __restrict__ Ah, const __half* __restrict__ Al,
    const __half* __restrict__ Bh,
    float* __restrict__ C, int M, int N, int K)
{
    extern __shared__ char smg[];
    const uint32_t sb = smem_u32(smg);
    const int t = threadIdx.x;
    const int wid = t >> 5, lane = t & 31;
    const int wm = wid >> 2, wn = wid & 3;
    const int row0 = blockIdx.y << 7, col0 = blockIdx.x << 7;

    float acc[4][4][4];
#pragma unroll
    for (int mi = 0; mi < 4; mi++)
#pragma unroll
        for (int nt = 0; nt < 4; nt++)
#pragma unroll
            for (int e = 0; e < 4; e++) acc[mi][nt][e] = 0.f;

    const int arow = lane & 15, agrp = (lane >> 4) << 3;
    const int nch = K / KC;

    GEMM_LOAD(0, 0);
    CP_COMMIT();
    if (nch > 1) GEMM_LOAD(KC, 1);
    CP_COMMIT();

    for (int c = 0; c < nch; c++) {
        CP_WAIT1();
        __syncthreads();

        const uint32_t stb = sb + (c & 1) * STAGE;
        uint32_t ah[2][4][4], al[2][4][4], bh[2][4][2];
        FRAG_LOAD(0, 0);                       // prologue: k-step 0 fragments
#pragma unroll
        for (int ks = 0; ks < 4; ks++) {
            const int cur = ks & 1;
            if (ks < 3) FRAG_LOAD(cur ^ 1, ks + 1);   // prefetch next k-step under MMA
#pragma unroll
            for (int mi = 0; mi < 4; mi++)
#pragma unroll
                for (int nt = 0; nt < 4; nt++) {
                    mma16816(acc[mi][nt], ah[cur][mi], bh[cur][nt]);
                    mma16816(acc[mi][nt], al[cur][mi], bh[cur][nt]);
                }
        }
        __syncthreads();
        if (c + 2 < nch) GEMM_LOAD((c + 2) * KC, (c & 1));
        CP_COMMIT();
    }

    const int drow = lane >> 2, dcol = (lane & 3) * 2;
#pragma unroll
    for (int mi = 0; mi < 4; mi++) {
        int r = row0 + wm * 64 + mi * 16 + drow;
#pragma unroll
        for (int nt = 0; nt < 4; nt++) {
            int col = col0 + wn * 32 + nt * 8 + dcol;
            *(float2*)(C + (size_t)r * N + col)       = make_float2(acc[mi][nt][0], acc[mi][nt][1]);
            *(float2*)(C + (size_t)(r + 8) * N + col) = make_float2(acc[mi][nt][2], acc[mi][nt][3]);
        }
    }
}

// ---------------------------------------------------------------------------
// Tensor-core flash attention (R7, verified) — unchanged this round.
// ---------------------------------------------------------------------------
#define FBM 128
#define FBN 64
#define F_STR 136
#define QH_OFF 0
#define QL_OFF 34816
#define KV0_OFF 69632
#define KV_STAGE 34816
#define FATTN_SMEM 139264

#define KV_LOAD(k0_, st)                                                             \
    {                                                                                \
        const __half* kb = Kh + ((size_t)b * Sq + (k0_)) * DKV + kh * HD;            \
        const __half* vb = Vh + ((size_t)b * Sq + (k0_)) * DKV + kh * HD;            \
        uint32_t kbase = sb + KV0_OFF + (st) * KV_STAGE;                             \
        _Pragma("unroll")                                                            \
        for (int i = 0; i < 4; i++) {                                                \
            int li = t + (i << 8);                                                   \
            int r = li >> 4, c8 = li & 15;                                           \
            uint32_t dof = (uint32_t)(r * F_STR + c8 * 8) * 2;                       \
            cpa16(kbase + dof,         kb + (size_t)r * DKV + c8 * 8);               \
            cpa16(kbase + 17408 + dof, vb + (size_t)r * DKV + c8 * 8);               \
        }                                                                            \
    }

__global__ __launch_bounds__(256, 1) void flash_attn_mma(
    const __half* __restrict__ Qh, const __half* __restrict__ Ql,
    const __half* __restrict__ Kh, const __half* __restrict__ Vh,
    __half* __restrict__ Oh, __half* __restrict__ Ol)
{
    extern __shared__ char smf[];
    const uint32_t sb = smem_u32(smf);
    const int qtile = gridDim.x - 1 - blockIdx.x;
    const int h = blockIdx.y, b = blockIdx.z;
    const int kh = h >> 2;
    const int t = threadIdx.x;
    const int w = t >> 5, lane = t & 31;
    const int arow = lane & 15, agrp = (lane >> 4) << 3;
    const int q0 = qtile * FBM;

    {
        const __half* qbh = Qh + ((size_t)b * Sq + q0) * DOUT + h * HD;
        const __half* qbl = Ql + ((size_t)b * Sq + q0) * DOUT + h * HD;
#pragma unroll
        for (int i = 0; i < 8; i++) {
            int li = t + (i << 8);
            int r = li >> 4, c8 = li & 15;
            uint32_t dof = (uint32_t)(r * F_STR + c8 * 8) * 2;
            cpa16(sb + QH_OFF + dof, qbh + (size_t)r * DOUT + c8 * 8);
            cpa16(sb + QL_OFF + dof, qbl + (size_t)r * DOUT + c8 * 8);
        }
    }
    KV_LOAD(0, 0);
    CP_COMMIT();

    float o[16][4];
#pragma unroll
    for (int nt = 0; nt < 16; nt++)
#pragma unroll
        for (int e = 0; e < 4; e++) o[nt][e] = 0.f;
    float m0 = -1e30f, m1 = -1e30f, l0 = 0.f, l1 = 0.f;

    const int wrow_max = q0 + w * 16 + 15;
    const int niter = (q0 + FBM) / FBN;

    for (int it = 0; it < niter; it++) {
        const int k0 = it * FBN;
        if (it + 1 < niter) {
            KV_LOAD((it + 1) * FBN, (it + 1) & 1);
            CP_COMMIT();
            CP_WAIT1();
        } else {
            CP_WAIT0();
        }
        __syncthreads();

        if (k0 <= wrow_max) {
            const uint32_t kvb = sb + KV0_OFF + (it & 1) * KV_STAGE;
            const uint32_t KHo = kvb, VHo = kvb + 17408;

            float s[8][4];
#pragma unroll
            for (int nt = 0; nt < 8; nt++)
#pragma unroll
                for (int e = 0; e < 4; e++) s[nt][e] = 0.f;

#pragma unroll
            for (int ks = 0; ks < 8; ks++) {
                uint32_t qh[4], ql[4];
                uint32_t qa = (uint32_t)((w * 16 + arow) * F_STR + ks * 16 + agrp) * 2;
                ldsm_x4(qh[0], qh[1], qh[2], qh[3], sb + QH_OFF + qa);
                ldsm_x4(ql[0], ql[1], ql[2], ql[3], sb + QL_OFF + qa);
#pragma unroll
                for (int g = 0; g < 4; g++) {
                    uint32_t ka = (uint32_t)((g * 16 + arow) * F_STR + ks * 16 + agrp) * 2;
                    uint32_t h0, h1, h2, h3;
                    ldsm_x4(h0, h1, h2, h3, KHo + ka);
                    uint32_t bh0[2] = {h0, h2}, bh1[2] = {h1, h3};
                    mma16816(s[2 * g],     qh, bh0);
                    mma16816(s[2 * g],     ql, bh0);
                    mma16816(s[2 * g + 1], qh, bh1);
                    mma16816(s[2 * g + 1], ql, bh1);
                }
            }

            const int rg0 = q0 + w * 16 + (lane >> 2);
            if (k0 + FBN - 1 > q0 + w * 16) {
                int cg = k0 + 2 * (lane & 3);
#pragma unroll
                for (int nt = 0; nt < 8; nt++) {
                    int c = cg + nt * 8;
                    if (c     > rg0)     s[nt][0] = -1e30f;
                    if (c + 1 > rg0)     s[nt][1] = -1e30f;
                    if (c     > rg0 + 8) s[nt][2] = -1e30f;
                    if (c + 1 > rg0 + 8) s[nt][3] = -1e30f;
                }
            }

            float mx0 = -1e30f, mx1 = -1e30f;
#pragma unroll
            for (int nt = 0; nt < 8; nt++) {
                mx0 = fmaxf(mx0, fmaxf(s[nt][0], s[nt][1]));
                mx1 = fmaxf(mx1, fmaxf(s[nt][2], s[nt][3]));
            }
            mx0 = fmaxf(mx0, __shfl_xor_sync(0xffffffffu, mx0, 1));
            mx0 = fmaxf(mx0, __shfl_xor_sync(0xffffffffu, mx0, 2));
            mx1 = fmaxf(mx1, __shfl_xor_sync(0xffffffffu, mx1, 1));
            mx1 = fmaxf(mx1, __shfl_xor_sync(0xffffffffu, mx1, 2));
            float mn0 = fmaxf(m0, mx0), mn1 = fmaxf(m1, mx1);
            float a0 = __expf(m0 - mn0), a1 = __expf(m1 - mn1);
            m0 = mn0; m1 = mn1;

            float sum0 = 0.f, sum1 = 0.f;
#pragma unroll
            for (int nt = 0; nt < 8; nt++) {
                s[nt][0] = __expf(s[nt][0] - mn0);
                s[nt][1] = __expf(s[nt][1] - mn0);
                s[nt][2] = __expf(s[nt][2] - mn1);
                s[nt][3] = __expf(s[nt][3] - mn1);
                sum0 += s[nt][0] + s[nt][1];
                sum1 += s[nt][2] + s[nt][3];
            }
            sum0 += __shfl_xor_sync(0xffffffffu, sum0, 1);
            sum0 += __shfl_xor_sync(0xffffffffu, sum0, 2);
            sum1 += __shfl_xor_sync(0xffffffffu, sum1, 1);
            sum1 += __shfl_xor_sync(0xffffffffu, sum1, 2);
            l0 = l0 * a0 + sum0;
            l1 = l1 * a1 + sum1;

#pragma unroll
            for (int nt = 0; nt < 16; nt++) {
                o[nt][0] *= a0; o[nt][1] *= a0;
                o[nt][2] *= a1; o[nt][3] *= a1;
            }

            uint32_t aph[4][4], apl[4][4];
#pragma unroll
            for (int ts = 0; ts < 4; ts++) {
                aph[ts][0] = split_hi_pack(s[2 * ts][0],     s[2 * ts][1],     apl[ts][0]);
                aph[ts][1] = split_hi_pack(s[2 * ts][2],     s[2 * ts][3],     apl[ts][1]);
                aph[ts][2] = split_hi_pack(s[2 * ts + 1][0], s[2 * ts + 1][1], apl[ts][2]);
                aph[ts][3] = split_hi_pack(s[2 * ts + 1][2], s[2 * ts + 1][3], apl[ts][3]);
            }

#pragma unroll
            for (int ts = 0; ts < 4; ts++) {
#pragma unroll
                for (int g = 0; g < 8; g++) {
                    uint32_t va = (uint32_t)((ts * 16 + arow) * F_STR + g * 16 + agrp) * 2;
                    uint32_t h0, h1, h2, h3;
                    ldsm_x4t(h0, h1, h2, h3, VHo + va);
                    uint32_t bh0[2] = {h0, h1}, bh1[2] = {h2, h3};
                    mma16816(o[2 * g],     aph[ts], bh0);
                    mma16816(o[2 * g],     apl[ts], bh0);
                    mma16816(o[2 * g + 1], aph[ts], bh1);
                    mma16816(o[2 * g + 1], apl[ts], bh1);
                }
            }
        }
        __syncthreads();
    }

    float inv0 = 1.f / l0, inv1 = 1.f / l1;
    const int rg0 = q0 + w * 16 + (lane >> 2);
    size_t base0 = ((size_t)b * Sq + rg0) * DOUT + h * HD + 2 * (lane & 3);
    size_t base1 = base0 + (size_t)8 * DOUT;
#pragma unroll
    for (int nt = 0; nt < 16; nt++) {
        uint32_t lo0, lo1;
        uint32_t hi0 = split_hi_pack(o[nt][0] * inv0, o[nt][1] * inv0, lo0);
        uint32_t hi1 = split_hi_pack(o[nt][2] * inv1, o[nt][3] * inv1, lo1);
        ((uint32_t*)Oh)[(base0 + nt * 8) >> 1] = hi0;
        ((uint32_t*)Ol)[(base0 + nt * 8) >> 1] = lo0;
        ((uint32_t*)Oh)[(base1 + nt * 8) >> 1] = hi1;
        ((uint32_t*)Ol)[(base1 + nt * 8) >> 1] = lo1;
    }
}

// ---------------------------------------------------------------------------
extern "C" void kernel_launch(void* const* d_in, const int* in_sizes, int n_in,
                              void* d_out, int out_size)
{
    const float* x    = (const float*)d_in[0];
    const float* Wq   = (const float*)d_in[1];
    const float* Wk   = (const float*)d_in[2];
    const float* Wv   = (const float*)d_in[3];
    const float* Wo   = (const float*)d_in[4];
    const float* cosT = (const float*)d_in[5];
    const float* sinT = (const float*)d_in[6];
    float* out = (float*)d_out;

    float* qkv;
    __half *xh, *xl, *wqkv, *woh, *qh, *ql, *khb, *vhb, *ch, *cl;
    cudaGetSymbolAddress((void**)&qkv,  g_qkv);
    cudaGetSymbolAddress((void**)&xh,   g_xh);   cudaGetSymbolAddress((void**)&xl, g_xl);
    cudaGetSymbolAddress((void**)&wqkv, g_wqkv);
    cudaGetSymbolAddress((void**)&woh,  g_woh);
    cudaGetSymbolAddress((void**)&qh,   g_qh);   cudaGetSymbolAddress((void**)&ql, g_ql);
    cudaGetSymbolAddress((void**)&khb,  g_kh);
    cudaGetSymbolAddress((void**)&vhb,  g_vh);
    cudaGetSymbolAddress((void**)&ch,   g_ch);   cudaGetSymbolAddress((void**)&cl, g_cl);

    cudaFuncSetAttribute(gemm_mma,       cudaFuncAttributeMaxDynamicSharedMemorySize, GEMM_SMEM);
    cudaFuncSetAttribute(flash_attn_mma, cudaFuncAttributeMaxDynamicSharedMemorySize, FATTN_SMEM);

    dim3 thr(256);
    split_kernel<<<(MROWS * DIN / 4 + 255) / 256, thr>>>(x, xh, xl, MROWS * DIN / 4);
    convw_kernel<<<(DIN * DOUT / 4 + 255) / 256, thr>>>(Wq, wqkv, DOUT, NQKV, 0,          DIN * DOUT / 4);
    convw_kernel<<<(DIN * DKV  / 4 + 255) / 256, thr>>>(Wk, wqkv, DKV,  NQKV, DOUT,       DIN * DKV / 4);
    convw_kernel<<<(DIN * DKV  / 4 + 255) / 256, thr>>>(Wv, wqkv, DKV,  NQKV, DOUT + DKV, DIN * DKV / 4);
    convw_kernel<<<(DOUT * DOUT / 4 + 255) / 256, thr>>>(Wo, woh, DOUT, DOUT, 0,          DOUT * DOUT / 4);

    gemm_mma<<<dim3(NQKV / 128, MROWS / 128), thr, GEMM_SMEM>>>(xh, xl, wqkv, qkv, MROWS, NQKV, DIN);

    prep_q<<<MROWS * NH  * 64 / 256, thr>>>(qkv, cosT, sinT, qh, ql);
    prep_k<<<MROWS * NKV * 64 / 256, thr>>>(qkv, cosT, sinT, khb);
    prep_v<<<MROWS * DKV / 4 / 256, thr>>>(qkv, vhb, MROWS * DKV / 4);

    flash_attn_mma<<<dim3(Sq / FBM, NH, Bb), thr, FATTN_SMEM>>>(qh, ql, khb, vhb, ch, cl);

    gemm_mma<<<dim3(DOUT / 128, MROWS / 128), thr, GEMM_SMEM>>>(ch, cl, woh, out, MROWS, DOUT, DOUT);
}

// round 10
// speedup vs baseline: 8.3197x; 1.6168x over previous
#include <cuda_runtime.h>
#include <cuda_fp16.h>
#include <cstdint>

// Problem constants
#define Bb    2
#define Sq    2048
#define DIN   2048
#define DOUT  2048
#define NH    16
#define NKV   4
#define HD    128
#define MROWS (Bb*Sq)        // 4096
#define DKV   (NKV*HD)       // 512
#define NQKV  (DOUT + 2*DKV) // 3072

// Scratch
__device__ float  g_qkv[(size_t)MROWS*NQKV];
__device__ __half g_xh[(size_t)MROWS*DIN];
__device__ __half g_wqkv[(size_t)DIN*NQKV];
__device__ __half g_woh[(size_t)DOUT*DOUT];
__device__ __half g_qh[(size_t)MROWS*DOUT];
__device__ __half g_kh[(size_t)MROWS*DKV];
__device__ __half g_vh[(size_t)MROWS*DKV];
__device__ __half g_ch[(size_t)MROWS*DOUT];

// ---------------------------------------------------------------------------
// Helpers
// ---------------------------------------------------------------------------
__device__ __forceinline__ uint32_t smem_u32(const void* p) {
    uint32_t a;
    asm("{ .reg .u64 t; cvta.to.shared.u64 t, %1; cvt.u32.u64 %0, t; }" : "=r"(a) : "l"(p));
    return a;
}
__device__ __forceinline__ void ldsm_x4(uint32_t& r0, uint32_t& r1, uint32_t& r2, uint32_t& r3,
                                        uint32_t addr) {
    asm volatile("ldmatrix.sync.aligned.m8n8.x4.shared.b16 {%0,%1,%2,%3}, [%4];"
                 : "=r"(r0), "=r"(r1), "=r"(r2), "=r"(r3) : "r"(addr));
}
__device__ __forceinline__ void ldsm_x4t(uint32_t& r0, uint32_t& r1, uint32_t& r2, uint32_t& r3,
                                         uint32_t addr) {
    asm volatile("ldmatrix.sync.aligned.m8n8.x4.trans.shared.b16 {%0,%1,%2,%3}, [%4];"
                 : "=r"(r0), "=r"(r1), "=r"(r2), "=r"(r3) : "r"(addr));
}
__device__ __forceinline__ void mma16816(float* d, const uint32_t* a, const uint32_t* b) {
    asm volatile(
        "mma.sync.aligned.m16n8k16.row.col.f32.f16.f16.f32 "
        "{%0,%1,%2,%3}, {%4,%5,%6,%7}, {%8,%9}, {%0,%1,%2,%3};"
        : "+f"(d[0]), "+f"(d[1]), "+f"(d[2]), "+f"(d[3])
        : "r"(a[0]), "r"(a[1]), "r"(a[2]), "r"(a[3]), "r"(b[0]), "r"(b[1]));
}
__device__ __forceinline__ uint32_t pack_hi(float a, float b) {
    __half2 h = __floats2half2_rn(a, b);
    return *(uint32_t*)&h;
}
__device__ __forceinline__ void cpa16(uint32_t dst, const void* src) {
    asm volatile("cp.async.cg.shared.global [%0], [%1], 16;" :: "r"(dst), "l"(src));
}
#define CP_COMMIT() asm volatile("cp.async.commit_group;" ::: "memory")
#define CP_WAIT1()  asm volatile("cp.async.wait_group 1;" ::: "memory")
#define CP_WAIT0()  asm volatile("cp.async.wait_group 0;" ::: "memory")

// ---------------------------------------------------------------------------
// Conversions / prep
// ---------------------------------------------------------------------------
__global__ void conv_kernel(const float* __restrict__ in, __half* __restrict__ hi, int n4)
{
    int i = blockIdx.x * blockDim.x + threadIdx.x;
    if (i >= n4) return;
    float4 f = ((const float4*)in)[i];
    ((uint2*)hi)[i] = make_uint2(pack_hi(f.x, f.y), pack_hi(f.z, f.w));
}
__global__ void convw_kernel(const float* __restrict__ in, __half* __restrict__ out,
                             int N, int ostride, int ooff, int n4)
{
    int i = blockIdx.x * blockDim.x + threadIdx.x;
    if (i >= n4) return;
    float4 f = ((const float4*)in)[i];
    int row = i / (N / 4), c4 = i % (N / 4);
    *(uint2*)(out + (size_t)row * ostride + ooff + c4 * 4)
        = make_uint2(pack_hi(f.x, f.y), pack_hi(f.z, f.w));
}
__global__ void prep_q(const float* __restrict__ qkv,
                       const float* __restrict__ cosT, const float* __restrict__ sinT,
                       __half* __restrict__ qh)
{
    const float scale = 0.08838834764831845f;
    int idx = blockIdx.x * blockDim.x + threadIdx.x;
    if (idx >= MROWS * NH * 64) return;
    int d = idx & 63, h = (idx >> 6) & (NH - 1), row = idx >> 10;
    int s = row & (Sq - 1);
    const float* src = qkv + (size_t)row * NQKV + h * HD;
    float t1 = src[d], t2 = src[d + 64];
    float c1 = cosT[s * HD + d],      s1 = sinT[s * HD + d];
    float c2 = cosT[s * HD + d + 64], s2 = sinT[s * HD + d + 64];
    size_t o = (size_t)row * DOUT + h * HD + d;
    qh[o]      = __float2half_rn((t1 * c1 - t2 * s1) * scale);
    qh[o + 64] = __float2half_rn((t2 * c2 + t1 * s2) * scale);
}
__global__ void prep_k(const float* __restrict__ qkv,
                       const float* __restrict__ cosT, const float* __restrict__ sinT,
                       __half* __restrict__ kh)
{
    int idx = blockIdx.x * blockDim.x + threadIdx.x;
    if (idx >= MROWS * NKV * 64) return;
    int d = idx & 63, h = (idx >> 6) & (NKV - 1), row = idx >> 8;
    int s = row & (Sq - 1);
    const float* src = qkv + (size_t)row * NQKV + DOUT + h * HD;
    float t1 = src[d], t2 = src[d + 64];
    float c1 = cosT[s * HD + d],      s1 = sinT[s * HD + d];
    float c2 = cosT[s * HD + d + 64], s2 = sinT[s * HD + d + 64];
    size_t o = (size_t)row * DKV + h * HD + d;
    kh[o]      = __float2half_rn(t1 * c1 - t2 * s1);
    kh[o + 64] = __float2half_rn(t2 * c2 + t1 * s2);
}
__global__ void prep_v(const float* __restrict__ qkv, __half* __restrict__ vh, int n4)
{
    int i = blockIdx.x * blockDim.x + threadIdx.x;
    if (i >= n4) return;
    int row = i >> 7, c4 = i & 127;
    float4 f = *(const float4*)(qkv + (size_t)row * NQKV + DOUT + DKV + c4 * 4);
    ((uint2*)vh)[i] = make_uint2(pack_hi(f.x, f.y), pack_hi(f.z, f.w));
}

// ---------------------------------------------------------------------------
// HMMA fp16 GEMM, single-pass (exact on fp16-rounded operands), cp.async
// double buffer. 128x128 tile, 8 warps (2x4), 64x32 warp tile, K chunks 64.
// ---------------------------------------------------------------------------
#define KC    64
#define A_STR 72
#define B_STR 136
#define A_OFF 0
#define B_OFF 18432
#define STAGE 35840
#define GEMM_SMEM (2*STAGE)

#define GEMM_LOAD(k0, st)                                                            \
    {                                                                                \
        uint32_t base = sb + (st) * STAGE;                                           \
        _Pragma("unroll")                                                            \
        for (int i = 0; i < 4; i++) {                                                \
            int li = t + (i << 8);                                                   \
            int r = li >> 3, ch = li & 7;                                            \
            size_t so = (size_t)(row0 + r) * K + (k0) + ch * 8;                      \
            cpa16(base + A_OFF + (uint32_t)(r * A_STR + ch * 8) * 2, Ah + so);       \
        }                                                                            \
        _Pragma("unroll")                                                            \
        for (int i = 0; i < 4; i++) {                                                \
            int li = t + (i << 8);                                                   \
            int kk = li >> 4, ch = li & 15;                                          \
            size_t so = (size_t)((k0) + kk) * N + col0 + ch * 8;                     \
            cpa16(base + B_OFF + (uint32_t)(kk * B_STR + ch * 8) * 2, Bh + so);      \
        }                                                                            \
    }

__global__ __launch_bounds__(256) void gemm_mma(
    const __half* __restrict__ Ah, const __half* __restrict__ Bh,
    float* __restrict__ C, int M, int N, int K)
{
    extern __shared__ char smg[];
    const uint32_t sb = smem_u32(smg);
    const int t = threadIdx.x;
    const int wid = t >> 5, lane = t & 31;
    const int wm = wid >> 2, wn = wid & 3;
    const int row0 = blockIdx.y << 7, col0 = blockIdx.x << 7;

    float acc[4][4][4];
#pragma unroll
    for (int mi = 0; mi < 4; mi++)
#pragma unroll
        for (int nt = 0; nt < 4; nt++)
#pragma unroll
            for (int e = 0; e < 4; e++) acc[mi][nt][e] = 0.f;

    const int arow = lane & 15, agrp = (lane >> 4) << 3;
    const int nch = K / KC;

    GEMM_LOAD(0, 0);
    CP_COMMIT();
    if (nch > 1) GEMM_LOAD(KC, 1);
    CP_COMMIT();

    for (int c = 0; c < nch; c++) {
        CP_WAIT1();
        __syncthreads();

        const uint32_t stb = sb + (c & 1) * STAGE;
#pragma unroll
        for (int ks = 0; ks < 4; ks++) {
            uint32_t a[4][4];
#pragma unroll
            for (int mi = 0; mi < 4; mi++) {
                uint32_t ao = (uint32_t)((wm * 64 + mi * 16 + arow) * A_STR + ks * 16 + agrp) * 2;
                ldsm_x4(a[mi][0], a[mi][1], a[mi][2], a[mi][3], stb + A_OFF + ao);
            }
            uint32_t b[4][2];
#pragma unroll
            for (int p = 0; p < 2; p++) {
                uint32_t bo = (uint32_t)((ks * 16 + arow) * B_STR + wn * 32 + p * 16 + agrp) * 2;
                uint32_t r0, r1, r2, r3;
                ldsm_x4t(r0, r1, r2, r3, stb + B_OFF + bo);
                b[2 * p][0] = r0;     b[2 * p][1] = r1;
                b[2 * p + 1][0] = r2; b[2 * p + 1][1] = r3;
            }
#pragma unroll
            for (int mi = 0; mi < 4; mi++)
#pragma unroll
                for (int nt = 0; nt < 4; nt++)
                    mma16816(acc[mi][nt], a[mi], b[nt]);
        }
        __syncthreads();
        if (c + 2 < nch) GEMM_LOAD((c + 2) * KC, (c & 1));
        CP_COMMIT();
    }

    const int drow = lane >> 2, dcol = (lane & 3) * 2;
#pragma unroll
    for (int mi = 0; mi < 4; mi++) {
        int r = row0 + wm * 64 + mi * 16 + drow;
#pragma unroll
        for (int nt = 0; nt < 4; nt++) {
            int col = col0 + wn * 32 + nt * 8 + dcol;
            *(float2*)(C + (size_t)r * N + col)       = make_float2(acc[mi][nt][0], acc[mi][nt][1]);
            *(float2*)(C + (size_t)(r + 8) * N + col) = make_float2(acc[mi][nt][2], acc[mi][nt][3]);
        }
    }
}

// ---------------------------------------------------------------------------
// Tensor-core flash attention, single-pass fp16 (exact on rounded operands).
// ---------------------------------------------------------------------------
#define FBM 128
#define FBN 64
#define F_STR 136
#define QH_OFF 0
#define KV0_OFF 34816
#define KV_STAGE 34816
#define FATTN_SMEM 104448

#define KV_LOAD(k0_, st)                                                             \
    {                                                                                \
        const __half* kb = Kh + ((size_t)b * Sq + (k0_)) * DKV + kh * HD;            \
        const __half* vb = Vh + ((size_t)b * Sq + (k0_)) * DKV + kh * HD;            \
        uint32_t kbase = sb + KV0_OFF + (st) * KV_STAGE;                             \
        _Pragma("unroll")                                                            \
        for (int i = 0; i < 4; i++) {                                                \
            int li = t + (i << 8);                                                   \
            int r = li >> 4, c8 = li & 15;                                           \
            uint32_t dof = (uint32_t)(r * F_STR + c8 * 8) * 2;                       \
            cpa16(kbase + dof,         kb + (size_t)r * DKV + c8 * 8);               \
            cpa16(kbase + 17408 + dof, vb + (size_t)r * DKV + c8 * 8);               \
        }                                                                            \
    }

__global__ __launch_bounds__(256, 1) void flash_attn_mma(
    const __half* __restrict__ Qh, const __half* __restrict__ Kh,
    const __half* __restrict__ Vh, __half* __restrict__ Oh)
{
    extern __shared__ char smf[];
    const uint32_t sb = smem_u32(smf);
    const int qtile = gridDim.x - 1 - blockIdx.x;
    const int h = blockIdx.y, b = blockIdx.z;
    const int kh = h >> 2;
    const int t = threadIdx.x;
    const int w = t >> 5, lane = t & 31;
    const int arow = lane & 15, agrp = (lane >> 4) << 3;
    const int q0 = qtile * FBM;

    {
        const __half* qb = Qh + ((size_t)b * Sq + q0) * DOUT + h * HD;
#pragma unroll
        for (int i = 0; i < 4; i++) {
            int li = t + (i << 8);
            int r = li >> 3, c8 = li & 7;
            // 128 rows x 128 halfs: 8 chunks/row
            uint32_t dof = (uint32_t)(r * F_STR + c8 * 16) * 2;
            cpa16(sb + QH_OFF + dof,      qb + (size_t)r * DOUT + c8 * 16);
            cpa16(sb + QH_OFF + dof + 16, qb + (size_t)r * DOUT + c8 * 16 + 8);
        }
    }
    KV_LOAD(0, 0);
    CP_COMMIT();

    float o[16][4];
#pragma unroll
    for (int nt = 0; nt < 16; nt++)
#pragma unroll
        for (int e = 0; e < 4; e++) o[nt][e] = 0.f;
    float m0 = -1e30f, m1 = -1e30f, l0 = 0.f, l1 = 0.f;

    const int wrow_max = q0 + w * 16 + 15;
    const int niter = (q0 + FBM) / FBN;

    for (int it = 0; it < niter; it++) {
        const int k0 = it * FBN;
        if (it + 1 < niter) {
            KV_LOAD((it + 1) * FBN, (it + 1) & 1);
            CP_COMMIT();
            CP_WAIT1();
        } else {
            CP_WAIT0();
        }
        __syncthreads();

        if (k0 <= wrow_max) {
            const uint32_t kvb = sb + KV0_OFF + (it & 1) * KV_STAGE;
            const uint32_t KHo = kvb, VHo = kvb + 17408;

            float s[8][4];
#pragma unroll
            for (int nt = 0; nt < 8; nt++)
#pragma unroll
                for (int e = 0; e < 4; e++) s[nt][e] = 0.f;

#pragma unroll
            for (int ks = 0; ks < 8; ks++) {
                uint32_t q[4];
                uint32_t qa = (uint32_t)((w * 16 + arow) * F_STR + ks * 16 + agrp) * 2;
                ldsm_x4(q[0], q[1], q[2], q[3], sb + QH_OFF + qa);
#pragma unroll
                for (int g = 0; g < 4; g++) {
                    uint32_t ka = (uint32_t)((g * 16 + arow) * F_STR + ks * 16 + agrp) * 2;
                    uint32_t h0, h1, h2, h3;
                    ldsm_x4(h0, h1, h2, h3, KHo + ka);
                    uint32_t b0[2] = {h0, h2}, b1[2] = {h1, h3};
                    mma16816(s[2 * g],     q, b0);
                    mma16816(s[2 * g + 1], q, b1);
                }
            }

            const int rg0 = q0 + w * 16 + (lane >> 2);
            if (k0 + FBN - 1 > q0 + w * 16) {
                int cg = k0 + 2 * (lane & 3);
#pragma unroll
                for (int nt = 0; nt < 8; nt++) {
                    int c = cg + nt * 8;
                    if (c     > rg0)     s[nt][0] = -1e30f;
                    if (c + 1 > rg0)     s[nt][1] = -1e30f;
                    if (c     > rg0 + 8) s[nt][2] = -1e30f;
                    if (c + 1 > rg0 + 8) s[nt][3] = -1e30f;
                }
            }

            float mx0 = -1e30f, mx1 = -1e30f;
#pragma unroll
            for (int nt = 0; nt < 8; nt++) {
                mx0 = fmaxf(mx0, fmaxf(s[nt][0], s[nt][1]));
                mx1 = fmaxf(mx1, fmaxf(s[nt][2], s[nt][3]));
            }
            mx0 = fmaxf(mx0, __shfl_xor_sync(0xffffffffu, mx0, 1));
            mx0 = fmaxf(mx0, __shfl_xor_sync(0xffffffffu, mx0, 2));
            mx1 = fmaxf(mx1, __shfl_xor_sync(0xffffffffu, mx1, 1));
            mx1 = fmaxf(mx1, __shfl_xor_sync(0xffffffffu, mx1, 2));
            float mn0 = fmaxf(m0, mx0), mn1 = fmaxf(m1, mx1);
            float a0 = __expf(m0 - mn0), a1 = __expf(m1 - mn1);
            m0 = mn0; m1 = mn1;

            float sum0 = 0.f, sum1 = 0.f;
#pragma unroll
            for (int nt = 0; nt < 8; nt++) {
                s[nt][0] = __expf(s[nt][0] - mn0);
                s[nt][1] = __expf(s[nt][1] - mn0);
                s[nt][2] = __expf(s[nt][2] - mn1);
                s[nt][3] = __expf(s[nt][3] - mn1);
                sum0 += s[nt][0] + s[nt][1];
                sum1 += s[nt][2] + s[nt][3];
            }
            sum0 += __shfl_xor_sync(0xffffffffu, sum0, 1);
            sum0 += __shfl_xor_sync(0xffffffffu, sum0, 2);
            sum1 += __shfl_xor_sync(0xffffffffu, sum1, 1);
            sum1 += __shfl_xor_sync(0xffffffffu, sum1, 2);
            l0 = l0 * a0 + sum0;
            l1 = l1 * a1 + sum1;

#pragma unroll
            for (int nt = 0; nt < 16; nt++) {
                o[nt][0] *= a0; o[nt][1] *= a0;
                o[nt][2] *= a1; o[nt][3] *= a1;
            }

            // P -> fp16 A-frags (single pass)
            uint32_t ap[4][4];
#pragma unroll
            for (int ts = 0; ts < 4; ts++) {
                ap[ts][0] = pack_hi(s[2 * ts][0],     s[2 * ts][1]);
                ap[ts][1] = pack_hi(s[2 * ts][2],     s[2 * ts][3]);
                ap[ts][2] = pack_hi(s[2 * ts + 1][0], s[2 * ts + 1][1]);
                ap[ts][3] = pack_hi(s[2 * ts + 1][2], s[2 * ts + 1][3]);
            }

#pragma unroll
            for (int ts = 0; ts < 4; ts++) {
#pragma unroll
                for (int g = 0; g < 8; g++) {
                    uint32_t va = (uint32_t)((ts * 16 + arow) * F_STR + g * 16 + agrp) * 2;
                    uint32_t h0, h1, h2, h3;
                    ldsm_x4t(h0, h1, h2, h3, VHo + va);
                    uint32_t b0[2] = {h0, h1}, b1[2] = {h2, h3};
                    mma16816(o[2 * g],     ap[ts], b0);
                    mma16816(o[2 * g + 1], ap[ts], b1);
                }
            }
        }
        __syncthreads();
    }

    // normalize + write ctx fp16
    float inv0 = 1.f / l0, inv1 = 1.f / l1;
    const int rg0 = q0 + w * 16 + (lane >> 2);
    size_t base0 = ((size_t)b * Sq + rg0) * DOUT + h * HD + 2 * (lane & 3);
    size_t base1 = base0 + (size_t)8 * DOUT;
#pragma unroll
    for (int nt = 0; nt < 16; nt++) {
        ((uint32_t*)Oh)[(base0 + nt * 8) >> 1] = pack_hi(o[nt][0] * inv0, o[nt][1] * inv0);
        ((uint32_t*)Oh)[(base1 + nt * 8) >> 1] = pack_hi(o[nt][2] * inv1, o[nt][3] * inv1);
    }
}

// ---------------------------------------------------------------------------
extern "C" void kernel_launch(void* const* d_in, const int* in_sizes, int n_in,
                              void* d_out, int out_size)
{
    const float* x    = (const float*)d_in[0];
    const float* Wq   = (const float*)d_in[1];
    const float* Wk   = (const float*)d_in[2];
    const float* Wv   = (const float*)d_in[3];
    const float* Wo   = (const float*)d_in[4];
    const float* cosT = (const float*)d_in[5];
    const float* sinT = (const float*)d_in[6];
    float* out = (float*)d_out;

    float* qkv;
    __half *xh, *wqkv, *woh, *qh, *khb, *vhb, *ch;
    cudaGetSymbolAddress((void**)&qkv,  g_qkv);
    cudaGetSymbolAddress((void**)&xh,   g_xh);
    cudaGetSymbolAddress((void**)&wqkv, g_wqkv);
    cudaGetSymbolAddress((void**)&woh,  g_woh);
    cudaGetSymbolAddress((void**)&qh,   g_qh);
    cudaGetSymbolAddress((void**)&khb,  g_kh);
    cudaGetSymbolAddress((void**)&vhb,  g_vh);
    cudaGetSymbolAddress((void**)&ch,   g_ch);

    cudaFuncSetAttribute(gemm_mma,       cudaFuncAttributeMaxDynamicSharedMemorySize, GEMM_SMEM);
    cudaFuncSetAttribute(flash_attn_mma, cudaFuncAttributeMaxDynamicSharedMemorySize, FATTN_SMEM);

    dim3 thr(256);
    // fp16 conversions
    conv_kernel<<<(MROWS * DIN / 4 + 255) / 256, thr>>>(x, xh, MROWS * DIN / 4);
    convw_kernel<<<(DIN * DOUT / 4 + 255) / 256, thr>>>(Wq, wqkv, DOUT, NQKV, 0,          DIN * DOUT / 4);
    convw_kernel<<<(DIN * DKV  / 4 + 255) / 256, thr>>>(Wk, wqkv, DKV,  NQKV, DOUT,       DIN * DKV / 4);
    convw_kernel<<<(DIN * DKV  / 4 + 255) / 256, thr>>>(Wv, wqkv, DKV,  NQKV, DOUT + DKV, DIN * DKV / 4);
    convw_kernel<<<(DOUT * DOUT / 4 + 255) / 256, thr>>>(Wo, woh, DOUT, DOUT, 0,          DOUT * DOUT / 4);

    // Fused QKV projection (single-pass fp16)
    gemm_mma<<<dim3(NQKV / 128, MROWS / 128), thr, GEMM_SMEM>>>(xh, wqkv, qkv, MROWS, NQKV, DIN);

    // q/k/v prep (rope, scale, fp16)
    prep_q<<<MROWS * NH  * 64 / 256, thr>>>(qkv, cosT, sinT, qh);
    prep_k<<<MROWS * NKV * 64 / 256, thr>>>(qkv, cosT, sinT, khb);
    prep_v<<<MROWS * DKV / 4 / 256, thr>>>(qkv, vhb, MROWS * DKV / 4);

    // Attention -> fp16 ctx
    flash_attn_mma<<<dim3(Sq / FBM, NH, Bb), thr, FATTN_SMEM>>>(qh, khb, vhb, ch);

    // Output projection (single-pass fp16)
    gemm_mma<<<dim3(DOUT / 128, MROWS / 128), thr, GEMM_SMEM>>>(ch, woh, out, MROWS, DOUT, DOUT);
}

// round 11
// speedup vs baseline: 8.4367x; 1.0141x over previous
#include <cuda_runtime.h>
#include <cuda_fp16.h>
#include <cstdint>

// Problem constants
#define Bb    2
#define Sq    2048
#define DIN   2048
#define DOUT  2048
#define NH    16
#define NKV   4
#define HD    128
#define MROWS (Bb*Sq)        // 4096
#define DKV   (NKV*HD)       // 512
#define NQKV  (DOUT + 2*DKV) // 3072

// Scratch
__device__ float  g_qkv[(size_t)MROWS*NQKV];
__device__ __half g_xh[(size_t)MROWS*DIN];
__device__ __half g_wqkv[(size_t)DIN*NQKV];
__device__ __half g_woh[(size_t)DOUT*DOUT];
__device__ __half g_qh[(size_t)MROWS*DOUT];
__device__ __half g_kh[(size_t)MROWS*DKV];
__device__ __half g_vh[(size_t)MROWS*DKV];
__device__ __half g_ch[(size_t)MROWS*DOUT];

// ---------------------------------------------------------------------------
// Helpers
// ---------------------------------------------------------------------------
__device__ __forceinline__ uint32_t smem_u32(const void* p) {
    uint32_t a;
    asm("{ .reg .u64 t; cvta.to.shared.u64 t, %1; cvt.u32.u64 %0, t; }" : "=r"(a) : "l"(p));
    return a;
}
__device__ __forceinline__ void ldsm_x4(uint32_t& r0, uint32_t& r1, uint32_t& r2, uint32_t& r3,
                                        uint32_t addr) {
    asm volatile("ldmatrix.sync.aligned.m8n8.x4.shared.b16 {%0,%1,%2,%3}, [%4];"
                 : "=r"(r0), "=r"(r1), "=r"(r2), "=r"(r3) : "r"(addr));
}
__device__ __forceinline__ void ldsm_x4t(uint32_t& r0, uint32_t& r1, uint32_t& r2, uint32_t& r3,
                                         uint32_t addr) {
    asm volatile("ldmatrix.sync.aligned.m8n8.x4.trans.shared.b16 {%0,%1,%2,%3}, [%4];"
                 : "=r"(r0), "=r"(r1), "=r"(r2), "=r"(r3) : "r"(addr));
}
__device__ __forceinline__ void mma16816(float* d, const uint32_t* a, const uint32_t* b) {
    asm volatile(
        "mma.sync.aligned.m16n8k16.row.col.f32.f16.f16.f32 "
        "{%0,%1,%2,%3}, {%4,%5,%6,%7}, {%8,%9}, {%0,%1,%2,%3};"
        : "+f"(d[0]), "+f"(d[1]), "+f"(d[2]), "+f"(d[3])
        : "r"(a[0]), "r"(a[1]), "r"(a[2]), "r"(a[3]), "r"(b[0]), "r"(b[1]));
}
__device__ __forceinline__ uint32_t pack_hi(float a, float b) {
    __half2 h = __floats2half2_rn(a, b);
    return *(uint32_t*)&h;
}
__device__ __forceinline__ void cpa16(uint32_t dst, const void* src) {
    asm volatile("cp.async.cg.shared.global [%0], [%1], 16;" :: "r"(dst), "l"(src));
}
#define CP_COMMIT() asm volatile("cp.async.commit_group;" ::: "memory")
#define CP_WAIT1()  asm volatile("cp.async.wait_group 1;" ::: "memory")
#define CP_WAIT0()  asm volatile("cp.async.wait_group 0;" ::: "memory")

// ---------------------------------------------------------------------------
// Conversions / prep
// ---------------------------------------------------------------------------
__global__ void conv_kernel(const float* __restrict__ in, __half* __restrict__ hi, int n4)
{
    int i = blockIdx.x * blockDim.x + threadIdx.x;
    if (i >= n4) return;
    float4 f = ((const float4*)in)[i];
    ((uint2*)hi)[i] = make_uint2(pack_hi(f.x, f.y), pack_hi(f.z, f.w));
}
// All four weight matrices in one launch. Segments (in float4 units):
//  [0, NQ)          Wq  -> wqkv col 0..2047    (row stride NQKV)
//  [NQ, NQ+NK)      Wk  -> wqkv col 2048..2559
//  [NQ+NK, NQ+2NK)  Wv  -> wqkv col 2560..3071
//  [NQ+2NK, +NO)    Wo  -> woh (dense)
#define NQ4 (DIN*DOUT/4)
#define NK4 (DIN*DKV/4)
#define NO4 (DOUT*DOUT/4)
__global__ void convw_all(const float* __restrict__ Wq, const float* __restrict__ Wk,
                          const float* __restrict__ Wv, const float* __restrict__ Wo,
                          __half* __restrict__ wqkv, __half* __restrict__ woh)
{
    int i = blockIdx.x * blockDim.x + threadIdx.x;
    const float* src;
    __half* dst;
    int N, ostride, ooff, li;
    if (i < NQ4)                      { src = Wq; dst = wqkv; N = DOUT; ostride = NQKV; ooff = 0;          li = i; }
    else if (i < NQ4 + NK4)           { src = Wk; dst = wqkv; N = DKV;  ostride = NQKV; ooff = DOUT;       li = i - NQ4; }
    else if (i < NQ4 + 2 * NK4)       { src = Wv; dst = wqkv; N = DKV;  ostride = NQKV; ooff = DOUT + DKV; li = i - NQ4 - NK4; }
    else if (i < NQ4 + 2 * NK4 + NO4) { src = Wo; dst = woh;  N = DOUT; ostride = DOUT; ooff = 0;          li = i - NQ4 - 2 * NK4; }
    else return;
    float4 f = ((const float4*)src)[li];
    int row = li / (N / 4), c4 = li % (N / 4);
    *(uint2*)(dst + (size_t)row * ostride + ooff + c4 * 4)
        = make_uint2(pack_hi(f.x, f.y), pack_hi(f.z, f.w));
}
__global__ void prep_q(const float* __restrict__ qkv,
                       const float* __restrict__ cosT, const float* __restrict__ sinT,
                       __half* __restrict__ qh)
{
    const float scale = 0.08838834764831845f;
    int idx = blockIdx.x * blockDim.x + threadIdx.x;
    if (idx >= MROWS * NH * 64) return;
    int d = idx & 63, h = (idx >> 6) & (NH - 1), row = idx >> 10;
    int s = row & (Sq - 1);
    const float* src = qkv + (size_t)row * NQKV + h * HD;
    float t1 = src[d], t2 = src[d + 64];
    float c1 = cosT[s * HD + d],      s1 = sinT[s * HD + d];
    float c2 = cosT[s * HD + d + 64], s2 = sinT[s * HD + d + 64];
    size_t o = (size_t)row * DOUT + h * HD + d;
    qh[o]      = __float2half_rn((t1 * c1 - t2 * s1) * scale);
    qh[o + 64] = __float2half_rn((t2 * c2 + t1 * s2) * scale);
}
__global__ void prep_k(const float* __restrict__ qkv,
                       const float* __restrict__ cosT, const float* __restrict__ sinT,
                       __half* __restrict__ kh)
{
    int idx = blockIdx.x * blockDim.x + threadIdx.x;
    if (idx >= MROWS * NKV * 64) return;
    int d = idx & 63, h = (idx >> 6) & (NKV - 1), row = idx >> 8;
    int s = row & (Sq - 1);
    const float* src = qkv + (size_t)row * NQKV + DOUT + h * HD;
    float t1 = src[d], t2 = src[d + 64];
    float c1 = cosT[s * HD + d],      s1 = sinT[s * HD + d];
    float c2 = cosT[s * HD + d + 64], s2 = sinT[s * HD + d + 64];
    size_t o = (size_t)row * DKV + h * HD + d;
    kh[o]      = __float2half_rn(t1 * c1 - t2 * s1);
    kh[o + 64] = __float2half_rn(t2 * c2 + t1 * s2);
}
__global__ void prep_v(const float* __restrict__ qkv, __half* __restrict__ vh, int n4)
{
    int i = blockIdx.x * blockDim.x + threadIdx.x;
    if (i >= n4) return;
    int row = i >> 7, c4 = i & 127;
    float4 f = *(const float4*)(qkv + (size_t)row * NQKV + DOUT + DKV + c4 * 4);
    ((uint2*)vh)[i] = make_uint2(pack_hi(f.x, f.y), pack_hi(f.z, f.w));
}

// ---------------------------------------------------------------------------
// HMMA fp16 GEMM, single-pass, cp.async double buffer, 2 CTAs/SM.
// 128x128 tile, 8 warps (2x4), 64x32 warp tile, K chunks 64.
// ---------------------------------------------------------------------------
#define KC    64
#define A_STR 72
#define B_STR 136
#define A_OFF 0
#define B_OFF 18432
#define STAGE 35840
#define GEMM_SMEM (2*STAGE)

#define GEMM_LOAD(k0, st)                                                            \
    {                                                                                \
        uint32_t base = sb + (st) * STAGE;                                           \
        _Pragma("unroll")                                                            \
        for (int i = 0; i < 4; i++) {                                                \
            int li = t + (i << 8);                                                   \
            int r = li >> 3, ch = li & 7;                                            \
            size_t so = (size_t)(row0 + r) * K + (k0) + ch * 8;                      \
            cpa16(base + A_OFF + (uint32_t)(r * A_STR + ch * 8) * 2, Ah + so);       \
        }                                                                            \
        _Pragma("unroll")                                                            \
        for (int i = 0; i < 4; i++) {                                                \
            int li = t + (i << 8);                                                   \
            int kk = li >> 4, ch = li & 15;                                          \
            size_t so = (size_t)((k0) + kk) * N + col0 + ch * 8;                     \
            cpa16(base + B_OFF + (uint32_t)(kk * B_STR + ch * 8) * 2, Bh + so);      \
        }                                                                            \
    }

__global__ __launch_bounds__(256, 2) void gemm_mma(
    const __half* __restrict__ Ah, const __half* __restrict__ Bh,
    float* __restrict__ C, int M, int N, int K)
{
    extern __shared__ char smg[];
    const uint32_t sb = smem_u32(smg);
    const int t = threadIdx.x;
    const int wid = t >> 5, lane = t & 31;
    const int wm = wid >> 2, wn = wid & 3;
    const int row0 = blockIdx.y << 7, col0 = blockIdx.x << 7;

    float acc[4][4][4];
#pragma unroll
    for (int mi = 0; mi < 4; mi++)
#pragma unroll
        for (int nt = 0; nt < 4; nt++)
#pragma unroll
            for (int e = 0; e < 4; e++) acc[mi][nt][e] = 0.f;

    const int arow = lane & 15, agrp = (lane >> 4) << 3;
    const int nch = K / KC;

    GEMM_LOAD(0, 0);
    CP_COMMIT();
    if (nch > 1) GEMM_LOAD(KC, 1);
    CP_COMMIT();

    for (int c = 0; c < nch; c++) {
        CP_WAIT1();
        __syncthreads();

        const uint32_t stb = sb + (c & 1) * STAGE;
#pragma unroll
        for (int ks = 0; ks < 4; ks++) {
            uint32_t a[4][4];
#pragma unroll
            for (int mi = 0; mi < 4; mi++) {
                uint32_t ao = (uint32_t)((wm * 64 + mi * 16 + arow) * A_STR + ks * 16 + agrp) * 2;
                ldsm_x4(a[mi][0], a[mi][1], a[mi][2], a[mi][3], stb + A_OFF + ao);
            }
            uint32_t b[4][2];
#pragma unroll
            for (int p = 0; p < 2; p++) {
                uint32_t bo = (uint32_t)((ks * 16 + arow) * B_STR + wn * 32 + p * 16 + agrp) * 2;
                uint32_t r0, r1, r2, r3;
                ldsm_x4t(r0, r1, r2, r3, stb + B_OFF + bo);
                b[2 * p][0] = r0;     b[2 * p][1] = r1;
                b[2 * p + 1][0] = r2; b[2 * p + 1][1] = r3;
            }
#pragma unroll
            for (int mi = 0; mi < 4; mi++)
#pragma unroll
                for (int nt = 0; nt < 4; nt++)
                    mma16816(acc[mi][nt], a[mi], b[nt]);
        }
        __syncthreads();
        if (c + 2 < nch) GEMM_LOAD((c + 2) * KC, (c & 1));
        CP_COMMIT();
    }

    const int drow = lane >> 2, dcol = (lane & 3) * 2;
#pragma unroll
    for (int mi = 0; mi < 4; mi++) {
        int r = row0 + wm * 64 + mi * 16 + drow;
#pragma unroll
        for (int nt = 0; nt < 4; nt++) {
            int col = col0 + wn * 32 + nt * 8 + dcol;
            *(float2*)(C + (size_t)r * N + col)       = make_float2(acc[mi][nt][0], acc[mi][nt][1]);
            *(float2*)(C + (size_t)(r + 8) * N + col) = make_float2(acc[mi][nt][2], acc[mi][nt][3]);
        }
    }
}

// ---------------------------------------------------------------------------
// Tensor-core flash attention, single-pass fp16 (R10, verified, unchanged).
// ---------------------------------------------------------------------------
#define FBM 128
#define FBN 64
#define F_STR 136
#define QH_OFF 0
#define KV0_OFF 34816
#define KV_STAGE 34816
#define FATTN_SMEM 104448

#define KV_LOAD(k0_, st)                                                             \
    {                                                                                \
        const __half* kb = Kh + ((size_t)b * Sq + (k0_)) * DKV + kh * HD;            \
        const __half* vb = Vh + ((size_t)b * Sq + (k0_)) * DKV + kh * HD;            \
        uint32_t kbase = sb + KV0_OFF + (st) * KV_STAGE;                             \
        _Pragma("unroll")                                                            \
        for (int i = 0; i < 4; i++) {                                                \
            int li = t + (i << 8);                                                   \
            int r = li >> 4, c8 = li & 15;                                           \
            uint32_t dof = (uint32_t)(r * F_STR + c8 * 8) * 2;                       \
            cpa16(kbase + dof,         kb + (size_t)r * DKV + c8 * 8);               \
            cpa16(kbase + 17408 + dof, vb + (size_t)r * DKV + c8 * 8);               \
        }                                                                            \
    }

__global__ __launch_bounds__(256, 1) void flash_attn_mma(
    const __half* __restrict__ Qh, const __half* __restrict__ Kh,
    const __half* __restrict__ Vh, __half* __restrict__ Oh)
{
    extern __shared__ char smf[];
    const uint32_t sb = smem_u32(smf);
    const int qtile = gridDim.x - 1 - blockIdx.x;
    const int h = blockIdx.y, b = blockIdx.z;
    const int kh = h >> 2;
    const int t = threadIdx.x;
    const int w = t >> 5, lane = t & 31;
    const int arow = lane & 15, agrp = (lane >> 4) << 3;
    const int q0 = qtile * FBM;

    {
        const __half* qb = Qh + ((size_t)b * Sq + q0) * DOUT + h * HD;
#pragma unroll
        for (int i = 0; i < 4; i++) {
            int li = t + (i << 8);
            int r = li >> 3, c8 = li & 7;
            uint32_t dof = (uint32_t)(r * F_STR + c8 * 16) * 2;
            cpa16(sb + QH_OFF + dof,      qb + (size_t)r * DOUT + c8 * 16);
            cpa16(sb + QH_OFF + dof + 16, qb + (size_t)r * DOUT + c8 * 16 + 8);
        }
    }
    KV_LOAD(0, 0);
    CP_COMMIT();

    float o[16][4];
#pragma unroll
    for (int nt = 0; nt < 16; nt++)
#pragma unroll
        for (int e = 0; e < 4; e++) o[nt][e] = 0.f;
    float m0 = -1e30f, m1 = -1e30f, l0 = 0.f, l1 = 0.f;

    const int wrow_max = q0 + w * 16 + 15;
    const int niter = (q0 + FBM) / FBN;

    for (int it = 0; it < niter; it++) {
        const int k0 = it * FBN;
        if (it + 1 < niter) {
            KV_LOAD((it + 1) * FBN, (it + 1) & 1);
            CP_COMMIT();
            CP_WAIT1();
        } else {
            CP_WAIT0();
        }
        __syncthreads();

        if (k0 <= wrow_max) {
            const uint32_t kvb = sb + KV0_OFF + (it & 1) * KV_STAGE;
            const uint32_t KHo = kvb, VHo = kvb + 17408;

            float s[8][4];
#pragma unroll
            for (int nt = 0; nt < 8; nt++)
#pragma unroll
                for (int e = 0; e < 4; e++) s[nt][e] = 0.f;

#pragma unroll
            for (int ks = 0; ks < 8; ks++) {
                uint32_t q[4];
                uint32_t qa = (uint32_t)((w * 16 + arow) * F_STR + ks * 16 + agrp) * 2;
                ldsm_x4(q[0], q[1], q[2], q[3], sb + QH_OFF + qa);
#pragma unroll
                for (int g = 0; g < 4; g++) {
                    uint32_t ka = (uint32_t)((g * 16 + arow) * F_STR + ks * 16 + agrp) * 2;
                    uint32_t h0, h1, h2, h3;
                    ldsm_x4(h0, h1, h2, h3, KHo + ka);
                    uint32_t b0[2] = {h0, h2}, b1[2] = {h1, h3};
                    mma16816(s[2 * g],     q, b0);
                    mma16816(s[2 * g + 1], q, b1);
                }
            }

            const int rg0 = q0 + w * 16 + (lane >> 2);
            if (k0 + FBN - 1 > q0 + w * 16) {
                int cg = k0 + 2 * (lane & 3);
#pragma unroll
                for (int nt = 0; nt < 8; nt++) {
                    int c = cg + nt * 8;
                    if (c     > rg0)     s[nt][0] = -1e30f;
                    if (c + 1 > rg0)     s[nt][1] = -1e30f;
                    if (c     > rg0 + 8) s[nt][2] = -1e30f;
                    if (c + 1 > rg0 + 8) s[nt][3] = -1e30f;
                }
            }

            float mx0 = -1e30f, mx1 = -1e30f;
#pragma unroll
            for (int nt = 0; nt < 8; nt++) {
                mx0 = fmaxf(mx0, fmaxf(s[nt][0], s[nt][1]));
                mx1 = fmaxf(mx1, fmaxf(s[nt][2], s[nt][3]));
            }
            mx0 = fmaxf(mx0, __shfl_xor_sync(0xffffffffu, mx0, 1));
            mx0 = fmaxf(mx0, __shfl_xor_sync(0xffffffffu, mx0, 2));
            mx1 = fmaxf(mx1, __shfl_xor_sync(0xffffffffu, mx1, 1));
            mx1 = fmaxf(mx1, __shfl_xor_sync(0xffffffffu, mx1, 2));
            float mn0 = fmaxf(m0, mx0), mn1 = fmaxf(m1, mx1);
            float a0 = __expf(m0 - mn0), a1 = __expf(m1 - mn1);
            m0 = mn0; m1 = mn1;

            float sum0 = 0.f, sum1 = 0.f;
#pragma unroll
            for (int nt = 0; nt < 8; nt++) {
                s[nt][0] = __expf(s[nt][0] - mn0);
                s[nt][1] = __expf(s[nt][1] - mn0);
                s[nt][2] = __expf(s[nt][2] - mn1);
                s[nt][3] = __expf(s[nt][3] - mn1);
                sum0 += s[nt][0] + s[nt][1];
                sum1 += s[nt][2] + s[nt][3];
            }
            sum0 += __shfl_xor_sync(0xffffffffu, sum0, 1);
            sum0 += __shfl_xor_sync(0xffffffffu, sum0, 2);
            sum1 += __shfl_xor_sync(0xffffffffu, sum1, 1);
            sum1 += __shfl_xor_sync(0xffffffffu, sum1, 2);
            l0 = l0 * a0 + sum0;
            l1 = l1 * a1 + sum1;

#pragma unroll
            for (int nt = 0; nt < 16; nt++) {
                o[nt][0] *= a0; o[nt][1] *= a0;
                o[nt][2] *= a1; o[nt][3] *= a1;
            }

            uint32_t ap[4][4];
#pragma unroll
            for (int ts = 0; ts < 4; ts++) {
                ap[ts][0] = pack_hi(s[2 * ts][0],     s[2 * ts][1]);
                ap[ts][1] = pack_hi(s[2 * ts][2],     s[2 * ts][3]);
                ap[ts][2] = pack_hi(s[2 * ts + 1][0], s[2 * ts + 1][1]);
                ap[ts][3] = pack_hi(s[2 * ts + 1][2], s[2 * ts + 1][3]);
            }

#pragma unroll
            for (int ts = 0; ts < 4; ts++) {
#pragma unroll
                for (int g = 0; g < 8; g++) {
                    uint32_t va = (uint32_t)((ts * 16 + arow) * F_STR + g * 16 + agrp) * 2;
                    uint32_t h0, h1, h2, h3;
                    ldsm_x4t(h0, h1, h2, h3, VHo + va);
                    uint32_t b0[2] = {h0, h1}, b1[2] = {h2, h3};
                    mma16816(o[2 * g],     ap[ts], b0);
                    mma16816(o[2 * g + 1], ap[ts], b1);
                }
            }
        }
        __syncthreads();
    }

    float inv0 = 1.f / l0, inv1 = 1.f / l1;
    const int rg0 = q0 + w * 16 + (lane >> 2);
    size_t base0 = ((size_t)b * Sq + rg0) * DOUT + h * HD + 2 * (lane & 3);
    size_t base1 = base0 + (size_t)8 * DOUT;
#pragma unroll
    for (int nt = 0; nt < 16; nt++) {
        ((uint32_t*)Oh)[(base0 + nt * 8) >> 1] = pack_hi(o[nt][0] * inv0, o[nt][1] * inv0);
        ((uint32_t*)Oh)[(base1 + nt * 8) >> 1] = pack_hi(o[nt][2] * inv1, o[nt][3] * inv1);
    }
}

// ---------------------------------------------------------------------------
extern "C" void kernel_launch(void* const* d_in, const int* in_sizes, int n_in,
                              void* d_out, int out_size)
{
    const float* x    = (const float*)d_in[0];
    const float* Wq   = (const float*)d_in[1];
    const float* Wk   = (const float*)d_in[2];
    const float* Wv   = (const float*)d_in[3];
    const float* Wo   = (const float*)d_in[4];
    const float* cosT = (const float*)d_in[5];
    const float* sinT = (const float*)d_in[6];
    float* out = (float*)d_out;

    float* qkv;
    __half *xh, *wqkv, *woh, *qh, *khb, *vhb, *ch;
    cudaGetSymbolAddress((void**)&qkv,  g_qkv);
    cudaGetSymbolAddress((void**)&xh,   g_xh);
    cudaGetSymbolAddress((void**)&wqkv, g_wqkv);
    cudaGetSymbolAddress((void**)&woh,  g_woh);
    cudaGetSymbolAddress((void**)&qh,   g_qh);
    cudaGetSymbolAddress((void**)&khb,  g_kh);
    cudaGetSymbolAddress((void**)&vhb,  g_vh);
    cudaGetSymbolAddress((void**)&ch,   g_ch);

    cudaFuncSetAttribute(gemm_mma,       cudaFuncAttributeMaxDynamicSharedMemorySize, GEMM_SMEM);
    cudaFuncSetAttribute(flash_attn_mma, cudaFuncAttributeMaxDynamicSharedMemorySize, FATTN_SMEM);

    dim3 thr(256);
    // fp16 conversions (x + all weights in one launch)
    conv_kernel<<<(MROWS * DIN / 4 + 255) / 256, thr>>>(x, xh, MROWS * DIN / 4);
    convw_all<<<(NQ4 + 2 * NK4 + NO4 + 255) / 256, thr>>>(Wq, Wk, Wv, Wo, wqkv, woh);

    // Fused QKV projection (single-pass fp16, 2 CTAs/SM)
    gemm_mma<<<dim3(NQKV / 128, MROWS / 128), thr, GEMM_SMEM>>>(xh, wqkv, qkv, MROWS, NQKV, DIN);

    // q/k/v prep (rope, scale, fp16)
    prep_q<<<MROWS * NH  * 64 / 256, thr>>>(qkv, cosT, sinT, qh);
    prep_k<<<MROWS * NKV * 64 / 256, thr>>>(qkv, cosT, sinT, khb);
    prep_v<<<MROWS * DKV / 4 / 256, thr>>>(qkv, vhb, MROWS * DKV / 4);

    // Attention -> fp16 ctx
    flash_attn_mma<<<dim3(Sq / FBM, NH, Bb), thr, FATTN_SMEM>>>(qh, khb, vhb, ch);

    // Output projection (single-pass fp16, 2 CTAs/SM)
    gemm_mma<<<dim3(DOUT / 128, MROWS / 128), thr, GEMM_SMEM>>>(ch, woh, out, MROWS, DOUT, DOUT);
}

// round 12
// speedup vs baseline: 9.1573x; 1.0854x over previous
#include <cuda_runtime.h>
#include <cuda_fp16.h>
#include <cstdint>

// Problem constants
#define Bb    2
#define Sq    2048
#define DIN   2048
#define DOUT  2048
#define NH    16
#define NKV   4
#define HD    128
#define MROWS (Bb*Sq)        // 4096
#define DKV   (NKV*HD)       // 512
#define NQKV  (DOUT + 2*DKV) // 3072

// Scratch
__device__ __half g_xh[(size_t)MROWS*DIN];
__device__ __half g_wqkv[(size_t)DIN*NQKV];   // Wq,Wk rope-pair permuted; Wv plain
__device__ __half g_woh[(size_t)DOUT*DOUT];
__device__ __half g_qh[(size_t)MROWS*DOUT];   // permuted d-layout (rope applied, scaled)
__device__ __half g_kh[(size_t)MROWS*DKV];    // permuted d-layout (rope applied)
__device__ __half g_vh[(size_t)MROWS*DKV];
__device__ __half g_ch[(size_t)MROWS*DOUT];

// ---------------------------------------------------------------------------
// Helpers
// ---------------------------------------------------------------------------
__device__ __forceinline__ uint32_t smem_u32(const void* p) {
    uint32_t a;
    asm("{ .reg .u64 t; cvta.to.shared.u64 t, %1; cvt.u32.u64 %0, t; }" : "=r"(a) : "l"(p));
    return a;
}
__device__ __forceinline__ void ldsm_x4(uint32_t& r0, uint32_t& r1, uint32_t& r2, uint32_t& r3,
                                        uint32_t addr) {
    asm volatile("ldmatrix.sync.aligned.m8n8.x4.shared.b16 {%0,%1,%2,%3}, [%4];"
                 : "=r"(r0), "=r"(r1), "=r"(r2), "=r"(r3) : "r"(addr));
}
__device__ __forceinline__ void ldsm_x4t(uint32_t& r0, uint32_t& r1, uint32_t& r2, uint32_t& r3,
                                         uint32_t addr) {
    asm volatile("ldmatrix.sync.aligned.m8n8.x4.trans.shared.b16 {%0,%1,%2,%3}, [%4];"
                 : "=r"(r0), "=r"(r1), "=r"(r2), "=r"(r3) : "r"(addr));
}
__device__ __forceinline__ void mma16816(float* d, const uint32_t* a, const uint32_t* b) {
    asm volatile(
        "mma.sync.aligned.m16n8k16.row.col.f32.f16.f16.f32 "
        "{%0,%1,%2,%3}, {%4,%5,%6,%7}, {%8,%9}, {%0,%1,%2,%3};"
        : "+f"(d[0]), "+f"(d[1]), "+f"(d[2]), "+f"(d[3])
        : "r"(a[0]), "r"(a[1]), "r"(a[2]), "r"(a[3]), "r"(b[0]), "r"(b[1]));
}
__device__ __forceinline__ uint32_t pack_hi(float a, float b) {
    __half2 h = __floats2half2_rn(a, b);
    return *(uint32_t*)&h;
}
__device__ __forceinline__ void cpa16(uint32_t dst, const void* src) {
    asm volatile("cp.async.cg.shared.global [%0], [%1], 16;" :: "r"(dst), "l"(src));
}
#define CP_COMMIT() asm volatile("cp.async.commit_group;" ::: "memory")
#define CP_WAIT1()  asm volatile("cp.async.wait_group 1;" ::: "memory")
#define CP_WAIT0()  asm volatile("cp.async.wait_group 0;" ::: "memory")

// ---------------------------------------------------------------------------
// One-shot conversion kernel: x plain; Wq/Wk rope-pair-permuted; Wv, Wo plain.
// Permutation (within each 128-d head block): new col 2j <- d=j, 2j+1 <- d=j+64.
// ---------------------------------------------------------------------------
#define XU  (MROWS*DIN/4)
#define WQU (DIN*NH*32)
#define WKU (DIN*NKV*32)
#define WVU (DIN*DKV/4)
#define WOU (DOUT*DOUT/4)
#define CONV_TOTAL (XU + WQU + WKU + WVU + WOU)

__global__ void conv_all(const float* __restrict__ x,
                         const float* __restrict__ Wq, const float* __restrict__ Wk,
                         const float* __restrict__ Wv, const float* __restrict__ Wo,
                         __half* __restrict__ xh, __half* __restrict__ wqkv,
                         __half* __restrict__ woh)
{
    int i = blockIdx.x * blockDim.x + threadIdx.x;
    if (i < XU) {
        float4 f = ((const float4*)x)[i];
        ((uint2*)xh)[i] = make_uint2(pack_hi(f.x, f.y), pack_hi(f.z, f.w));
        return;
    }
    i -= XU;
    if (i < WQU) {      // Wq permuted: unit = (k, h, j2); covers new cols 4j2..4j2+3
        int k = i >> 9, h = (i >> 5) & 15, j2 = i & 31;
        const float* base = Wq + (size_t)k * DOUT + h * HD + j2 * 2;
        float2 a = *(const float2*)base;
        float2 b = *(const float2*)(base + 64);
        *(uint2*)(wqkv + (size_t)k * NQKV + h * HD + j2 * 4)
            = make_uint2(pack_hi(a.x, b.x), pack_hi(a.y, b.y));
        return;
    }
    i -= WQU;
    if (i < WKU) {      // Wk permuted
        int k = i >> 7, h = (i >> 5) & 3, j2 = i & 31;
        const float* base = Wk + (size_t)k * DKV + h * HD + j2 * 2;
        float2 a = *(const float2*)base;
        float2 b = *(const float2*)(base + 64);
        *(uint2*)(wqkv + (size_t)k * NQKV + DOUT + h * HD + j2 * 4)
            = make_uint2(pack_hi(a.x, b.x), pack_hi(a.y, b.y));
        return;
    }
    i -= WKU;
    if (i < WVU) {      // Wv plain
        int k = i >> 7, c4 = i & 127;
        float4 f = *(const float4*)(Wv + (size_t)k * DKV + c4 * 4);
        *(uint2*)(wqkv + (size_t)k * NQKV + DOUT + DKV + c4 * 4)
            = make_uint2(pack_hi(f.x, f.y), pack_hi(f.z, f.w));
        return;
    }
    i -= WVU;
    if (i < WOU) {      // Wo plain (dense)
        float4 f = ((const float4*)Wo)[i];
        ((uint2*)woh)[i] = make_uint2(pack_hi(f.x, f.y), pack_hi(f.z, f.w));
    }
}

// ---------------------------------------------------------------------------
// Shared GEMM mainloop pieces
// ---------------------------------------------------------------------------
#define KC    64
#define A_STR 72
#define B_STR 136
#define A_OFF 0
#define B_OFF 18432
#define STAGE 35840
#define GEMM_SMEM (2*STAGE)

#define GEMM_LOAD(k0, st)                                                            \
    {                                                                                \
        uint32_t base = sb + (st) * STAGE;                                           \
        _Pragma("unroll")                                                            \
        for (int i = 0; i < 4; i++) {                                                \
            int li = t + (i << 8);                                                   \
            int r = li >> 3, ch = li & 7;                                            \
            size_t so = (size_t)(row0 + r) * K + (k0) + ch * 8;                      \
            cpa16(base + A_OFF + (uint32_t)(r * A_STR + ch * 8) * 2, Ah + so);       \
        }                                                                            \
        _Pragma("unroll")                                                            \
        for (int i = 0; i < 4; i++) {                                                \
            int li = t + (i << 8);                                                   \
            int kk = li >> 4, ch = li & 15;                                          \
            size_t so = (size_t)((k0) + kk) * N + col0 + ch * 8;                     \
            cpa16(base + B_OFF + (uint32_t)(kk * B_STR + ch * 8) * 2, Bh + so);      \
        }                                                                            \
    }

#define GEMM_MAINLOOP()                                                              \
    GEMM_LOAD(0, 0);                                                                 \
    CP_COMMIT();                                                                     \
    GEMM_LOAD(KC, 1);                                                                \
    CP_COMMIT();                                                                     \
    for (int c = 0; c < nch; c++) {                                                  \
        CP_WAIT1();                                                                  \
        __syncthreads();                                                             \
        const uint32_t stb = sb + (c & 1) * STAGE;                                   \
        _Pragma("unroll")                                                            \
        for (int ks = 0; ks < 4; ks++) {                                             \
            uint32_t a[4][4];                                                        \
            _Pragma("unroll")                                                        \
            for (int mi = 0; mi < 4; mi++) {                                         \
                uint32_t ao = (uint32_t)((wm * 64 + mi * 16 + arow) * A_STR          \
                                         + ks * 16 + agrp) * 2;                      \
                ldsm_x4(a[mi][0], a[mi][1], a[mi][2], a[mi][3], stb + A_OFF + ao);   \
            }                                                                        \
            uint32_t b[4][2];                                                        \
            _Pragma("unroll")                                                        \
            for (int p = 0; p < 2; p++) {                                            \
                uint32_t bo = (uint32_t)((ks * 16 + arow) * B_STR                    \
                                         + wn * 32 + p * 16 + agrp) * 2;             \
                uint32_t r0, r1, r2, r3;                                             \
                ldsm_x4t(r0, r1, r2, r3, stb + B_OFF + bo);                          \
                b[2 * p][0] = r0;     b[2 * p][1] = r1;                              \
                b[2 * p + 1][0] = r2; b[2 * p + 1][1] = r3;                          \
            }                                                                        \
            _Pragma("unroll")                                                        \
            for (int mi = 0; mi < 4; mi++)                                           \
                _Pragma("unroll")                                                    \
                for (int nt = 0; nt < 4; nt++)                                       \
                    mma16816(acc[mi][nt], a[mi], b[nt]);                             \
        }                                                                            \
        __syncthreads();                                                             \
        if (c + 2 < nch) GEMM_LOAD((c + 2) * KC, (c & 1));                           \
        CP_COMMIT();                                                                 \
    }

// ---------------------------------------------------------------------------
// QKV GEMM with fused rope/scale/fp16 epilogue.
// Column tiles: [0,2048) q-perm, [2048,2560) k-perm, [2560,3072) v.
// ---------------------------------------------------------------------------
__global__ __launch_bounds__(256, 2) void gemm_qkv(
    const __half* __restrict__ Ah, const __half* __restrict__ Bh,
    const float* __restrict__ cosT, const float* __restrict__ sinT,
    __half* __restrict__ Qh, __half* __restrict__ Kh, __half* __restrict__ Vh)
{
    extern __shared__ char smg[];
    const uint32_t sb = smem_u32(smg);
    const int t = threadIdx.x;
    const int wid = t >> 5, lane = t & 31;
    const int wm = wid >> 2, wn = wid & 3;
    const int row0 = blockIdx.y << 7, col0 = blockIdx.x << 7;
    const int K = DIN, N = NQKV;
    const int nch = K / KC;

    float acc[4][4][4];
#pragma unroll
    for (int mi = 0; mi < 4; mi++)
#pragma unroll
        for (int nt = 0; nt < 4; nt++)
#pragma unroll
            for (int e = 0; e < 4; e++) acc[mi][nt][e] = 0.f;

    const int arow = lane & 15, agrp = (lane >> 4) << 3;

    GEMM_MAINLOOP();

    const int drow = lane >> 2, dcol = (lane & 3) * 2;
    const float scale = 0.08838834764831845f;

    if (col0 < DOUT) {
        // q: rope + scale, permuted layout preserved
#pragma unroll
        for (int mi = 0; mi < 4; mi++) {
            int r = row0 + wm * 64 + mi * 16 + drow;
            int s0 = r & (Sq - 1), s1 = (r + 8) & (Sq - 1);
#pragma unroll
            for (int nt = 0; nt < 4; nt++) {
                int col = col0 + wn * 32 + nt * 8 + dcol;
                int jj = (col & 127) >> 1;
                float c0 = cosT[s0 * HD + jj], n0 = sinT[s0 * HD + jj];
                float c1 = cosT[s1 * HD + jj], n1 = sinT[s1 * HD + jj];
                float t1 = acc[mi][nt][0], t2 = acc[mi][nt][1];
                uint32_t p0 = pack_hi((t1 * c0 - t2 * n0) * scale,
                                      (t2 * c0 + t1 * n0) * scale);
                t1 = acc[mi][nt][2]; t2 = acc[mi][nt][3];
                uint32_t p1 = pack_hi((t1 * c1 - t2 * n1) * scale,
                                      (t2 * c1 + t1 * n1) * scale);
                *(uint32_t*)(Qh + (size_t)r * DOUT + col)       = p0;
                *(uint32_t*)(Qh + (size_t)(r + 8) * DOUT + col) = p1;
            }
        }
    } else if (col0 < DOUT + DKV) {
        // k: rope, permuted layout preserved
#pragma unroll
        for (int mi = 0; mi < 4; mi++) {
            int r = row0 + wm * 64 + mi * 16 + drow;
            int s0 = r & (Sq - 1), s1 = (r + 8) & (Sq - 1);
#pragma unroll
            for (int nt = 0; nt < 4; nt++) {
                int col = col0 + wn * 32 + nt * 8 + dcol;
                int kc = col - DOUT;
                int jj = (kc & 127) >> 1;
                float c0 = cosT[s0 * HD + jj], n0 = sinT[s0 * HD + jj];
                float c1 = cosT[s1 * HD + jj], n1 = sinT[s1 * HD + jj];
                float t1 = acc[mi][nt][0], t2 = acc[mi][nt][1];
                uint32_t p0 = pack_hi(t1 * c0 - t2 * n0, t2 * c0 + t1 * n0);
                t1 = acc[mi][nt][2]; t2 = acc[mi][nt][3];
                uint32_t p1 = pack_hi(t1 * c1 - t2 * n1, t2 * c1 + t1 * n1);
                *(uint32_t*)(Kh + (size_t)r * DKV + kc)       = p0;
                *(uint32_t*)(Kh + (size_t)(r + 8) * DKV + kc) = p1;
            }
        }
    } else {
        // v: plain fp16 convert
#pragma unroll
        for (int mi = 0; mi < 4; mi++) {
            int r = row0 + wm * 64 + mi * 16 + drow;
#pragma unroll
            for (int nt = 0; nt < 4; nt++) {
                int col = col0 + wn * 32 + nt * 8 + dcol;
                int vc = col - DOUT - DKV;
                *(uint32_t*)(Vh + (size_t)r * DKV + vc)
                    = pack_hi(acc[mi][nt][0], acc[mi][nt][1]);
                *(uint32_t*)(Vh + (size_t)(r + 8) * DKV + vc)
                    = pack_hi(acc[mi][nt][2], acc[mi][nt][3]);
            }
        }
    }
}

// ---------------------------------------------------------------------------
// Output-projection GEMM (plain fp32 epilogue).
// ---------------------------------------------------------------------------
__global__ __launch_bounds__(256, 2) void gemm_out(
    const __half* __restrict__ Ah, const __half* __restrict__ Bh,
    float* __restrict__ C)
{
    extern __shared__ char smg[];
    const uint32_t sb = smem_u32(smg);
    const int t = threadIdx.x;
    const int wid = t >> 5, lane = t & 31;
    const int wm = wid >> 2, wn = wid & 3;
    const int row0 = blockIdx.y << 7, col0 = blockIdx.x << 7;
    const int K = DOUT, N = DOUT;
    const int nch = K / KC;

    float acc[4][4][4];
#pragma unroll
    for (int mi = 0; mi < 4; mi++)
#pragma unroll
        for (int nt = 0; nt < 4; nt++)
#pragma unroll
            for (int e = 0; e < 4; e++) acc[mi][nt][e] = 0.f;

    const int arow = lane & 15, agrp = (lane >> 4) << 3;

    GEMM_MAINLOOP();

    const int drow = lane >> 2, dcol = (lane & 3) * 2;
#pragma unroll
    for (int mi = 0; mi < 4; mi++) {
        int r = row0 + wm * 64 + mi * 16 + drow;
#pragma unroll
        for (int nt = 0; nt < 4; nt++) {
            int col = col0 + wn * 32 + nt * 8 + dcol;
            *(float2*)(C + (size_t)r * N + col)       = make_float2(acc[mi][nt][0], acc[mi][nt][1]);
            *(float2*)(C + (size_t)(r + 8) * N + col) = make_float2(acc[mi][nt][2], acc[mi][nt][3]);
        }
    }
}

// ---------------------------------------------------------------------------
// Tensor-core flash attention, single-pass fp16 (verified, unchanged —
// q/k consumed in permuted d-layout, which is QK^T-invariant).
// ---------------------------------------------------------------------------
#define FBM 128
#define FBN 64
#define F_STR 136
#define QH_OFF 0
#define KV0_OFF 34816
#define KV_STAGE 34816
#define FATTN_SMEM 104448

#define KV_LOAD(k0_, st)                                                             \
    {                                                                                \
        const __half* kb = Kh + ((size_t)b * Sq + (k0_)) * DKV + kh * HD;            \
        const __half* vb = Vh + ((size_t)b * Sq + (k0_)) * DKV + kh * HD;            \
        uint32_t kbase = sb + KV0_OFF + (st) * KV_STAGE;                             \
        _Pragma("unroll")                                                            \
        for (int i = 0; i < 4; i++) {                                                \
            int li = t + (i << 8);                                                   \
            int r = li >> 4, c8 = li & 15;                                           \
            uint32_t dof = (uint32_t)(r * F_STR + c8 * 8) * 2;                       \
            cpa16(kbase + dof,         kb + (size_t)r * DKV + c8 * 8);               \
            cpa16(kbase + 17408 + dof, vb + (size_t)r * DKV + c8 * 8);               \
        }                                                                            \
    }

__global__ __launch_bounds__(256, 1) void flash_attn_mma(
    const __half* __restrict__ Qh, const __half* __restrict__ Kh,
    const __half* __restrict__ Vh, __half* __restrict__ Oh)
{
    extern __shared__ char smf[];
    const uint32_t sb = smem_u32(smf);
    const int qtile = gridDim.x - 1 - blockIdx.x;
    const int h = blockIdx.y, b = blockIdx.z;
    const int kh = h >> 2;
    const int t = threadIdx.x;
    const int w = t >> 5, lane = t & 31;
    const int arow = lane & 15, agrp = (lane >> 4) << 3;
    const int q0 = qtile * FBM;

    {
        const __half* qb = Qh + ((size_t)b * Sq + q0) * DOUT + h * HD;
#pragma unroll
        for (int i = 0; i < 4; i++) {
            int li = t + (i << 8);
            int r = li >> 3, c8 = li & 7;
            uint32_t dof = (uint32_t)(r * F_STR + c8 * 16) * 2;
            cpa16(sb + QH_OFF + dof,      qb + (size_t)r * DOUT + c8 * 16);
            cpa16(sb + QH_OFF + dof + 16, qb + (size_t)r * DOUT + c8 * 16 + 8);
        }
    }
    KV_LOAD(0, 0);
    CP_COMMIT();

    float o[16][4];
#pragma unroll
    for (int nt = 0; nt < 16; nt++)
#pragma unroll
        for (int e = 0; e < 4; e++) o[nt][e] = 0.f;
    float m0 = -1e30f, m1 = -1e30f, l0 = 0.f, l1 = 0.f;

    const int wrow_max = q0 + w * 16 + 15;
    const int niter = (q0 + FBM) / FBN;

    for (int it = 0; it < niter; it++) {
        const int k0 = it * FBN;
        if (it + 1 < niter) {
            KV_LOAD((it + 1) * FBN, (it + 1) & 1);
            CP_COMMIT();
            CP_WAIT1();
        } else {
            CP_WAIT0();
        }
        __syncthreads();

        if (k0 <= wrow_max) {
            const uint32_t kvb = sb + KV0_OFF + (it & 1) * KV_STAGE;
            const uint32_t KHo = kvb, VHo = kvb + 17408;

            float s[8][4];
#pragma unroll
            for (int nt = 0; nt < 8; nt++)
#pragma unroll
                for (int e = 0; e < 4; e++) s[nt][e] = 0.f;

#pragma unroll
            for (int ks = 0; ks < 8; ks++) {
                uint32_t q[4];
                uint32_t qa = (uint32_t)((w * 16 + arow) * F_STR + ks * 16 + agrp) * 2;
                ldsm_x4(q[0], q[1], q[2], q[3], sb + QH_OFF + qa);
#pragma unroll
                for (int g = 0; g < 4; g++) {
                    uint32_t ka = (uint32_t)((g * 16 + arow) * F_STR + ks * 16 + agrp) * 2;
                    uint32_t h0, h1, h2, h3;
                    ldsm_x4(h0, h1, h2, h3, KHo + ka);
                    uint32_t b0[2] = {h0, h2}, b1[2] = {h1, h3};
                    mma16816(s[2 * g],     q, b0);
                    mma16816(s[2 * g + 1], q, b1);
                }
            }

            const int rg0 = q0 + w * 16 + (lane >> 2);
            if (k0 + FBN - 1 > q0 + w * 16) {
                int cg = k0 + 2 * (lane & 3);
#pragma unroll
                for (int nt = 0; nt < 8; nt++) {
                    int c = cg + nt * 8;
                    if (c     > rg0)     s[nt][0] = -1e30f;
                    if (c + 1 > rg0)     s[nt][1] = -1e30f;
                    if (c     > rg0 + 8) s[nt][2] = -1e30f;
                    if (c + 1 > rg0 + 8) s[nt][3] = -1e30f;
                }
            }

            float mx0 = -1e30f, mx1 = -1e30f;
#pragma unroll
            for (int nt = 0; nt < 8; nt++) {
                mx0 = fmaxf(mx0, fmaxf(s[nt][0], s[nt][1]));
                mx1 = fmaxf(mx1, fmaxf(s[nt][2], s[nt][3]));
            }
            mx0 = fmaxf(mx0, __shfl_xor_sync(0xffffffffu, mx0, 1));
            mx0 = fmaxf(mx0, __shfl_xor_sync(0xffffffffu, mx0, 2));
            mx1 = fmaxf(mx1, __shfl_xor_sync(0xffffffffu, mx1, 1));
            mx1 = fmaxf(mx1, __shfl_xor_sync(0xffffffffu, mx1, 2));
            float mn0 = fmaxf(m0, mx0), mn1 = fmaxf(m1, mx1);
            float a0 = __expf(m0 - mn0), a1 = __expf(m1 - mn1);
            m0 = mn0; m1 = mn1;

            float sum0 = 0.f, sum1 = 0.f;
#pragma unroll
            for (int nt = 0; nt < 8; nt++) {
                s[nt][0] = __expf(s[nt][0] - mn0);
                s[nt][1] = __expf(s[nt][1] - mn0);
                s[nt][2] = __expf(s[nt][2] - mn1);
                s[nt][3] = __expf(s[nt][3] - mn1);
                sum0 += s[nt][0] + s[nt][1];
                sum1 += s[nt][2] + s[nt][3];
            }
            sum0 += __shfl_xor_sync(0xffffffffu, sum0, 1);
            sum0 += __shfl_xor_sync(0xffffffffu, sum0, 2);
            sum1 += __shfl_xor_sync(0xffffffffu, sum1, 1);
            sum1 += __shfl_xor_sync(0xffffffffu, sum1, 2);
            l0 = l0 * a0 + sum0;
            l1 = l1 * a1 + sum1;

#pragma unroll
            for (int nt = 0; nt < 16; nt++) {
                o[nt][0] *= a0; o[nt][1] *= a0;
                o[nt][2] *= a1; o[nt][3] *= a1;
            }

            uint32_t ap[4][4];
#pragma unroll
            for (int ts = 0; ts < 4; ts++) {
                ap[ts][0] = pack_hi(s[2 * ts][0],     s[2 * ts][1]);
                ap[ts][1] = pack_hi(s[2 * ts][2],     s[2 * ts][3]);
                ap[ts][2] = pack_hi(s[2 * ts + 1][0], s[2 * ts + 1][1]);
                ap[ts][3] = pack_hi(s[2 * ts + 1][2], s[2 * ts + 1][3]);
            }

#pragma unroll
            for (int ts = 0; ts < 4; ts++) {
#pragma unroll
                for (int g = 0; g < 8; g++) {
                    uint32_t va = (uint32_t)((ts * 16 + arow) * F_STR + g * 16 + agrp) * 2;
                    uint32_t h0, h1, h2, h3;
                    ldsm_x4t(h0, h1, h2, h3, VHo + va);
                    uint32_t b0[2] = {h0, h1}, b1[2] = {h2, h3};
                    mma16816(o[2 * g],     ap[ts], b0);
                    mma16816(o[2 * g + 1], ap[ts], b1);
                }
            }
        }
        __syncthreads();
    }

    float inv0 = 1.f / l0, inv1 = 1.f / l1;
    const int rg0 = q0 + w * 16 + (lane >> 2);
    size_t base0 = ((size_t)b * Sq + rg0) * DOUT + h * HD + 2 * (lane & 3);
    size_t base1 = base0 + (size_t)8 * DOUT;
#pragma unroll
    for (int nt = 0; nt < 16; nt++) {
        ((uint32_t*)Oh)[(base0 + nt * 8) >> 1] = pack_hi(o[nt][0] * inv0, o[nt][1] * inv0);
        ((uint32_t*)Oh)[(base1 + nt * 8) >> 1] = pack_hi(o[nt][2] * inv1, o[nt][3] * inv1);
    }
}

// ---------------------------------------------------------------------------
extern "C" void kernel_launch(void* const* d_in, const int* in_sizes, int n_in,
                              void* d_out, int out_size)
{
    const float* x    = (const float*)d_in[0];
    const float* Wq   = (const float*)d_in[1];
    const float* Wk   = (const float*)d_in[2];
    const float* Wv   = (const float*)d_in[3];
    const float* Wo   = (const float*)d_in[4];
    const float* cosT = (const float*)d_in[5];
    const float* sinT = (const float*)d_in[6];
    float* out = (float*)d_out;

    __half *xh, *wqkv, *woh, *qh, *khb, *vhb, *ch;
    cudaGetSymbolAddress((void**)&xh,   g_xh);
    cudaGetSymbolAddress((void**)&wqkv, g_wqkv);
    cudaGetSymbolAddress((void**)&woh,  g_woh);
    cudaGetSymbolAddress((void**)&qh,   g_qh);
    cudaGetSymbolAddress((void**)&khb,  g_kh);
    cudaGetSymbolAddress((void**)&vhb,  g_vh);
    cudaGetSymbolAddress((void**)&ch,   g_ch);

    cudaFuncSetAttribute(gemm_qkv,       cudaFuncAttributeMaxDynamicSharedMemorySize, GEMM_SMEM);
    cudaFuncSetAttribute(gemm_out,       cudaFuncAttributeMaxDynamicSharedMemorySize, GEMM_SMEM);
    cudaFuncSetAttribute(flash_attn_mma, cudaFuncAttributeMaxDynamicSharedMemorySize, FATTN_SMEM);

    dim3 thr(256);
    // One-shot conversion (x + permuted Wq/Wk + Wv + Wo)
    conv_all<<<(CONV_TOTAL + 255) / 256, thr>>>(x, Wq, Wk, Wv, Wo, xh, wqkv, woh);

    // Fused QKV projection + rope + scale + fp16 (no fp32 intermediate)
    gemm_qkv<<<dim3(NQKV / 128, MROWS / 128), thr, GEMM_SMEM>>>(
        xh, wqkv, cosT, sinT, qh, khb, vhb);

    // Attention -> fp16 ctx
    flash_attn_mma<<<dim3(Sq / FBM, NH, Bb), thr, FATTN_SMEM>>>(qh, khb, vhb, ch);

    // Output projection
    gemm_out<<<dim3(DOUT / 128, MROWS / 128), thr, GEMM_SMEM>>>(ch, woh, out);
}